// round 4
// baseline (speedup 1.0000x reference)
#include <cuda_runtime.h>
#include <cuda_bf16.h>
#include <cstdint>
#include <math.h>

// ---------------------------------------------------------------------------
// Problem constants
// ---------------------------------------------------------------------------
#define Bc  4
#define Sc  2048
#define Dc  512
#define Hc  8
#define Wc  16
#define DKc 64
#define Mtot (Bc * Sc)          // 8192
#define NELEM (Mtot * Dc)       // 4194304

// ---------------------------------------------------------------------------
// Device scratch
// ---------------------------------------------------------------------------
__device__ __nv_bfloat16 g_ah[3][NELEM];      // hi split of query/key/value
__device__ __nv_bfloat16 g_al[3][NELEM];      // lo split
__device__ __nv_bfloat16 g_wth[4][Dc * Dc];   // W^T hi: [n][k]
__device__ __nv_bfloat16 g_wtl[4][Dc * Dc];   // W^T lo
__device__ float g_Q[NELEM];                  // projected, [m, 512]
__device__ float g_K[NELEM];
__device__ float g_V[NELEM];
__device__ __nv_bfloat16 g_ch[NELEM];         // ctx hi split [m, 512]
__device__ __nv_bfloat16 g_cl[NELEM];         // ctx lo split

__device__ __forceinline__ uint32_t smem_to_u32(const void* p) {
    uint32_t a;
    asm("{ .reg .u64 t; cvta.to.shared.u64 t, %1; cvt.u32.u64 %0, t; }"
        : "=r"(a) : "l"(p));
    return a;
}

// ---------------------------------------------------------------------------
// bf16x3 GEMM via mma.sync (HMMA; tcgen05 unavailable — harness PTX targets
// bare sm_103). C[*,512] = (Ah+Al)@(Wh+Wl)^T + bias as virtual K'=1536:
// seg 0: Ah*Wh, seg 1: Ah*Wl, seg 2: Al*Wh.
// CTA tile 128x256, 512 threads (16 warps, 2x8), warp tile 64x32,
// K-chunk 32, double-buffered cp.async, m16n8k16 bf16, fp32 accum.
// ---------------------------------------------------------------------------
#define KCHUNK 32
#define NCHUNKv 48                  // 1536 / 32
#define A_TILE_B (128 * KCHUNK * 2) // 8192
#define B_TILE_B (256 * KCHUNK * 2) // 16384

__device__ __forceinline__ void cp_async16(uint32_t sp, const void* gp) {
    asm volatile("cp.async.cg.shared.global [%0], [%1], 16;" :: "r"(sp), "l"(gp));
}
__device__ __forceinline__ void cp_commit() {
    asm volatile("cp.async.commit_group;");
}

// A: 128 rows x 32 k -> 512 granules of 16B, 1 per thread
__device__ __forceinline__ void load_tile_a(
    uint32_t sbase, const __nv_bfloat16* __restrict__ src, int rowBase, int kk)
{
    const int g = threadIdx.x;            // 0..511
    const int row = g >> 2;
    const int cg = g & 3;
    const int cgs = cg ^ (row & 3);
    cp_async16(sbase + row * 64 + cgs * 16,
               src + (size_t)(rowBase + row) * Dc + kk + cg * 8);
}
// B: 256 rows x 32 k -> 1024 granules, 2 per thread
__device__ __forceinline__ void load_tile_b(
    uint32_t sbase, const __nv_bfloat16* __restrict__ src, int colBase, int kk)
{
    #pragma unroll
    for (int i = 0; i < 2; i++) {
        const int g = threadIdx.x * 2 + i;  // 0..1023
        const int row = g >> 2;
        const int cg = g & 3;
        const int cgs = cg ^ (row & 3);
        cp_async16(sbase + row * 64 + cgs * 16,
                   src + (size_t)(colBase + row) * Dc + kk + cg * 8);
    }
}

__device__ __forceinline__ void ldsm_x4(uint32_t* r, uint32_t addr) {
    asm volatile("ldmatrix.sync.aligned.m8n8.x4.shared.b16 {%0,%1,%2,%3}, [%4];"
                 : "=r"(r[0]), "=r"(r[1]), "=r"(r[2]), "=r"(r[3]) : "r"(addr));
}
__device__ __forceinline__ void ldsm_x2(uint32_t* r, uint32_t addr) {
    asm volatile("ldmatrix.sync.aligned.m8n8.x2.shared.b16 {%0,%1}, [%2];"
                 : "=r"(r[0]), "=r"(r[1]) : "r"(addr));
}
__device__ __forceinline__ void mma16816(
    float* d, const uint32_t* a, const uint32_t* b)
{
    asm volatile(
        "mma.sync.aligned.m16n8k16.row.col.f32.bf16.bf16.f32 "
        "{%0,%1,%2,%3}, {%4,%5,%6,%7}, {%8,%9}, {%0,%1,%2,%3};"
        : "+f"(d[0]), "+f"(d[1]), "+f"(d[2]), "+f"(d[3])
        : "r"(a[0]), "r"(a[1]), "r"(a[2]), "r"(a[3]), "r"(b[0]), "r"(b[1]));
}

__device__ void gemm_core(
    const __nv_bfloat16* __restrict__ Ah, const __nv_bfloat16* __restrict__ Al,
    const __nv_bfloat16* __restrict__ Wh, const __nv_bfloat16* __restrict__ Wl,
    const float* __restrict__ bias, float* __restrict__ dst,
    int rowBase, int colBase)
{
    __shared__ __align__(16) char smA[2][A_TILE_B];
    __shared__ __align__(16) char smB[2][B_TILE_B];

    const int tid = threadIdx.x;
    const int wid = tid >> 5;
    const int lane = tid & 31;
    const int wm = wid >> 3;       // 0..1
    const int wn = wid & 7;        // 0..7

    const uint32_t sA0 = smem_to_u32(smA[0]);
    const uint32_t sA1 = smem_to_u32(smA[1]);
    const uint32_t sB0 = smem_to_u32(smB[0]);
    const uint32_t sB1 = smem_to_u32(smB[1]);

    float acc[4][4][4];
    #pragma unroll
    for (int i = 0; i < 4; i++)
        #pragma unroll
        for (int j = 0; j < 4; j++)
            #pragma unroll
            for (int k = 0; k < 4; k++)
                acc[i][j][k] = 0.0f;

    int aRow[4], aR3[4];
    #pragma unroll
    for (int mi = 0; mi < 4; mi++) {
        const int r = wm * 64 + mi * 16 + (lane & 7) + (((lane >> 3) & 1) << 3);
        aRow[mi] = r * 64;
        aR3[mi] = r & 3;
    }
    const int aHi = lane >> 4;
    int bRow[4], bR3[4];
    #pragma unroll
    for (int ni = 0; ni < 4; ni++) {
        const int r = wn * 32 + ni * 8 + (lane & 7);
        bRow[ni] = r * 64;
        bR3[ni] = r & 3;
    }
    const int bHi = (lane & 15) >> 3;

    // prologue: chunks 0,1 (both in segment 0: Ah, Wh)
    #pragma unroll
    for (int c = 0; c < 2; c++) {
        load_tile_a(c ? sA1 : sA0, Ah, rowBase, c * KCHUNK);
        load_tile_b(c ? sB1 : sB0, Wh, colBase, c * KCHUNK);
        cp_commit();
    }

    for (int c = 0; c < NCHUNKv; c++) {
        if (c < NCHUNKv - 2) asm volatile("cp.async.wait_group 1;");
        else                 asm volatile("cp.async.wait_group 0;");
        __syncthreads();

        const uint32_t cA = (c & 1) ? sA1 : sA0;
        const uint32_t cB = (c & 1) ? sB1 : sB0;

        #pragma unroll
        for (int ks = 0; ks < 2; ks++) {
            uint32_t af[4][4], bf[4][2];
            #pragma unroll
            for (int mi = 0; mi < 4; mi++) {
                const int cg = (ks * 2 + aHi) ^ aR3[mi];
                ldsm_x4(af[mi], cA + aRow[mi] + cg * 16);
            }
            #pragma unroll
            for (int ni = 0; ni < 4; ni++) {
                const int cg = (ks * 2 + bHi) ^ bR3[ni];
                ldsm_x2(bf[ni], cB + bRow[ni] + cg * 16);
            }
            #pragma unroll
            for (int mi = 0; mi < 4; mi++)
                #pragma unroll
                for (int ni = 0; ni < 4; ni++)
                    mma16816(acc[mi][ni], af[mi], bf[ni]);
        }
        __syncthreads();

        if (c + 2 < NCHUNKv) {
            const int cc = c + 2;
            const int seg = cc >> 4;               // 0,1,2
            const int kk = (cc & 15) * KCHUNK;
            const __nv_bfloat16* As = (seg == 2) ? Al : Ah;
            const __nv_bfloat16* Ws = (seg == 1) ? Wl : Wh;
            load_tile_a((c & 1) ? sA1 : sA0, As, rowBase, kk);
            load_tile_b((c & 1) ? sB1 : sB0, Ws, colBase, kk);
            cp_commit();
        }
    }

    // epilogue
    const int lr = lane >> 2;
    const int lc = (lane & 3) * 2;
    #pragma unroll
    for (int ni = 0; ni < 4; ni++) {
        const int col = colBase + wn * 32 + ni * 8 + lc;
        const float2 bb = *(const float2*)&bias[col];
        #pragma unroll
        for (int mi = 0; mi < 4; mi++) {
            const int row = rowBase + wm * 64 + mi * 16 + lr;
            float2 v0 = { acc[mi][ni][0] + bb.x, acc[mi][ni][1] + bb.y };
            float2 v1 = { acc[mi][ni][2] + bb.x, acc[mi][ni][3] + bb.y };
            *(float2*)&dst[(size_t)row * Dc + col] = v0;
            *(float2*)&dst[(size_t)(row + 8) * Dc + col] = v1;
        }
    }
}

__global__ __launch_bounds__(512, 1) void qkv_gemm_tc(
    const float* __restrict__ bq, const float* __restrict__ bk,
    const float* __restrict__ bv)
{
    const int z = blockIdx.z;
    const float* bias = (z == 0) ? bq : (z == 1) ? bk : bv;
    float* dst = (z == 0) ? g_Q : (z == 1) ? g_K : g_V;
    gemm_core(g_ah[z], g_al[z], g_wth[z], g_wtl[z], bias, dst,
              blockIdx.y * 128, blockIdx.x * 256);
}

__global__ __launch_bounds__(512, 1) void out_gemm_tc(
    const float* __restrict__ bo, float* __restrict__ out)
{
    gemm_core(g_ch, g_cl, g_wth[3], g_wtl[3], bo, out,
              blockIdx.y * 128, blockIdx.x * 256);
}

// ---------------------------------------------------------------------------
// fp32 -> bf16 hi/lo splits
// ---------------------------------------------------------------------------
__global__ __launch_bounds__(256) void split_inputs_kernel(
    const float* __restrict__ q, const float* __restrict__ k,
    const float* __restrict__ v)
{
    const int z = blockIdx.y;
    const float* src = (z == 0) ? q : (z == 1) ? k : v;
    const size_t i4 = (size_t)blockIdx.x * 256 + threadIdx.x;
    float4 f = ((const float4*)src)[i4];
    float a[4] = {f.x, f.y, f.z, f.w};
    __align__(8) __nv_bfloat16 h[4], lo[4];
    #pragma unroll
    for (int i = 0; i < 4; i++) {
        h[i] = __float2bfloat16_rn(a[i]);
        lo[i] = __float2bfloat16_rn(a[i] - __bfloat162float(h[i]));
    }
    *(uint2*)&g_ah[z][i4 * 4] = *(uint2*)h;
    *(uint2*)&g_al[z][i4 * 4] = *(uint2*)lo;
}

__global__ __launch_bounds__(1024) void split_weights_kernel(
    const float* __restrict__ Wq, const float* __restrict__ Wk,
    const float* __restrict__ Wv, const float* __restrict__ Wo)
{
    const int z = blockIdx.z;
    const float* w = (z == 0) ? Wq : (z == 1) ? Wk : (z == 2) ? Wv : Wo;
    __shared__ float s[32][33];
    const int tx = threadIdx.x & 31;
    const int ty = threadIdx.x >> 5;
    const int rb = blockIdx.y * 32;   // k block
    const int cb = blockIdx.x * 32;   // n block
    s[ty][tx] = w[(size_t)(rb + ty) * Dc + cb + tx];
    __syncthreads();
    const float a = s[tx][ty];        // = w[rb+tx][cb+ty]
    const __nv_bfloat16 h = __float2bfloat16_rn(a);
    const __nv_bfloat16 l = __float2bfloat16_rn(a - __bfloat162float(h));
    const size_t o = (size_t)(cb + ty) * Dc + rb + tx;   // [n][k]
    g_wth[z][o] = h;
    g_wtl[z][o] = l;
}

// ---------------------------------------------------------------------------
// Banded local attention. No online-max: scores are bounded (|s| <= ~10),
// exp() safely in fp32 range, so plain exp-sum softmax. Fused bf16 hi/lo
// split of ctx for the output projection.
// ---------------------------------------------------------------------------
#define TQ 64
#define HALO (TQ + 2 * Wc)    // 96
#define SKW 64

__global__ __launch_bounds__(256) void attn_kernel()
{
    __shared__ float sK[HALO * SKW];
    __shared__ float sV[HALO * SKW];

    const int bh = blockIdx.y;
    const int b = bh >> 3;
    const int h = bh & 7;
    const int q0 = blockIdx.x * TQ;
    const int kstart = q0 - Wc;
    const size_t rowBase = ((size_t)b * Sc) * Dc + h * DKc;

    for (int idx = threadIdx.x; idx < HALO * 16; idx += 256) {
        const int r = idx >> 4;
        const int c4 = idx & 15;
        const int j = kstart + r;
        float4 kv = {0, 0, 0, 0}, vv = {0, 0, 0, 0};
        if (j >= 0 && j < Sc) {
            const size_t off = rowBase + (size_t)j * Dc + c4 * 4;
            kv = *(const float4*)(g_K + off);
            vv = *(const float4*)(g_V + off);
        }
        *(float4*)(sK + r * SKW + c4 * 4) = kv;
        *(float4*)(sV + r * SKW + c4 * 4) = vv;
    }
    __syncthreads();

    const int warp = threadIdx.x >> 5;
    const int lane = threadIdx.x & 31;
    const int lq = lane >> 3;     // local query 0..3
    const int g = lane & 7;       // dim group 0..7

    #pragma unroll
    for (int it = 0; it < 2; it++) {
        const int q = q0 + warp * 8 + it * 4 + lq;
        const size_t qoff = rowBase + (size_t)q * Dc + g * 8;
        const float4 qa = *(const float4*)(g_Q + qoff);
        const float4 qb = *(const float4*)(g_Q + qoff + 4);

        float l = 0.0f;
        float4 a0 = {0, 0, 0, 0}, a1 = {0, 0, 0, 0};

        for (int s = 0; s <= 2 * Wc; s++) {
            const int j = q - Wc + s;
            const bool valid = (j >= 0) && (j < Sc);
            const int r = j - kstart;
            const float* kr = sK + r * SKW + g * 8;
            const float4 ka = *(const float4*)kr;
            const float4 kb = *(const float4*)(kr + 4);
            float p = qa.x * ka.x + qa.y * ka.y + qa.z * ka.z + qa.w * ka.w
                    + qb.x * kb.x + qb.y * kb.y + qb.z * kb.z + qb.w * kb.w;
            p += __shfl_xor_sync(0xffffffffu, p, 1);
            p += __shfl_xor_sync(0xffffffffu, p, 2);
            p += __shfl_xor_sync(0xffffffffu, p, 4);

            const float w = valid ? __expf(p * 0.125f) : 0.0f;

            const float* vr = sV + r * SKW + g * 8;
            const float4 va = *(const float4*)vr;
            const float4 vb = *(const float4*)(vr + 4);
            a0.x += w * va.x;  a0.y += w * va.y;
            a0.z += w * va.z;  a0.w += w * va.w;
            a1.x += w * vb.x;  a1.y += w * vb.y;
            a1.z += w * vb.z;  a1.w += w * vb.w;
            l += w;
        }

        const float inv = 1.0f / l;
        float v[8] = {a0.x * inv, a0.y * inv, a0.z * inv, a0.w * inv,
                      a1.x * inv, a1.y * inv, a1.z * inv, a1.w * inv};
        __align__(16) __nv_bfloat16 hi[8], lo[8];
        #pragma unroll
        for (int d = 0; d < 8; d++) {
            hi[d] = __float2bfloat16_rn(v[d]);
            lo[d] = __float2bfloat16_rn(v[d] - __bfloat162float(hi[d]));
        }
        const size_t coff = ((size_t)(b * Sc + q)) * Dc + h * DKc + g * 8;
        *(uint4*)(g_ch + coff) = *(uint4*)hi;
        *(uint4*)(g_cl + coff) = *(uint4*)lo;
    }
}

// ---------------------------------------------------------------------------
// Launch
// ---------------------------------------------------------------------------
extern "C" void kernel_launch(void* const* d_in, const int* in_sizes, int n_in,
                              void* d_out, int out_size)
{
    const float* query = (const float*)d_in[0];
    const float* key   = (const float*)d_in[1];
    const float* value = (const float*)d_in[2];
    const float* Wq    = (const float*)d_in[3];
    const float* bq    = (const float*)d_in[4];
    const float* Wk    = (const float*)d_in[5];
    const float* bk    = (const float*)d_in[6];
    const float* Wv    = (const float*)d_in[7];
    const float* bv    = (const float*)d_in[8];
    const float* Wo    = (const float*)d_in[9];
    const float* bo    = (const float*)d_in[10];
    float* out = (float*)d_out;

    // 1. fp32 -> bf16 hi/lo splits
    split_inputs_kernel<<<dim3(NELEM / 4 / 256, 3), 256>>>(query, key, value);
    split_weights_kernel<<<dim3(16, 16, 4), 1024>>>(Wq, Wk, Wv, Wo);

    // 2. QKV projections (HMMA bf16x3), CTA tile 128x256
    qkv_gemm_tc<<<dim3(2, 64, 3), 512>>>(bq, bk, bv);

    // 3. banded attention
    attn_kernel<<<dim3(Sc / TQ, Bc * Hc), 256>>>();

    // 4. output projection
    out_gemm_tc<<<dim3(2, 64), 512>>>(bo, out);
}

// round 5
// speedup vs baseline: 1.3058x; 1.3058x over previous
#include <cuda_runtime.h>
#include <cuda_bf16.h>
#include <cstdint>
#include <math.h>

// ---------------------------------------------------------------------------
// Problem constants
// ---------------------------------------------------------------------------
#define Bc  4
#define Sc  2048
#define Dc  512
#define Hc  8
#define Wc  16
#define DKc 64
#define Mtot (Bc * Sc)          // 8192
#define NELEM (Mtot * Dc)       // 4194304

// ---------------------------------------------------------------------------
// Device scratch
// ---------------------------------------------------------------------------
__device__ __nv_bfloat16 g_ah[3][NELEM];      // hi split of query/key/value
__device__ __nv_bfloat16 g_al[3][NELEM];      // lo split
__device__ __nv_bfloat16 g_wth[4][Dc * Dc];   // W^T hi: [n][k]
__device__ __nv_bfloat16 g_wtl[4][Dc * Dc];   // W^T lo
__device__ float g_Q[NELEM];                  // projected, [m, 512]
__device__ float g_K[NELEM];
__device__ float g_V[NELEM];
__device__ __nv_bfloat16 g_ch[NELEM];         // ctx hi split [m, 512]
__device__ __nv_bfloat16 g_cl[NELEM];         // ctx lo split

__device__ __forceinline__ uint32_t smem_to_u32(const void* p) {
    uint32_t a;
    asm("{ .reg .u64 t; cvta.to.shared.u64 t, %1; cvt.u32.u64 %0, t; }"
        : "=r"(a) : "l"(p));
    return a;
}

// ---------------------------------------------------------------------------
// bf16x3 GEMM via mma.sync. C = (Ah+Al)@(Wh+Wl)^T + bias as virtual K'=1536:
// seg 0: Ah*Wh, seg 1: Ah*Wl, seg 2: Al*Wh.
// CTA tile 128x128, 256 thr (8 warps 2x4), warp tile 64x32, K-chunk 32,
// 3-stage cp.async pipeline with ONE __syncthreads per chunk.
// ---------------------------------------------------------------------------
#define KCHUNK 32
#define NCHUNKv 48                    // 1536 / 32
#define TILE_B (128 * KCHUNK * 2)     // 8192 bytes (A or B tile)
#define STAGE_B (2 * TILE_B)          // 16384

__device__ __forceinline__ void cp_async16(uint32_t sp, const void* gp) {
    asm volatile("cp.async.cg.shared.global [%0], [%1], 16;" :: "r"(sp), "l"(gp));
}
__device__ __forceinline__ void cp_commit() {
    asm volatile("cp.async.commit_group;");
}

// load a 128x32 bf16 tile into swizzled smem (512 granules, 2/thread)
__device__ __forceinline__ void load_tile(
    uint32_t sbase, const __nv_bfloat16* __restrict__ src, int rowBase, int kk)
{
    #pragma unroll
    for (int i = 0; i < 2; i++) {
        const int g = threadIdx.x + i * 256;   // 0..511
        const int row = g >> 2;
        const int cg = g & 3;
        const int cgs = cg ^ (row & 3);
        cp_async16(sbase + row * 64 + cgs * 16,
                   src + (size_t)(rowBase + row) * Dc + kk + cg * 8);
    }
}

__device__ __forceinline__ void ldsm_x4(uint32_t* r, uint32_t addr) {
    asm volatile("ldmatrix.sync.aligned.m8n8.x4.shared.b16 {%0,%1,%2,%3}, [%4];"
                 : "=r"(r[0]), "=r"(r[1]), "=r"(r[2]), "=r"(r[3]) : "r"(addr));
}
__device__ __forceinline__ void ldsm_x2(uint32_t* r, uint32_t addr) {
    asm volatile("ldmatrix.sync.aligned.m8n8.x2.shared.b16 {%0,%1}, [%2];"
                 : "=r"(r[0]), "=r"(r[1]) : "r"(addr));
}
__device__ __forceinline__ void mma16816(
    float* d, const uint32_t* a, const uint32_t* b)
{
    asm volatile(
        "mma.sync.aligned.m16n8k16.row.col.f32.bf16.bf16.f32 "
        "{%0,%1,%2,%3}, {%4,%5,%6,%7}, {%8,%9}, {%0,%1,%2,%3};"
        : "+f"(d[0]), "+f"(d[1]), "+f"(d[2]), "+f"(d[3])
        : "r"(a[0]), "r"(a[1]), "r"(a[2]), "r"(a[3]), "r"(b[0]), "r"(b[1]));
}

__device__ void gemm_core(
    const __nv_bfloat16* __restrict__ Ah, const __nv_bfloat16* __restrict__ Al,
    const __nv_bfloat16* __restrict__ Wh, const __nv_bfloat16* __restrict__ Wl,
    const float* __restrict__ bias, float* __restrict__ dst,
    int rowBase, int colBase)
{
    __shared__ __align__(16) char sm[3][STAGE_B];   // 49152 bytes

    const int tid = threadIdx.x;
    const int wid = tid >> 5;
    const int lane = tid & 31;
    const int wm = wid >> 2;       // 0..1
    const int wn = wid & 3;        // 0..3

    uint32_t stA[3], stB[3];
    #pragma unroll
    for (int s = 0; s < 3; s++) {
        stA[s] = smem_to_u32(sm[s]);
        stB[s] = stA[s] + TILE_B;
    }

    float acc[4][4][4];
    #pragma unroll
    for (int i = 0; i < 4; i++)
        #pragma unroll
        for (int j = 0; j < 4; j++)
            #pragma unroll
            for (int k = 0; k < 4; k++)
                acc[i][j][k] = 0.0f;

    int aRow[4], aR3[4];
    #pragma unroll
    for (int mi = 0; mi < 4; mi++) {
        const int r = wm * 64 + mi * 16 + (lane & 7) + (((lane >> 3) & 1) << 3);
        aRow[mi] = r * 64;
        aR3[mi] = r & 3;
    }
    const int aHi = lane >> 4;
    int bRow[4], bR3[4];
    #pragma unroll
    for (int ni = 0; ni < 4; ni++) {
        const int r = wn * 32 + ni * 8 + (lane & 7);
        bRow[ni] = r * 64;
        bR3[ni] = r & 3;
    }
    const int bHi = (lane & 15) >> 3;

    // prologue: chunks 0,1 (segment 0) into stages 0,1
    #pragma unroll
    for (int c = 0; c < 2; c++) {
        load_tile(stA[c], Ah, rowBase, c * KCHUNK);
        load_tile(stB[c], Wh, colBase, c * KCHUNK);
        cp_commit();
    }

    for (int c = 0; c < NCHUNKv; c++) {
        asm volatile("cp.async.wait_group 1;");
        __syncthreads();

        // prefetch chunk c+2 into stage (c+2)%3 == (c-1)%3 (drained last iter)
        if (c + 2 < NCHUNKv) {
            const int cc = c + 2;
            const int seg = cc >> 4;               // 0,1,2
            const int kk = (cc & 15) * KCHUNK;
            const __nv_bfloat16* As = (seg == 2) ? Al : Ah;
            const __nv_bfloat16* Ws = (seg == 1) ? Wl : Wh;
            const int st = cc - (cc / 3) * 3;
            load_tile(stA[st], As, rowBase, kk);
            load_tile(stB[st], Ws, colBase, kk);
            cp_commit();
        }

        const int cs = c - (c / 3) * 3;
        const uint32_t cA = stA[cs];
        const uint32_t cB = stB[cs];

        #pragma unroll
        for (int ks = 0; ks < 2; ks++) {
            uint32_t af[4][4], bf[4][2];
            #pragma unroll
            for (int mi = 0; mi < 4; mi++) {
                const int cg = (ks * 2 + aHi) ^ aR3[mi];
                ldsm_x4(af[mi], cA + aRow[mi] + cg * 16);
            }
            #pragma unroll
            for (int ni = 0; ni < 4; ni++) {
                const int cg = (ks * 2 + bHi) ^ bR3[ni];
                ldsm_x2(bf[ni], cB + bRow[ni] + cg * 16);
            }
            #pragma unroll
            for (int mi = 0; mi < 4; mi++)
                #pragma unroll
                for (int ni = 0; ni < 4; ni++)
                    mma16816(acc[mi][ni], af[mi], bf[ni]);
        }
    }

    // epilogue
    const int lr = lane >> 2;
    const int lc = (lane & 3) * 2;
    #pragma unroll
    for (int ni = 0; ni < 4; ni++) {
        const int col = colBase + wn * 32 + ni * 8 + lc;
        const float2 bb = *(const float2*)&bias[col];
        #pragma unroll
        for (int mi = 0; mi < 4; mi++) {
            const int row = rowBase + wm * 64 + mi * 16 + lr;
            float2 v0 = { acc[mi][ni][0] + bb.x, acc[mi][ni][1] + bb.y };
            float2 v1 = { acc[mi][ni][2] + bb.x, acc[mi][ni][3] + bb.y };
            *(float2*)&dst[(size_t)row * Dc + col] = v0;
            *(float2*)&dst[(size_t)(row + 8) * Dc + col] = v1;
        }
    }
}

__global__ __launch_bounds__(256, 2) void qkv_gemm_tc(
    const float* __restrict__ bq, const float* __restrict__ bk,
    const float* __restrict__ bv)
{
    const int z = blockIdx.z;
    const float* bias = (z == 0) ? bq : (z == 1) ? bk : bv;
    float* dst = (z == 0) ? g_Q : (z == 1) ? g_K : g_V;
    gemm_core(g_ah[z], g_al[z], g_wth[z], g_wtl[z], bias, dst,
              blockIdx.y * 128, blockIdx.x * 128);
}

__global__ __launch_bounds__(256, 2) void out_gemm_tc(
    const float* __restrict__ bo, float* __restrict__ out)
{
    gemm_core(g_ch, g_cl, g_wth[3], g_wtl[3], bo, out,
              blockIdx.y * 128, blockIdx.x * 128);
}

// ---------------------------------------------------------------------------
// fp32 -> bf16 hi/lo splits
// ---------------------------------------------------------------------------
__global__ __launch_bounds__(256) void split_inputs_kernel(
    const float* __restrict__ q, const float* __restrict__ k,
    const float* __restrict__ v)
{
    const int z = blockIdx.y;
    const float* src = (z == 0) ? q : (z == 1) ? k : v;
    const size_t i4 = (size_t)blockIdx.x * 256 + threadIdx.x;
    float4 f = ((const float4*)src)[i4];
    float a[4] = {f.x, f.y, f.z, f.w};
    __align__(8) __nv_bfloat16 h[4], lo[4];
    #pragma unroll
    for (int i = 0; i < 4; i++) {
        h[i] = __float2bfloat16_rn(a[i]);
        lo[i] = __float2bfloat16_rn(a[i] - __bfloat162float(h[i]));
    }
    *(uint2*)&g_ah[z][i4 * 4] = *(uint2*)h;
    *(uint2*)&g_al[z][i4 * 4] = *(uint2*)lo;
}

__global__ __launch_bounds__(1024) void split_weights_kernel(
    const float* __restrict__ Wq, const float* __restrict__ Wk,
    const float* __restrict__ Wv, const float* __restrict__ Wo)
{
    const int z = blockIdx.z;
    const float* w = (z == 0) ? Wq : (z == 1) ? Wk : (z == 2) ? Wv : Wo;
    __shared__ float s[32][33];
    const int tx = threadIdx.x & 31;
    const int ty = threadIdx.x >> 5;
    const int rb = blockIdx.y * 32;   // k block
    const int cb = blockIdx.x * 32;   // n block
    s[ty][tx] = w[(size_t)(rb + ty) * Dc + cb + tx];
    __syncthreads();
    const float a = s[tx][ty];        // = w[rb+tx][cb+ty]
    const __nv_bfloat16 h = __float2bfloat16_rn(a);
    const __nv_bfloat16 l = __float2bfloat16_rn(a - __bfloat162float(h));
    const size_t o = (size_t)(cb + ty) * Dc + rb + tx;   // [n][k]
    g_wth[z][o] = h;
    g_wtl[z][o] = l;
}

// ---------------------------------------------------------------------------
// Banded local attention. Plain exp-sum softmax (scores bounded).
// 8-lane groups per query; lane g owns dims [4g,4g+3] U [32+4g,32+4g+3]
// so each LDS.128 phase reads 32 consecutive words -> conflict-free.
// Two query-chains (A/B) interleaved for ILP. Fused bf16 hi/lo ctx split.
// ---------------------------------------------------------------------------
#define TQ 64
#define HALO (TQ + 2 * Wc)    // 96
#define SKW 64

__global__ __launch_bounds__(256) void attn_kernel()
{
    __shared__ float sK[HALO * SKW];
    __shared__ float sV[HALO * SKW];

    const int bh = blockIdx.y;
    const int b = bh >> 3;
    const int h = bh & 7;
    const int q0 = blockIdx.x * TQ;
    const int kstart = q0 - Wc;
    const size_t rowBase = ((size_t)b * Sc) * Dc + h * DKc;

    for (int idx = threadIdx.x; idx < HALO * 16; idx += 256) {
        const int r = idx >> 4;
        const int c4 = idx & 15;
        const int j = kstart + r;
        float4 kv = {0, 0, 0, 0}, vv = {0, 0, 0, 0};
        if (j >= 0 && j < Sc) {
            const size_t off = rowBase + (size_t)j * Dc + c4 * 4;
            kv = *(const float4*)(g_K + off);
            vv = *(const float4*)(g_V + off);
        }
        *(float4*)(sK + r * SKW + c4 * 4) = kv;
        *(float4*)(sV + r * SKW + c4 * 4) = vv;
    }
    __syncthreads();

    const int warp = threadIdx.x >> 5;
    const int lane = threadIdx.x & 31;
    const int lq = lane >> 3;     // local query 0..3
    const int g = lane & 7;       // dim-group: words 4g..4g+3 and 32+4g..+3
    const int d0 = g * 4;
    const int d1 = 32 + g * 4;

    const int qA = q0 + warp * 8 + lq;
    const int qB = qA + 4;
    const int rA0 = qA - kstart - Wc;   // = warp*8 + lq
    const int rB0 = rA0 + 4;

    const size_t qoffA = rowBase + (size_t)qA * Dc;
    const size_t qoffB = rowBase + (size_t)qB * Dc;
    float4 qa0 = *(const float4*)(g_Q + qoffA + d0);
    float4 qa1 = *(const float4*)(g_Q + qoffA + d1);
    float4 qb0 = *(const float4*)(g_Q + qoffB + d0);
    float4 qb1 = *(const float4*)(g_Q + qoffB + d1);
    // prescale by 1/sqrt(DK)=0.125
    qa0.x *= 0.125f; qa0.y *= 0.125f; qa0.z *= 0.125f; qa0.w *= 0.125f;
    qa1.x *= 0.125f; qa1.y *= 0.125f; qa1.z *= 0.125f; qa1.w *= 0.125f;
    qb0.x *= 0.125f; qb0.y *= 0.125f; qb0.z *= 0.125f; qb0.w *= 0.125f;
    qb1.x *= 0.125f; qb1.y *= 0.125f; qb1.z *= 0.125f; qb1.w *= 0.125f;

    float lA = 0.0f, lB = 0.0f;
    float4 accA0 = {0,0,0,0}, accA1 = {0,0,0,0};
    float4 accB0 = {0,0,0,0}, accB1 = {0,0,0,0};

    #pragma unroll 4
    for (int s = 0; s <= 2 * Wc; s++) {
        const int jA = qA - Wc + s;
        const int jB = qB - Wc + s;
        const bool vA = (jA >= 0) && (jA < Sc);
        const bool vB = (jB >= 0) && (jB < Sc);
        const float* krA = sK + (rA0 + s) * SKW;
        const float* krB = sK + (rB0 + s) * SKW;

        const float4 kA0 = *(const float4*)(krA + d0);
        const float4 kA1 = *(const float4*)(krA + d1);
        const float4 kB0 = *(const float4*)(krB + d0);
        const float4 kB1 = *(const float4*)(krB + d1);

        float pA = qa0.x*kA0.x + qa0.y*kA0.y + qa0.z*kA0.z + qa0.w*kA0.w
                 + qa1.x*kA1.x + qa1.y*kA1.y + qa1.z*kA1.z + qa1.w*kA1.w;
        float pB = qb0.x*kB0.x + qb0.y*kB0.y + qb0.z*kB0.z + qb0.w*kB0.w
                 + qb1.x*kB1.x + qb1.y*kB1.y + qb1.z*kB1.z + qb1.w*kB1.w;

        pA += __shfl_xor_sync(0xffffffffu, pA, 1);
        pB += __shfl_xor_sync(0xffffffffu, pB, 1);
        pA += __shfl_xor_sync(0xffffffffu, pA, 2);
        pB += __shfl_xor_sync(0xffffffffu, pB, 2);
        pA += __shfl_xor_sync(0xffffffffu, pA, 4);
        pB += __shfl_xor_sync(0xffffffffu, pB, 4);

        const float wA = vA ? __expf(pA) : 0.0f;
        const float wB = vB ? __expf(pB) : 0.0f;

        const float* vrA = sV + (rA0 + s) * SKW;
        const float* vrB = sV + (rB0 + s) * SKW;
        const float4 vA0 = *(const float4*)(vrA + d0);
        const float4 vA1 = *(const float4*)(vrA + d1);
        const float4 vB0 = *(const float4*)(vrB + d0);
        const float4 vB1 = *(const float4*)(vrB + d1);

        accA0.x += wA * vA0.x; accA0.y += wA * vA0.y;
        accA0.z += wA * vA0.z; accA0.w += wA * vA0.w;
        accA1.x += wA * vA1.x; accA1.y += wA * vA1.y;
        accA1.z += wA * vA1.z; accA1.w += wA * vA1.w;
        accB0.x += wB * vB0.x; accB0.y += wB * vB0.y;
        accB0.z += wB * vB0.z; accB0.w += wB * vB0.w;
        accB1.x += wB * vB1.x; accB1.y += wB * vB1.y;
        accB1.z += wB * vB1.z; accB1.w += wB * vB1.w;
        lA += wA;
        lB += wB;
    }

    const float invA = 1.0f / lA;
    const float invB = 1.0f / lB;

    {
        float v[8] = {accA0.x*invA, accA0.y*invA, accA0.z*invA, accA0.w*invA,
                      accA1.x*invA, accA1.y*invA, accA1.z*invA, accA1.w*invA};
        __align__(8) __nv_bfloat16 hi[8], lo[8];
        #pragma unroll
        for (int d = 0; d < 8; d++) {
            hi[d] = __float2bfloat16_rn(v[d]);
            lo[d] = __float2bfloat16_rn(v[d] - __bfloat162float(hi[d]));
        }
        const size_t coff = ((size_t)(b * Sc + qA)) * Dc + h * DKc;
        *(uint2*)(g_ch + coff + d0) = *(uint2*)&hi[0];
        *(uint2*)(g_ch + coff + d1) = *(uint2*)&hi[4];
        *(uint2*)(g_cl + coff + d0) = *(uint2*)&lo[0];
        *(uint2*)(g_cl + coff + d1) = *(uint2*)&lo[4];
    }
    {
        float v[8] = {accB0.x*invB, accB0.y*invB, accB0.z*invB, accB0.w*invB,
                      accB1.x*invB, accB1.y*invB, accB1.z*invB, accB1.w*invB};
        __align__(8) __nv_bfloat16 hi[8], lo[8];
        #pragma unroll
        for (int d = 0; d < 8; d++) {
            hi[d] = __float2bfloat16_rn(v[d]);
            lo[d] = __float2bfloat16_rn(v[d] - __bfloat162float(hi[d]));
        }
        const size_t coff = ((size_t)(b * Sc + qB)) * Dc + h * DKc;
        *(uint2*)(g_ch + coff + d0) = *(uint2*)&hi[0];
        *(uint2*)(g_ch + coff + d1) = *(uint2*)&hi[4];
        *(uint2*)(g_cl + coff + d0) = *(uint2*)&lo[0];
        *(uint2*)(g_cl + coff + d1) = *(uint2*)&lo[4];
    }
}

// ---------------------------------------------------------------------------
// Launch
// ---------------------------------------------------------------------------
extern "C" void kernel_launch(void* const* d_in, const int* in_sizes, int n_in,
                              void* d_out, int out_size)
{
    const float* query = (const float*)d_in[0];
    const float* key   = (const float*)d_in[1];
    const float* value = (const float*)d_in[2];
    const float* Wq    = (const float*)d_in[3];
    const float* bq    = (const float*)d_in[4];
    const float* Wk    = (const float*)d_in[5];
    const float* bk    = (const float*)d_in[6];
    const float* Wv    = (const float*)d_in[7];
    const float* bv    = (const float*)d_in[8];
    const float* Wo    = (const float*)d_in[9];
    const float* bo    = (const float*)d_in[10];
    float* out = (float*)d_out;

    // 1. fp32 -> bf16 hi/lo splits
    split_inputs_kernel<<<dim3(NELEM / 4 / 256, 3), 256>>>(query, key, value);
    split_weights_kernel<<<dim3(16, 16, 4), 1024>>>(Wq, Wk, Wv, Wo);

    // 2. QKV projections (HMMA bf16x3), 3-stage pipeline
    qkv_gemm_tc<<<dim3(4, 64, 3), 256>>>(bq, bk, bv);

    // 3. banded attention
    attn_kernel<<<dim3(Sc / TQ, Bc * Hc), 256>>>();

    // 4. output projection
    out_gemm_tc<<<dim3(4, 64), 256>>>(bo, out);
}

// round 6
// speedup vs baseline: 1.6742x; 1.2822x over previous
#include <cuda_runtime.h>
#include <cuda_bf16.h>
#include <cstdint>
#include <math.h>

// ---------------------------------------------------------------------------
// Problem constants
// ---------------------------------------------------------------------------
#define Bc  4
#define Sc  2048
#define Dc  512
#define Hc  8
#define Wc  16
#define DKc 64
#define Mtot (Bc * Sc)          // 8192
#define NELEM (Mtot * Dc)       // 4194304

// ---------------------------------------------------------------------------
// Device scratch
// ---------------------------------------------------------------------------
__device__ __nv_bfloat16 g_ah[3][NELEM];      // hi split of query/key/value
__device__ __nv_bfloat16 g_al[3][NELEM];      // lo split
__device__ __nv_bfloat16 g_wth[4][Dc * Dc];   // W^T hi: [n][k]
__device__ __nv_bfloat16 g_wtl[4][Dc * Dc];   // W^T lo
__device__ float g_Q[NELEM];                  // projected, [m, 512]
__device__ float g_K[NELEM];
__device__ float g_V[NELEM];
__device__ __nv_bfloat16 g_ch[NELEM];         // ctx hi split [m, 512]
__device__ __nv_bfloat16 g_cl[NELEM];         // ctx lo split

__device__ __forceinline__ uint32_t smem_to_u32(const void* p) {
    uint32_t a;
    asm("{ .reg .u64 t; cvta.to.shared.u64 t, %1; cvt.u32.u64 %0, t; }"
        : "=r"(a) : "l"(p));
    return a;
}

// ---------------------------------------------------------------------------
// bf16x3 GEMM via mma.sync. C = (Ah+Al)@(Wh+Wl)^T + bias as virtual K'=1536:
// seg 0: Ah*Wh, seg 1: Ah*Wl, seg 2: Al*Wh.
// CTA tile 128x128, 256 thr (8 warps 2x4), warp tile 64x32, K-chunk 64,
// 3-stage cp.async pipeline (96KB dynamic smem), ONE sync per chunk.
// ---------------------------------------------------------------------------
#define KCHUNK 64
#define NCHUNKv 24                    // 1536 / 64
#define TILE_B (128 * KCHUNK * 2)     // 16384 bytes (A or B tile)
#define STAGE_B (2 * TILE_B)          // 32768
#define GEMM_SMEM (3 * STAGE_B)       // 98304

__device__ __forceinline__ void cp_async16(uint32_t sp, const void* gp) {
    asm volatile("cp.async.cg.shared.global [%0], [%1], 16;" :: "r"(sp), "l"(gp));
}
__device__ __forceinline__ void cp_commit() {
    asm volatile("cp.async.commit_group;");
}

// load a 128x64 bf16 tile into swizzled smem (1024 granules of 16B, 4/thread)
// row stride = 128B (8 granules); swizzle cg ^= row&7
__device__ __forceinline__ void load_tile(
    uint32_t sbase, const __nv_bfloat16* __restrict__ src, int rowBase, int kk)
{
    #pragma unroll
    for (int i = 0; i < 4; i++) {
        const int g = threadIdx.x + i * 256;   // 0..1023
        const int row = g >> 3;
        const int cg = g & 7;
        const int cgs = cg ^ (row & 7);
        cp_async16(sbase + row * 128 + cgs * 16,
                   src + (size_t)(rowBase + row) * Dc + kk + cg * 8);
    }
}

__device__ __forceinline__ void ldsm_x4(uint32_t* r, uint32_t addr) {
    asm volatile("ldmatrix.sync.aligned.m8n8.x4.shared.b16 {%0,%1,%2,%3}, [%4];"
                 : "=r"(r[0]), "=r"(r[1]), "=r"(r[2]), "=r"(r[3]) : "r"(addr));
}
__device__ __forceinline__ void mma16816(
    float* d, const uint32_t* a, const uint32_t* b)
{
    asm volatile(
        "mma.sync.aligned.m16n8k16.row.col.f32.bf16.bf16.f32 "
        "{%0,%1,%2,%3}, {%4,%5,%6,%7}, {%8,%9}, {%0,%1,%2,%3};"
        : "+f"(d[0]), "+f"(d[1]), "+f"(d[2]), "+f"(d[3])
        : "r"(a[0]), "r"(a[1]), "r"(a[2]), "r"(a[3]), "r"(b[0]), "r"(b[1]));
}

__device__ void gemm_core(
    const __nv_bfloat16* __restrict__ Ah, const __nv_bfloat16* __restrict__ Al,
    const __nv_bfloat16* __restrict__ Wh, const __nv_bfloat16* __restrict__ Wl,
    const float* __restrict__ bias, float* __restrict__ dst,
    int rowBase, int colBase)
{
    extern __shared__ char dynsm[];

    const int tid = threadIdx.x;
    const int wid = tid >> 5;
    const int lane = tid & 31;
    const int wm = wid >> 2;       // 0..1
    const int wn = wid & 3;        // 0..3

    const uint32_t sb = smem_to_u32(dynsm);
    uint32_t stA[3], stB[3];
    #pragma unroll
    for (int s = 0; s < 3; s++) {
        stA[s] = sb + s * STAGE_B;
        stB[s] = stA[s] + TILE_B;
    }

    float acc[4][4][4];
    #pragma unroll
    for (int i = 0; i < 4; i++)
        #pragma unroll
        for (int j = 0; j < 4; j++)
            #pragma unroll
            for (int k = 0; k < 4; k++)
                acc[i][j][k] = 0.0f;

    // A frag lane addressing: 16 rows over lanes 0..15, k-granule = lane>>4
    int aRow[4], aR7[4];
    #pragma unroll
    for (int mi = 0; mi < 4; mi++) {
        const int r = wm * 64 + mi * 16 + (lane & 7) + (((lane >> 3) & 1) << 3);
        aRow[mi] = r * 128;
        aR7[mi] = r & 7;
    }
    const int aHi = lane >> 4;
    // B paired-x4 addressing: matrix m = lane>>3; ni = 2*pi + (lane>>4),
    // granule bit = (lane>>3)&1
    int bRowP[2], bR7P[2];
    #pragma unroll
    for (int pi = 0; pi < 2; pi++) {
        const int r = wn * 32 + (2 * pi + (lane >> 4)) * 8 + (lane & 7);
        bRowP[pi] = r * 128;
        bR7P[pi] = r & 7;
    }
    const int bG = (lane >> 3) & 1;

    // prologue: chunks 0,1 (segment 0) into stages 0,1
    #pragma unroll
    for (int c = 0; c < 2; c++) {
        load_tile(stA[c], Ah, rowBase, c * KCHUNK);
        load_tile(stB[c], Wh, colBase, c * KCHUNK);
        cp_commit();
    }

    for (int c = 0; c < NCHUNKv; c++) {
        asm volatile("cp.async.wait_group 1;");
        __syncthreads();

        // prefetch chunk c+2 into stage (c+2)%3 (drained last iteration)
        if (c + 2 < NCHUNKv) {
            const int cc = c + 2;
            const int seg = cc >> 3;               // 0,1,2 (8 chunks/segment)
            const int kk = (cc & 7) * KCHUNK;
            const __nv_bfloat16* As = (seg == 2) ? Al : Ah;
            const __nv_bfloat16* Ws = (seg == 1) ? Wl : Wh;
            const int st = cc - (cc / 3) * 3;
            load_tile(stA[st], As, rowBase, kk);
            load_tile(stB[st], Ws, colBase, kk);
            cp_commit();
        }

        const int cs = c - (c / 3) * 3;
        const uint32_t cA = stA[cs];
        const uint32_t cB = stB[cs];

        #pragma unroll
        for (int ks = 0; ks < 4; ks++) {
            uint32_t af[4][4], bf[4][2];
            #pragma unroll
            for (int mi = 0; mi < 4; mi++) {
                const int cg = (ks * 2 + aHi) ^ aR7[mi];
                ldsm_x4(af[mi], cA + aRow[mi] + cg * 16);
            }
            #pragma unroll
            for (int pi = 0; pi < 2; pi++) {
                const int cg = (ks * 2 + bG) ^ bR7P[pi];
                uint32_t t[4];
                ldsm_x4(t, cB + bRowP[pi] + cg * 16);
                bf[2 * pi][0] = t[0]; bf[2 * pi][1] = t[1];
                bf[2 * pi + 1][0] = t[2]; bf[2 * pi + 1][1] = t[3];
            }
            #pragma unroll
            for (int mi = 0; mi < 4; mi++)
                #pragma unroll
                for (int ni = 0; ni < 4; ni++)
                    mma16816(acc[mi][ni], af[mi], bf[ni]);
        }
    }

    // epilogue
    const int lr = lane >> 2;
    const int lc = (lane & 3) * 2;
    #pragma unroll
    for (int ni = 0; ni < 4; ni++) {
        const int col = colBase + wn * 32 + ni * 8 + lc;
        const float2 bb = *(const float2*)&bias[col];
        #pragma unroll
        for (int mi = 0; mi < 4; mi++) {
            const int row = rowBase + wm * 64 + mi * 16 + lr;
            float2 v0 = { acc[mi][ni][0] + bb.x, acc[mi][ni][1] + bb.y };
            float2 v1 = { acc[mi][ni][2] + bb.x, acc[mi][ni][3] + bb.y };
            *(float2*)&dst[(size_t)row * Dc + col] = v0;
            *(float2*)&dst[(size_t)(row + 8) * Dc + col] = v1;
        }
    }
}

__global__ __launch_bounds__(256, 2) void qkv_gemm_tc(
    const float* __restrict__ bq, const float* __restrict__ bk,
    const float* __restrict__ bv)
{
    const int z = blockIdx.z;
    const float* bias = (z == 0) ? bq : (z == 1) ? bk : bv;
    float* dst = (z == 0) ? g_Q : (z == 1) ? g_K : g_V;
    gemm_core(g_ah[z], g_al[z], g_wth[z], g_wtl[z], bias, dst,
              blockIdx.y * 128, blockIdx.x * 128);
}

__global__ __launch_bounds__(256, 2) void out_gemm_tc(
    const float* __restrict__ bo, float* __restrict__ out)
{
    gemm_core(g_ch, g_cl, g_wth[3], g_wtl[3], bo, out,
              blockIdx.y * 128, blockIdx.x * 128);
}

// ---------------------------------------------------------------------------
// fp32 -> bf16 hi/lo splits
// ---------------------------------------------------------------------------
__global__ __launch_bounds__(256) void split_inputs_kernel(
    const float* __restrict__ q, const float* __restrict__ k,
    const float* __restrict__ v)
{
    const int z = blockIdx.y;
    const float* src = (z == 0) ? q : (z == 1) ? k : v;
    const size_t i4 = (size_t)blockIdx.x * 256 + threadIdx.x;
    float4 f = ((const float4*)src)[i4];
    float a[4] = {f.x, f.y, f.z, f.w};
    __align__(8) __nv_bfloat16 h[4], lo[4];
    #pragma unroll
    for (int i = 0; i < 4; i++) {
        h[i] = __float2bfloat16_rn(a[i]);
        lo[i] = __float2bfloat16_rn(a[i] - __bfloat162float(h[i]));
    }
    *(uint2*)&g_ah[z][i4 * 4] = *(uint2*)h;
    *(uint2*)&g_al[z][i4 * 4] = *(uint2*)lo;
}

__global__ __launch_bounds__(1024) void split_weights_kernel(
    const float* __restrict__ Wq, const float* __restrict__ Wk,
    const float* __restrict__ Wv, const float* __restrict__ Wo)
{
    const int z = blockIdx.z;
    const float* w = (z == 0) ? Wq : (z == 1) ? Wk : (z == 2) ? Wv : Wo;
    __shared__ float s[32][33];
    const int tx = threadIdx.x & 31;
    const int ty = threadIdx.x >> 5;
    const int rb = blockIdx.y * 32;   // k block
    const int cb = blockIdx.x * 32;   // n block
    s[ty][tx] = w[(size_t)(rb + ty) * Dc + cb + tx];
    __syncthreads();
    const float a = s[tx][ty];        // = w[rb+tx][cb+ty]
    const __nv_bfloat16 h = __float2bfloat16_rn(a);
    const __nv_bfloat16 l = __float2bfloat16_rn(a - __bfloat162float(h));
    const size_t o = (size_t)(cb + ty) * Dc + rb + tx;   // [n][k]
    g_wth[z][o] = h;
    g_wtl[z][o] = l;
}

// ---------------------------------------------------------------------------
// Banded local attention. Plain exp-sum softmax (scores bounded).
// 8-lane groups per query; conflict-free LDS; dual query chains for ILP.
// Fused bf16 hi/lo ctx split.
// ---------------------------------------------------------------------------
#define TQ 64
#define HALO (TQ + 2 * Wc)    // 96
#define SKW 64

__global__ __launch_bounds__(256) void attn_kernel()
{
    __shared__ float sK[HALO * SKW];
    __shared__ float sV[HALO * SKW];

    const int bh = blockIdx.y;
    const int b = bh >> 3;
    const int h = bh & 7;
    const int q0 = blockIdx.x * TQ;
    const int kstart = q0 - Wc;
    const size_t rowBase = ((size_t)b * Sc) * Dc + h * DKc;

    for (int idx = threadIdx.x; idx < HALO * 16; idx += 256) {
        const int r = idx >> 4;
        const int c4 = idx & 15;
        const int j = kstart + r;
        float4 kv = {0, 0, 0, 0}, vv = {0, 0, 0, 0};
        if (j >= 0 && j < Sc) {
            const size_t off = rowBase + (size_t)j * Dc + c4 * 4;
            kv = *(const float4*)(g_K + off);
            vv = *(const float4*)(g_V + off);
        }
        *(float4*)(sK + r * SKW + c4 * 4) = kv;
        *(float4*)(sV + r * SKW + c4 * 4) = vv;
    }
    __syncthreads();

    const int warp = threadIdx.x >> 5;
    const int lane = threadIdx.x & 31;
    const int lq = lane >> 3;     // local query 0..3
    const int g = lane & 7;       // dim-group: words 4g..4g+3 and 32+4g..+3
    const int d0 = g * 4;
    const int d1 = 32 + g * 4;

    const int qA = q0 + warp * 8 + lq;
    const int qB = qA + 4;
    const int rA0 = qA - kstart - Wc;   // = warp*8 + lq
    const int rB0 = rA0 + 4;

    const size_t qoffA = rowBase + (size_t)qA * Dc;
    const size_t qoffB = rowBase + (size_t)qB * Dc;
    float4 qa0 = *(const float4*)(g_Q + qoffA + d0);
    float4 qa1 = *(const float4*)(g_Q + qoffA + d1);
    float4 qb0 = *(const float4*)(g_Q + qoffB + d0);
    float4 qb1 = *(const float4*)(g_Q + qoffB + d1);
    qa0.x *= 0.125f; qa0.y *= 0.125f; qa0.z *= 0.125f; qa0.w *= 0.125f;
    qa1.x *= 0.125f; qa1.y *= 0.125f; qa1.z *= 0.125f; qa1.w *= 0.125f;
    qb0.x *= 0.125f; qb0.y *= 0.125f; qb0.z *= 0.125f; qb0.w *= 0.125f;
    qb1.x *= 0.125f; qb1.y *= 0.125f; qb1.z *= 0.125f; qb1.w *= 0.125f;

    float lA = 0.0f, lB = 0.0f;
    float4 accA0 = {0,0,0,0}, accA1 = {0,0,0,0};
    float4 accB0 = {0,0,0,0}, accB1 = {0,0,0,0};

    #pragma unroll 4
    for (int s = 0; s <= 2 * Wc; s++) {
        const int jA = qA - Wc + s;
        const int jB = qB - Wc + s;
        const bool vA = (jA >= 0) && (jA < Sc);
        const bool vB = (jB >= 0) && (jB < Sc);
        const float* krA = sK + (rA0 + s) * SKW;
        const float* krB = sK + (rB0 + s) * SKW;

        const float4 kA0 = *(const float4*)(krA + d0);
        const float4 kA1 = *(const float4*)(krA + d1);
        const float4 kB0 = *(const float4*)(krB + d0);
        const float4 kB1 = *(const float4*)(krB + d1);

        float pA = qa0.x*kA0.x + qa0.y*kA0.y + qa0.z*kA0.z + qa0.w*kA0.w
                 + qa1.x*kA1.x + qa1.y*kA1.y + qa1.z*kA1.z + qa1.w*kA1.w;
        float pB = qb0.x*kB0.x + qb0.y*kB0.y + qb0.z*kB0.z + qb0.w*kB0.w
                 + qb1.x*kB1.x + qb1.y*kB1.y + qb1.z*kB1.z + qb1.w*kB1.w;

        pA += __shfl_xor_sync(0xffffffffu, pA, 1);
        pB += __shfl_xor_sync(0xffffffffu, pB, 1);
        pA += __shfl_xor_sync(0xffffffffu, pA, 2);
        pB += __shfl_xor_sync(0xffffffffu, pB, 2);
        pA += __shfl_xor_sync(0xffffffffu, pA, 4);
        pB += __shfl_xor_sync(0xffffffffu, pB, 4);

        const float wA = vA ? __expf(pA) : 0.0f;
        const float wB = vB ? __expf(pB) : 0.0f;

        const float* vrA = sV + (rA0 + s) * SKW;
        const float* vrB = sV + (rB0 + s) * SKW;
        const float4 vA0 = *(const float4*)(vrA + d0);
        const float4 vA1 = *(const float4*)(vrA + d1);
        const float4 vB0 = *(const float4*)(vrB + d0);
        const float4 vB1 = *(const float4*)(vrB + d1);

        accA0.x += wA * vA0.x; accA0.y += wA * vA0.y;
        accA0.z += wA * vA0.z; accA0.w += wA * vA0.w;
        accA1.x += wA * vA1.x; accA1.y += wA * vA1.y;
        accA1.z += wA * vA1.z; accA1.w += wA * vA1.w;
        accB0.x += wB * vB0.x; accB0.y += wB * vB0.y;
        accB0.z += wB * vB0.z; accB0.w += wB * vB0.w;
        accB1.x += wB * vB1.x; accB1.y += wB * vB1.y;
        accB1.z += wB * vB1.z; accB1.w += wB * vB1.w;
        lA += wA;
        lB += wB;
    }

    const float invA = 1.0f / lA;
    const float invB = 1.0f / lB;

    {
        float v[8] = {accA0.x*invA, accA0.y*invA, accA0.z*invA, accA0.w*invA,
                      accA1.x*invA, accA1.y*invA, accA1.z*invA, accA1.w*invA};
        __align__(8) __nv_bfloat16 hi[8], lo[8];
        #pragma unroll
        for (int d = 0; d < 8; d++) {
            hi[d] = __float2bfloat16_rn(v[d]);
            lo[d] = __float2bfloat16_rn(v[d] - __bfloat162float(hi[d]));
        }
        const size_t coff = ((size_t)(b * Sc + qA)) * Dc + h * DKc;
        *(uint2*)(g_ch + coff + d0) = *(uint2*)&hi[0];
        *(uint2*)(g_ch + coff + d1) = *(uint2*)&hi[4];
        *(uint2*)(g_cl + coff + d0) = *(uint2*)&lo[0];
        *(uint2*)(g_cl + coff + d1) = *(uint2*)&lo[4];
    }
    {
        float v[8] = {accB0.x*invB, accB0.y*invB, accB0.z*invB, accB0.w*invB,
                      accB1.x*invB, accB1.y*invB, accB1.z*invB, accB1.w*invB};
        __align__(8) __nv_bfloat16 hi[8], lo[8];
        #pragma unroll
        for (int d = 0; d < 8; d++) {
            hi[d] = __float2bfloat16_rn(v[d]);
            lo[d] = __float2bfloat16_rn(v[d] - __bfloat162float(hi[d]));
        }
        const size_t coff = ((size_t)(b * Sc + qB)) * Dc + h * DKc;
        *(uint2*)(g_ch + coff + d0) = *(uint2*)&hi[0];
        *(uint2*)(g_ch + coff + d1) = *(uint2*)&hi[4];
        *(uint2*)(g_cl + coff + d0) = *(uint2*)&lo[0];
        *(uint2*)(g_cl + coff + d1) = *(uint2*)&lo[4];
    }
}

// ---------------------------------------------------------------------------
// Launch
// ---------------------------------------------------------------------------
extern "C" void kernel_launch(void* const* d_in, const int* in_sizes, int n_in,
                              void* d_out, int out_size)
{
    const float* query = (const float*)d_in[0];
    const float* key   = (const float*)d_in[1];
    const float* value = (const float*)d_in[2];
    const float* Wq    = (const float*)d_in[3];
    const float* bq    = (const float*)d_in[4];
    const float* Wk    = (const float*)d_in[5];
    const float* bk    = (const float*)d_in[6];
    const float* Wv    = (const float*)d_in[7];
    const float* bv    = (const float*)d_in[8];
    const float* Wo    = (const float*)d_in[9];
    const float* bo    = (const float*)d_in[10];
    float* out = (float*)d_out;

    static bool attr_done = false;
    if (!attr_done) {
        cudaFuncSetAttribute(qkv_gemm_tc,
            cudaFuncAttributeMaxDynamicSharedMemorySize, GEMM_SMEM);
        cudaFuncSetAttribute(out_gemm_tc,
            cudaFuncAttributeMaxDynamicSharedMemorySize, GEMM_SMEM);
        attr_done = true;
    }

    // 1. fp32 -> bf16 hi/lo splits
    split_inputs_kernel<<<dim3(NELEM / 4 / 256, 3), 256>>>(query, key, value);
    split_weights_kernel<<<dim3(16, 16, 4), 1024>>>(Wq, Wk, Wv, Wo);

    // 2. QKV projections (HMMA bf16x3), K-chunk 64, 3-stage 96KB pipeline
    qkv_gemm_tc<<<dim3(4, 64, 3), 256, GEMM_SMEM>>>(bq, bk, bv);

    // 3. banded attention
    attn_kernel<<<dim3(Sc / TQ, Bc * Hc), 256>>>();

    // 4. output projection
    out_gemm_tc<<<dim3(4, 64), 256, GEMM_SMEM>>>(bo, out);
}

// round 7
// speedup vs baseline: 1.9946x; 1.1913x over previous
#include <cuda_runtime.h>
#include <cuda_bf16.h>
#include <cuda_fp16.h>
#include <cstdint>
#include <math.h>

// ---------------------------------------------------------------------------
// Problem constants
// ---------------------------------------------------------------------------
#define Bc  4
#define Sc  2048
#define Dc  512
#define Hc  8
#define Wc  16
#define DKc 64
#define Mtot (Bc * Sc)          // 8192
#define NELEM (Mtot * Dc)       // 4194304

// ---------------------------------------------------------------------------
// Device scratch
// ---------------------------------------------------------------------------
__device__ __half g_ah[3][NELEM];      // fp16 hi split of query/key/value
__device__ __half g_al[3][NELEM];      // fp16 lo split
__device__ __half g_wth[4][Dc * Dc];   // W^T hi (fp16): [n][k]
__device__ float g_Q[NELEM];           // projected, [m, 512]
__device__ float g_K[NELEM];
__device__ float g_V[NELEM];
__device__ __half g_ch[NELEM];         // ctx hi split [m, 512]
__device__ __half g_cl[NELEM];         // ctx lo split

__device__ __forceinline__ uint32_t smem_to_u32(const void* p) {
    uint32_t a;
    asm("{ .reg .u64 t; cvta.to.shared.u64 t, %1; cvt.u32.u64 %0, t; }"
        : "=r"(a) : "l"(p));
    return a;
}

// ---------------------------------------------------------------------------
// fp16 2-term GEMM via mma.sync: C = (Ah + Al) @ Wh^T + bias.
// Dropped term A@(W - Wh): ~2.8e-4 relative (fp16 rounding of W).
// Per 32-k chunk: load Ah, Al, Wh tiles (24KB); run BOTH A passes against
// the single Wh tile (B traffic halved). Virtual K = 1024.
// CTA tile 128x128, 256 thr (8 warps 2x4), warp tile 64x32,
// 3-stage cp.async pipeline (72KB dynamic smem), one sync per chunk.
// ---------------------------------------------------------------------------
#define KCHUNK 32
#define NCHUNK 16                     // 512 / 32
#define TILE_B (128 * KCHUNK * 2)     // 8192 bytes per tile
#define STAGE_B (3 * TILE_B)          // 24576 (Ah, Al, Wh)
#define GEMM_SMEM (3 * STAGE_B)       // 73728

__device__ __forceinline__ void cp_async16(uint32_t sp, const void* gp) {
    asm volatile("cp.async.cg.shared.global [%0], [%1], 16;" :: "r"(sp), "l"(gp));
}
__device__ __forceinline__ void cp_commit() {
    asm volatile("cp.async.commit_group;");
}

// load a 128x32 fp16 tile into swizzled smem (512 granules of 16B, 2/thread)
// row stride 64B (4 granules), swizzle cg ^= row&3
__device__ __forceinline__ void load_tile(
    uint32_t sbase, const __half* __restrict__ src, int rowBase, int kk)
{
    #pragma unroll
    for (int i = 0; i < 2; i++) {
        const int g = threadIdx.x + i * 256;   // 0..511
        const int row = g >> 2;
        const int cg = g & 3;
        const int cgs = cg ^ (row & 3);
        cp_async16(sbase + row * 64 + cgs * 16,
                   src + (size_t)(rowBase + row) * Dc + kk + cg * 8);
    }
}

__device__ __forceinline__ void ldsm_x4(uint32_t* r, uint32_t addr) {
    asm volatile("ldmatrix.sync.aligned.m8n8.x4.shared.b16 {%0,%1,%2,%3}, [%4];"
                 : "=r"(r[0]), "=r"(r[1]), "=r"(r[2]), "=r"(r[3]) : "r"(addr));
}
__device__ __forceinline__ void mma16816(
    float* d, const uint32_t* a, const uint32_t* b)
{
    asm volatile(
        "mma.sync.aligned.m16n8k16.row.col.f32.f16.f16.f32 "
        "{%0,%1,%2,%3}, {%4,%5,%6,%7}, {%8,%9}, {%0,%1,%2,%3};"
        : "+f"(d[0]), "+f"(d[1]), "+f"(d[2]), "+f"(d[3])
        : "r"(a[0]), "r"(a[1]), "r"(a[2]), "r"(a[3]), "r"(b[0]), "r"(b[1]));
}

__device__ void gemm_core(
    const __half* __restrict__ Ah, const __half* __restrict__ Al,
    const __half* __restrict__ Wh,
    const float* __restrict__ bias, float* __restrict__ dst,
    int rowBase, int colBase)
{
    extern __shared__ char dynsm[];

    const int tid = threadIdx.x;
    const int wid = tid >> 5;
    const int lane = tid & 31;
    const int wm = wid >> 2;       // 0..1
    const int wn = wid & 3;        // 0..3

    const uint32_t sb = smem_to_u32(dynsm);
    // stage s: Ah at +0, Al at +TILE_B, Wh at +2*TILE_B
    uint32_t stg[3];
    #pragma unroll
    for (int s = 0; s < 3; s++) stg[s] = sb + s * STAGE_B;

    float acc[4][4][4];
    #pragma unroll
    for (int i = 0; i < 4; i++)
        #pragma unroll
        for (int j = 0; j < 4; j++)
            #pragma unroll
            for (int k = 0; k < 4; k++)
                acc[i][j][k] = 0.0f;

    // A frag addressing (64B rows, 4 granules, swizzle &3)
    int aRow[4], aR3[4];
    #pragma unroll
    for (int mi = 0; mi < 4; mi++) {
        const int r = wm * 64 + mi * 16 + (lane & 7) + (((lane >> 3) & 1) << 3);
        aRow[mi] = r * 64;
        aR3[mi] = r & 3;
    }
    const int aHi = lane >> 4;
    // B paired-x4 addressing
    int bRowP[2], bR3P[2];
    #pragma unroll
    for (int pi = 0; pi < 2; pi++) {
        const int r = wn * 32 + (2 * pi + (lane >> 4)) * 8 + (lane & 7);
        bRowP[pi] = r * 64;
        bR3P[pi] = r & 3;
    }
    const int bG = (lane >> 3) & 1;

    // prologue: chunks 0,1 into stages 0,1
    #pragma unroll
    for (int c = 0; c < 2; c++) {
        load_tile(stg[c] + 0 * TILE_B, Ah, rowBase, c * KCHUNK);
        load_tile(stg[c] + 1 * TILE_B, Al, rowBase, c * KCHUNK);
        load_tile(stg[c] + 2 * TILE_B, Wh, colBase, c * KCHUNK);
        cp_commit();
    }

    for (int c = 0; c < NCHUNK; c++) {
        if (c < NCHUNK - 2) asm volatile("cp.async.wait_group 1;");
        else                asm volatile("cp.async.wait_group 0;");
        __syncthreads();

        if (c + 2 < NCHUNK) {
            const int cc = c + 2;
            const int kk = cc * KCHUNK;
            const int st = cc - (cc / 3) * 3;
            load_tile(stg[st] + 0 * TILE_B, Ah, rowBase, kk);
            load_tile(stg[st] + 1 * TILE_B, Al, rowBase, kk);
            load_tile(stg[st] + 2 * TILE_B, Wh, colBase, kk);
            cp_commit();
        }

        const int cs = c - (c / 3) * 3;
        const uint32_t cBase = stg[cs];
        const uint32_t cB = cBase + 2 * TILE_B;

        // B fragments once per chunk (reused by both A passes)
        uint32_t bf[2][4][2];
        #pragma unroll
        for (int ks = 0; ks < 2; ks++) {
            #pragma unroll
            for (int pi = 0; pi < 2; pi++) {
                const int cg = (ks * 2 + bG) ^ bR3P[pi];
                uint32_t t[4];
                ldsm_x4(t, cB + bRowP[pi] + cg * 16);
                bf[ks][2 * pi][0] = t[0]; bf[ks][2 * pi][1] = t[1];
                bf[ks][2 * pi + 1][0] = t[2]; bf[ks][2 * pi + 1][1] = t[3];
            }
        }

        // two A passes: Ah then Al, both against Wh
        #pragma unroll
        for (int seg = 0; seg < 2; seg++) {
            const uint32_t cA = cBase + seg * TILE_B;
            #pragma unroll
            for (int ks = 0; ks < 2; ks++) {
                uint32_t af[4][4];
                #pragma unroll
                for (int mi = 0; mi < 4; mi++) {
                    const int cg = (ks * 2 + aHi) ^ aR3[mi];
                    ldsm_x4(af[mi], cA + aRow[mi] + cg * 16);
                }
                #pragma unroll
                for (int mi = 0; mi < 4; mi++)
                    #pragma unroll
                    for (int ni = 0; ni < 4; ni++)
                        mma16816(acc[mi][ni], af[mi], bf[ks][ni]);
            }
        }
    }

    // epilogue
    const int lr = lane >> 2;
    const int lc = (lane & 3) * 2;
    #pragma unroll
    for (int ni = 0; ni < 4; ni++) {
        const int col = colBase + wn * 32 + ni * 8 + lc;
        const float2 bb = *(const float2*)&bias[col];
        #pragma unroll
        for (int mi = 0; mi < 4; mi++) {
            const int row = rowBase + wm * 64 + mi * 16 + lr;
            float2 v0 = { acc[mi][ni][0] + bb.x, acc[mi][ni][1] + bb.y };
            float2 v1 = { acc[mi][ni][2] + bb.x, acc[mi][ni][3] + bb.y };
            *(float2*)&dst[(size_t)row * Dc + col] = v0;
            *(float2*)&dst[(size_t)(row + 8) * Dc + col] = v1;
        }
    }
}

__global__ __launch_bounds__(256, 2) void qkv_gemm_tc(
    const float* __restrict__ bq, const float* __restrict__ bk,
    const float* __restrict__ bv)
{
    const int z = blockIdx.z;
    const float* bias = (z == 0) ? bq : (z == 1) ? bk : bv;
    float* dst = (z == 0) ? g_Q : (z == 1) ? g_K : g_V;
    gemm_core(g_ah[z], g_al[z], g_wth[z], bias, dst,
              blockIdx.y * 128, blockIdx.x * 128);
}

__global__ __launch_bounds__(256, 2) void out_gemm_tc(
    const float* __restrict__ bo, float* __restrict__ out)
{
    gemm_core(g_ch, g_cl, g_wth[3], bo, out,
              blockIdx.y * 128, blockIdx.x * 128);
}

// ---------------------------------------------------------------------------
// fp32 -> fp16 hi/lo splits
// ---------------------------------------------------------------------------
__global__ __launch_bounds__(256) void split_inputs_kernel(
    const float* __restrict__ q, const float* __restrict__ k,
    const float* __restrict__ v)
{
    const int z = blockIdx.y;
    const float* src = (z == 0) ? q : (z == 1) ? k : v;
    const size_t i4 = (size_t)blockIdx.x * 256 + threadIdx.x;
    float4 f = ((const float4*)src)[i4];
    float a[4] = {f.x, f.y, f.z, f.w};
    __align__(8) __half h[4], lo[4];
    #pragma unroll
    for (int i = 0; i < 4; i++) {
        h[i] = __float2half_rn(a[i]);
        lo[i] = __float2half_rn(a[i] - __half2float(h[i]));
    }
    *(uint2*)&g_ah[z][i4 * 4] = *(uint2*)h;
    *(uint2*)&g_al[z][i4 * 4] = *(uint2*)lo;
}

// tiled transpose + fp16 round: g_wth[z][n][k] = fp16(w[k][n])
__global__ __launch_bounds__(1024) void split_weights_kernel(
    const float* __restrict__ Wq, const float* __restrict__ Wk,
    const float* __restrict__ Wv, const float* __restrict__ Wo)
{
    const int z = blockIdx.z;
    const float* w = (z == 0) ? Wq : (z == 1) ? Wk : (z == 2) ? Wv : Wo;
    __shared__ float s[32][33];
    const int tx = threadIdx.x & 31;
    const int ty = threadIdx.x >> 5;
    const int rb = blockIdx.y * 32;   // k block
    const int cb = blockIdx.x * 32;   // n block
    s[ty][tx] = w[(size_t)(rb + ty) * Dc + cb + tx];
    __syncthreads();
    const float a = s[tx][ty];        // = w[rb+tx][cb+ty]
    g_wth[z][(size_t)(cb + ty) * Dc + rb + tx] = __float2half_rn(a);
}

// ---------------------------------------------------------------------------
// Banded local attention. Plain exp-sum softmax (scores bounded).
// 8-lane groups per query; conflict-free LDS; dual query chains for ILP.
// Fused fp16 hi/lo ctx split for the output projection.
// ---------------------------------------------------------------------------
#define TQ 64
#define HALO (TQ + 2 * Wc)    // 96
#define SKW 64

__global__ __launch_bounds__(256) void attn_kernel()
{
    __shared__ float sK[HALO * SKW];
    __shared__ float sV[HALO * SKW];

    const int bh = blockIdx.y;
    const int b = bh >> 3;
    const int h = bh & 7;
    const int q0 = blockIdx.x * TQ;
    const int kstart = q0 - Wc;
    const size_t rowBase = ((size_t)b * Sc) * Dc + h * DKc;

    for (int idx = threadIdx.x; idx < HALO * 16; idx += 256) {
        const int r = idx >> 4;
        const int c4 = idx & 15;
        const int j = kstart + r;
        float4 kv = {0, 0, 0, 0}, vv = {0, 0, 0, 0};
        if (j >= 0 && j < Sc) {
            const size_t off = rowBase + (size_t)j * Dc + c4 * 4;
            kv = *(const float4*)(g_K + off);
            vv = *(const float4*)(g_V + off);
        }
        *(float4*)(sK + r * SKW + c4 * 4) = kv;
        *(float4*)(sV + r * SKW + c4 * 4) = vv;
    }
    __syncthreads();

    const int warp = threadIdx.x >> 5;
    const int lane = threadIdx.x & 31;
    const int lq = lane >> 3;     // local query 0..3
    const int g = lane & 7;       // dim-group: words 4g..4g+3 and 32+4g..+3
    const int d0 = g * 4;
    const int d1 = 32 + g * 4;

    const int qA = q0 + warp * 8 + lq;
    const int qB = qA + 4;
    const int rA0 = qA - kstart - Wc;   // = warp*8 + lq
    const int rB0 = rA0 + 4;

    const size_t qoffA = rowBase + (size_t)qA * Dc;
    const size_t qoffB = rowBase + (size_t)qB * Dc;
    float4 qa0 = *(const float4*)(g_Q + qoffA + d0);
    float4 qa1 = *(const float4*)(g_Q + qoffA + d1);
    float4 qb0 = *(const float4*)(g_Q + qoffB + d0);
    float4 qb1 = *(const float4*)(g_Q + qoffB + d1);
    qa0.x *= 0.125f; qa0.y *= 0.125f; qa0.z *= 0.125f; qa0.w *= 0.125f;
    qa1.x *= 0.125f; qa1.y *= 0.125f; qa1.z *= 0.125f; qa1.w *= 0.125f;
    qb0.x *= 0.125f; qb0.y *= 0.125f; qb0.z *= 0.125f; qb0.w *= 0.125f;
    qb1.x *= 0.125f; qb1.y *= 0.125f; qb1.z *= 0.125f; qb1.w *= 0.125f;

    float lA = 0.0f, lB = 0.0f;
    float4 accA0 = {0,0,0,0}, accA1 = {0,0,0,0};
    float4 accB0 = {0,0,0,0}, accB1 = {0,0,0,0};

    #pragma unroll 4
    for (int s = 0; s <= 2 * Wc; s++) {
        const int jA = qA - Wc + s;
        const int jB = qB - Wc + s;
        const bool vA = (jA >= 0) && (jA < Sc);
        const bool vB = (jB >= 0) && (jB < Sc);
        const float* krA = sK + (rA0 + s) * SKW;
        const float* krB = sK + (rB0 + s) * SKW;

        const float4 kA0 = *(const float4*)(krA + d0);
        const float4 kA1 = *(const float4*)(krA + d1);
        const float4 kB0 = *(const float4*)(krB + d0);
        const float4 kB1 = *(const float4*)(krB + d1);

        float pA = qa0.x*kA0.x + qa0.y*kA0.y + qa0.z*kA0.z + qa0.w*kA0.w
                 + qa1.x*kA1.x + qa1.y*kA1.y + qa1.z*kA1.z + qa1.w*kA1.w;
        float pB = qb0.x*kB0.x + qb0.y*kB0.y + qb0.z*kB0.z + qb0.w*kB0.w
                 + qb1.x*kB1.x + qb1.y*kB1.y + qb1.z*kB1.z + qb1.w*kB1.w;

        pA += __shfl_xor_sync(0xffffffffu, pA, 1);
        pB += __shfl_xor_sync(0xffffffffu, pB, 1);
        pA += __shfl_xor_sync(0xffffffffu, pA, 2);
        pB += __shfl_xor_sync(0xffffffffu, pB, 2);
        pA += __shfl_xor_sync(0xffffffffu, pA, 4);
        pB += __shfl_xor_sync(0xffffffffu, pB, 4);

        const float wA = vA ? __expf(pA) : 0.0f;
        const float wB = vB ? __expf(pB) : 0.0f;

        const float* vrA = sV + (rA0 + s) * SKW;
        const float* vrB = sV + (rB0 + s) * SKW;
        const float4 vA0 = *(const float4*)(vrA + d0);
        const float4 vA1 = *(const float4*)(vrA + d1);
        const float4 vB0 = *(const float4*)(vrB + d0);
        const float4 vB1 = *(const float4*)(vrB + d1);

        accA0.x += wA * vA0.x; accA0.y += wA * vA0.y;
        accA0.z += wA * vA0.z; accA0.w += wA * vA0.w;
        accA1.x += wA * vA1.x; accA1.y += wA * vA1.y;
        accA1.z += wA * vA1.z; accA1.w += wA * vA1.w;
        accB0.x += wB * vB0.x; accB0.y += wB * vB0.y;
        accB0.z += wB * vB0.z; accB0.w += wB * vB0.w;
        accB1.x += wB * vB1.x; accB1.y += wB * vB1.y;
        accB1.z += wB * vB1.z; accB1.w += wB * vB1.w;
        lA += wA;
        lB += wB;
    }

    const float invA = 1.0f / lA;
    const float invB = 1.0f / lB;

    {
        float v[8] = {accA0.x*invA, accA0.y*invA, accA0.z*invA, accA0.w*invA,
                      accA1.x*invA, accA1.y*invA, accA1.z*invA, accA1.w*invA};
        __align__(8) __half hi[8], lo[8];
        #pragma unroll
        for (int d = 0; d < 8; d++) {
            hi[d] = __float2half_rn(v[d]);
            lo[d] = __float2half_rn(v[d] - __half2float(hi[d]));
        }
        const size_t coff = ((size_t)(b * Sc + qA)) * Dc + h * DKc;
        *(uint2*)(g_ch + coff + d0) = *(uint2*)&hi[0];
        *(uint2*)(g_ch + coff + d1) = *(uint2*)&hi[4];
        *(uint2*)(g_cl + coff + d0) = *(uint2*)&lo[0];
        *(uint2*)(g_cl + coff + d1) = *(uint2*)&lo[4];
    }
    {
        float v[8] = {accB0.x*invB, accB0.y*invB, accB0.z*invB, accB0.w*invB,
                      accB1.x*invB, accB1.y*invB, accB1.z*invB, accB1.w*invB};
        __align__(8) __half hi[8], lo[8];
        #pragma unroll
        for (int d = 0; d < 8; d++) {
            hi[d] = __float2half_rn(v[d]);
            lo[d] = __float2half_rn(v[d] - __half2float(hi[d]));
        }
        const size_t coff = ((size_t)(b * Sc + qB)) * Dc + h * DKc;
        *(uint2*)(g_ch + coff + d0) = *(uint2*)&hi[0];
        *(uint2*)(g_ch + coff + d1) = *(uint2*)&hi[4];
        *(uint2*)(g_cl + coff + d0) = *(uint2*)&lo[0];
        *(uint2*)(g_cl + coff + d1) = *(uint2*)&lo[4];
    }
}

// ---------------------------------------------------------------------------
// Launch
// ---------------------------------------------------------------------------
extern "C" void kernel_launch(void* const* d_in, const int* in_sizes, int n_in,
                              void* d_out, int out_size)
{
    const float* query = (const float*)d_in[0];
    const float* key   = (const float*)d_in[1];
    const float* value = (const float*)d_in[2];
    const float* Wq    = (const float*)d_in[3];
    const float* bq    = (const float*)d_in[4];
    const float* Wk    = (const float*)d_in[5];
    const float* bk    = (const float*)d_in[6];
    const float* Wv    = (const float*)d_in[7];
    const float* bv    = (const float*)d_in[8];
    const float* Wo    = (const float*)d_in[9];
    const float* bo    = (const float*)d_in[10];
    float* out = (float*)d_out;

    static bool attr_done = false;
    if (!attr_done) {
        cudaFuncSetAttribute(qkv_gemm_tc,
            cudaFuncAttributeMaxDynamicSharedMemorySize, GEMM_SMEM);
        cudaFuncSetAttribute(out_gemm_tc,
            cudaFuncAttributeMaxDynamicSharedMemorySize, GEMM_SMEM);
        attr_done = true;
    }

    // 1. fp32 -> fp16 hi/lo splits (weights: hi only, transposed)
    split_inputs_kernel<<<dim3(NELEM / 4 / 256, 3), 256>>>(query, key, value);
    split_weights_kernel<<<dim3(16, 16, 4), 1024>>>(Wq, Wk, Wv, Wo);

    // 2. QKV projections (fp16 2-term HMMA, shared-B chunks)
    qkv_gemm_tc<<<dim3(4, 64, 3), 256, GEMM_SMEM>>>(bq, bk, bv);

    // 3. banded attention
    attn_kernel<<<dim3(Sc / TQ, Bc * Hc), 256>>>();

    // 4. output projection
    out_gemm_tc<<<dim3(4, 64), 256, GEMM_SMEM>>>(bo, out);
}

// round 8
// speedup vs baseline: 2.2191x; 1.1126x over previous
#include <cuda_runtime.h>
#include <cuda_bf16.h>
#include <cuda_fp16.h>
#include <cstdint>
#include <math.h>

// ---------------------------------------------------------------------------
// Problem constants
// ---------------------------------------------------------------------------
#define Bc  4
#define Sc  2048
#define Dc  512
#define Hc  8
#define Wc  16
#define DKc 64
#define Mtot (Bc * Sc)          // 8192
#define NELEM (Mtot * Dc)       // 4194304

// ---------------------------------------------------------------------------
// Device scratch
// ---------------------------------------------------------------------------
__device__ __half g_ah[3][NELEM];      // fp16 hi split of query/key/value
__device__ __half g_al[3][NELEM];      // fp16 lo split
__device__ __half g_wth[4][Dc * Dc];   // W^T hi (fp16): [n][k]
__device__ __half g_qs[NELEM];         // projected Q fp16, [bh][s][64], prescaled 0.125
__device__ __half g_ks[NELEM];         // projected K fp16, [bh][s][64]
__device__ __half g_vs[NELEM];         // projected V fp16, [bh][s][64]
__device__ __half g_ch[NELEM];         // ctx hi split [m, 512]
__device__ __half g_cl[NELEM];         // ctx lo split

__device__ __forceinline__ uint32_t smem_to_u32(const void* p) {
    uint32_t a;
    asm("{ .reg .u64 t; cvta.to.shared.u64 t, %1; cvt.u32.u64 %0, t; }"
        : "=r"(a) : "l"(p));
    return a;
}

__device__ __forceinline__ void cp_async16(uint32_t sp, const void* gp) {
    asm volatile("cp.async.cg.shared.global [%0], [%1], 16;" :: "r"(sp), "l"(gp));
}
__device__ __forceinline__ void cp_commit() {
    asm volatile("cp.async.commit_group;");
}
__device__ __forceinline__ void ldsm_x4(uint32_t* r, uint32_t addr) {
    asm volatile("ldmatrix.sync.aligned.m8n8.x4.shared.b16 {%0,%1,%2,%3}, [%4];"
                 : "=r"(r[0]), "=r"(r[1]), "=r"(r[2]), "=r"(r[3]) : "r"(addr));
}
__device__ __forceinline__ void mma16816(
    float* d, const uint32_t* a, const uint32_t* b)
{
    asm volatile(
        "mma.sync.aligned.m16n8k16.row.col.f32.f16.f16.f32 "
        "{%0,%1,%2,%3}, {%4,%5,%6,%7}, {%8,%9}, {%0,%1,%2,%3};"
        : "+f"(d[0]), "+f"(d[1]), "+f"(d[2]), "+f"(d[3])
        : "r"(a[0]), "r"(a[1]), "r"(a[2]), "r"(a[3]), "r"(b[0]), "r"(b[1]));
}
__device__ __forceinline__ uint32_t pack_h2(float a, float b) {
    __half2 h = __floats2half2_rn(a, b);
    return *(uint32_t*)&h;
}

// ---------------------------------------------------------------------------
// fp16 2-term GEMM via mma.sync: C = (Ah + Al) @ Wh^T + bias.
// CTA tile 128x128, 256 thr (8 warps 2x4), warp tile 64x32, K-chunk 32,
// 3-stage cp.async pipeline (72KB dynamic smem). MODE 0: f32 output (+bias).
// MODE 1: fp16 scatter to [bh][s][64] with output scale.
// ---------------------------------------------------------------------------
#define KCHUNK 32
#define NCHUNK 16                     // 512 / 32
#define TILE_B (128 * KCHUNK * 2)     // 8192 bytes per tile
#define STAGE_B (3 * TILE_B)          // 24576 (Ah, Al, Wh)
#define GEMM_SMEM (3 * STAGE_B)       // 73728

__device__ __forceinline__ void load_tile(
    uint32_t sbase, const __half* __restrict__ src, int rowBase, int kk)
{
    #pragma unroll
    for (int i = 0; i < 2; i++) {
        const int g = threadIdx.x + i * 256;   // 0..511
        const int row = g >> 2;
        const int cg = g & 3;
        const int cgs = cg ^ (row & 3);
        cp_async16(sbase + row * 64 + cgs * 16,
                   src + (size_t)(rowBase + row) * Dc + kk + cg * 8);
    }
}

template <int MODE>
__device__ void gemm_core(
    const __half* __restrict__ Ah, const __half* __restrict__ Al,
    const __half* __restrict__ Wh, const float* __restrict__ bias,
    float* __restrict__ dstF, __half* __restrict__ dstH,
    int rowBase, int colBase, float oscale)
{
    extern __shared__ char dynsm[];

    const int tid = threadIdx.x;
    const int wid = tid >> 5;
    const int lane = tid & 31;
    const int wm = wid >> 2;       // 0..1
    const int wn = wid & 3;        // 0..3

    const uint32_t sb = smem_to_u32(dynsm);
    uint32_t stg[3];
    #pragma unroll
    for (int s = 0; s < 3; s++) stg[s] = sb + s * STAGE_B;

    float acc[4][4][4];
    #pragma unroll
    for (int i = 0; i < 4; i++)
        #pragma unroll
        for (int j = 0; j < 4; j++)
            #pragma unroll
            for (int k = 0; k < 4; k++)
                acc[i][j][k] = 0.0f;

    int aRow[4], aR3[4];
    #pragma unroll
    for (int mi = 0; mi < 4; mi++) {
        const int r = wm * 64 + mi * 16 + (lane & 7) + (((lane >> 3) & 1) << 3);
        aRow[mi] = r * 64;
        aR3[mi] = r & 3;
    }
    const int aHi = lane >> 4;
    int bRowP[2], bR3P[2];
    #pragma unroll
    for (int pi = 0; pi < 2; pi++) {
        const int r = wn * 32 + (2 * pi + (lane >> 4)) * 8 + (lane & 7);
        bRowP[pi] = r * 64;
        bR3P[pi] = r & 3;
    }
    const int bG = (lane >> 3) & 1;

    #pragma unroll
    for (int c = 0; c < 2; c++) {
        load_tile(stg[c] + 0 * TILE_B, Ah, rowBase, c * KCHUNK);
        load_tile(stg[c] + 1 * TILE_B, Al, rowBase, c * KCHUNK);
        load_tile(stg[c] + 2 * TILE_B, Wh, colBase, c * KCHUNK);
        cp_commit();
    }

    for (int c = 0; c < NCHUNK; c++) {
        if (c < NCHUNK - 2) asm volatile("cp.async.wait_group 1;");
        else                asm volatile("cp.async.wait_group 0;");
        __syncthreads();

        if (c + 2 < NCHUNK) {
            const int cc = c + 2;
            const int kk = cc * KCHUNK;
            const int st = cc - (cc / 3) * 3;
            load_tile(stg[st] + 0 * TILE_B, Ah, rowBase, kk);
            load_tile(stg[st] + 1 * TILE_B, Al, rowBase, kk);
            load_tile(stg[st] + 2 * TILE_B, Wh, colBase, kk);
            cp_commit();
        }

        const int cs = c - (c / 3) * 3;
        const uint32_t cBase = stg[cs];
        const uint32_t cB = cBase + 2 * TILE_B;

        uint32_t bf[2][4][2];
        #pragma unroll
        for (int ks = 0; ks < 2; ks++) {
            #pragma unroll
            for (int pi = 0; pi < 2; pi++) {
                const int cg = (ks * 2 + bG) ^ bR3P[pi];
                uint32_t t[4];
                ldsm_x4(t, cB + bRowP[pi] + cg * 16);
                bf[ks][2 * pi][0] = t[0]; bf[ks][2 * pi][1] = t[1];
                bf[ks][2 * pi + 1][0] = t[2]; bf[ks][2 * pi + 1][1] = t[3];
            }
        }

        #pragma unroll
        for (int seg = 0; seg < 2; seg++) {
            const uint32_t cA = cBase + seg * TILE_B;
            #pragma unroll
            for (int ks = 0; ks < 2; ks++) {
                uint32_t af[4][4];
                #pragma unroll
                for (int mi = 0; mi < 4; mi++) {
                    const int cg = (ks * 2 + aHi) ^ aR3[mi];
                    ldsm_x4(af[mi], cA + aRow[mi] + cg * 16);
                }
                #pragma unroll
                for (int mi = 0; mi < 4; mi++)
                    #pragma unroll
                    for (int ni = 0; ni < 4; ni++)
                        mma16816(acc[mi][ni], af[mi], bf[ks][ni]);
            }
        }
    }

    // epilogue
    const int lr = lane >> 2;
    const int lc = (lane & 3) * 2;
    #pragma unroll
    for (int ni = 0; ni < 4; ni++) {
        const int col = colBase + wn * 32 + ni * 8 + lc;
        const float2 bb = *(const float2*)&bias[col];
        #pragma unroll
        for (int mi = 0; mi < 4; mi++) {
            const int row = rowBase + wm * 64 + mi * 16 + lr;
            float2 v0 = { (acc[mi][ni][0] + bb.x) * oscale,
                          (acc[mi][ni][1] + bb.y) * oscale };
            float2 v1 = { (acc[mi][ni][2] + bb.x) * oscale,
                          (acc[mi][ni][3] + bb.y) * oscale };
            if (MODE == 0) {
                *(float2*)&dstF[(size_t)row * Dc + col] = v0;
                *(float2*)&dstF[(size_t)(row + 8) * Dc + col] = v1;
            } else {
                const int h = col >> 6;
                const int dk = col & 63;
                const int b = row >> 11;
                const int s = row & (Sc - 1);
                const size_t a0 = (((size_t)(b * Hc + h) * Sc + s)) * 64 + dk;
                const size_t a1 = a0 + 8 * 64;
                *(uint32_t*)&dstH[a0] = pack_h2(v0.x, v0.y);
                *(uint32_t*)&dstH[a1] = pack_h2(v1.x, v1.y);
            }
        }
    }
}

__global__ __launch_bounds__(256, 2) void qkv_gemm_tc(
    const float* __restrict__ bq, const float* __restrict__ bk,
    const float* __restrict__ bv)
{
    const int z = blockIdx.z;
    const float* bias = (z == 0) ? bq : (z == 1) ? bk : bv;
    __half* dst = (z == 0) ? g_qs : (z == 1) ? g_ks : g_vs;
    const float sc = (z == 0) ? 0.125f : 1.0f;   // fold 1/sqrt(DK) into Q
    gemm_core<1>(g_ah[z], g_al[z], g_wth[z], bias, nullptr, dst,
                 blockIdx.y * 128, blockIdx.x * 128, sc);
}

__global__ __launch_bounds__(256, 2) void out_gemm_tc(
    const float* __restrict__ bo, float* __restrict__ out)
{
    gemm_core<0>(g_ch, g_cl, g_wth[3], bo, out, nullptr,
                 blockIdx.y * 128, blockIdx.x * 128, 1.0f);
}

// ---------------------------------------------------------------------------
// fp32 -> fp16 hi/lo splits
// ---------------------------------------------------------------------------
__global__ __launch_bounds__(256) void split_inputs_kernel(
    const float* __restrict__ q, const float* __restrict__ k,
    const float* __restrict__ v)
{
    const int z = blockIdx.y;
    const float* src = (z == 0) ? q : (z == 1) ? k : v;
    const size_t i4 = (size_t)blockIdx.x * 256 + threadIdx.x;
    float4 f = ((const float4*)src)[i4];
    float a[4] = {f.x, f.y, f.z, f.w};
    __align__(8) __half h[4], lo[4];
    #pragma unroll
    for (int i = 0; i < 4; i++) {
        h[i] = __float2half_rn(a[i]);
        lo[i] = __float2half_rn(a[i] - __half2float(h[i]));
    }
    *(uint2*)&g_ah[z][i4 * 4] = *(uint2*)h;
    *(uint2*)&g_al[z][i4 * 4] = *(uint2*)lo;
}

__global__ __launch_bounds__(1024) void split_weights_kernel(
    const float* __restrict__ Wq, const float* __restrict__ Wk,
    const float* __restrict__ Wv, const float* __restrict__ Wo)
{
    const int z = blockIdx.z;
    const float* w = (z == 0) ? Wq : (z == 1) ? Wk : (z == 2) ? Wv : Wo;
    __shared__ float s[32][33];
    const int tx = threadIdx.x & 31;
    const int ty = threadIdx.x >> 5;
    const int rb = blockIdx.y * 32;   // k block
    const int cb = blockIdx.x * 32;   // n block
    s[ty][tx] = w[(size_t)(rb + ty) * Dc + cb + tx];
    __syncthreads();
    const float a = s[tx][ty];        // = w[rb+tx][cb+ty]
    g_wth[z][(size_t)(cb + ty) * Dc + rb + tx] = __float2half_rn(a);
}

// ---------------------------------------------------------------------------
// Banded local attention via HMMA (fp16 mma.sync).
// Per CTA: (bh, 64-query tile). S = Q(64x64) @ K^T(96x64), band mask + exp,
// ctx = P(64x96) @ V(96x64). 8 warps as 4(m) x 2(n); wn halves combined in
// smem. P A-fragments come directly from S C-fragments (FA2 layout identity).
// ---------------------------------------------------------------------------
#define TQ 64
#define HALO 96
// dynamic smem layout (bytes):
#define A_SQ 0                       // Q tile: 64 rows x 128B, swizzle ^(r&7)
#define A_SK 8192                    // K tile: 96 rows x 128B, swizzle ^(r&7)
#define A_SV 20480                   // V^T: 64 rows x 208B (104 fp16), no swizzle
#define A_SC 33792                   // combine: 64x64 f32
#define A_SL 50176                   // rowsums: float[2][64]
#define ATTN_SMEM 50688

__global__ __launch_bounds__(256) void attn_kernel()
{
    extern __shared__ char dynsm[];
    const uint32_t sb = smem_to_u32(dynsm);
    const int tid = threadIdx.x;
    const int bh = blockIdx.y;
    const int q0 = blockIdx.x * TQ;
    const int kstart = q0 - Wc;
    const size_t base = (size_t)bh * Sc * 64;

    // 1) zero K + V regions (handles out-of-range halo rows)
    for (int i = tid; i < 1600; i += 256)
        *(uint4*)(dynsm + A_SK + i * 16) = make_uint4(0, 0, 0, 0);
    __syncthreads();

    // 2) async-load Q (64x8 granules) and valid K rows (96x8)
    for (int i = tid; i < 512; i += 256) {
        const int row = i >> 3, cg = i & 7;
        cp_async16(sb + A_SQ + row * 128 + ((cg ^ (row & 7)) * 16),
                   g_qs + base + (size_t)(q0 + row) * 64 + cg * 8);
    }
    for (int i = tid; i < 768; i += 256) {
        const int row = i >> 3, cg = i & 7;
        const int j = kstart + row;
        if (j >= 0 && j < Sc)
            cp_async16(sb + A_SK + row * 128 + ((cg ^ (row & 7)) * 16),
                       g_ks + base + (size_t)j * 64 + cg * 8);
    }
    cp_commit();

    // 3) transpose-load V: [key][dk] -> sVt[dk][key], 208B rows (stride 104)
    __half* sVt = (__half*)(dynsm + A_SV);
    for (int i = tid; i < HALO * 16; i += 256) {
        const int row = i >> 4;      // key index in halo
        const int c4 = i & 15;       // 4-dk group
        const int j = kstart + row;
        if (j >= 0 && j < Sc) {
            uint2 v = *(const uint2*)(g_vs + base + (size_t)j * 64 + c4 * 4);
            const __half* hp = (const __half*)&v;
            #pragma unroll
            for (int d = 0; d < 4; d++)
                sVt[(c4 * 4 + d) * 104 + row] = hp[d];
        }
    }
    asm volatile("cp.async.wait_group 0;");
    __syncthreads();

    const int wid = tid >> 5;
    const int lane = tid & 31;
    const int wm = wid >> 1;      // 0..3 (query rows wm*16..)
    const int wn = wid & 1;       // 0..1 (key cols wn*48..)

    // ---- phase 1: S = Q @ K^T ----
    const int rA = wm * 16 + (lane & 7) + (((lane >> 3) & 1) << 3);
    const int aOff = rA * 128, aXor = rA & 7, aG = lane >> 4;
    int rBOff[3], bXor[3];
    #pragma unroll
    for (int pi = 0; pi < 3; pi++) {
        const int r = wn * 48 + (2 * pi + (lane >> 4)) * 8 + (lane & 7);
        rBOff[pi] = r * 128;
        bXor[pi] = r & 7;
    }
    const int bG = (lane >> 3) & 1;

    float sacc[6][4];
    #pragma unroll
    for (int i = 0; i < 6; i++)
        #pragma unroll
        for (int j = 0; j < 4; j++) sacc[i][j] = 0.0f;

    #pragma unroll
    for (int ks = 0; ks < 4; ks++) {
        uint32_t af[4];
        ldsm_x4(af, sb + A_SQ + aOff + (((ks * 2 + aG) ^ aXor) << 4));
        #pragma unroll
        for (int pi = 0; pi < 3; pi++) {
            uint32_t t[4];
            ldsm_x4(t, sb + A_SK + rBOff[pi] + (((ks * 2 + bG) ^ bXor[pi]) << 4));
            mma16816(sacc[2 * pi], af, t);
            mma16816(sacc[2 * pi + 1], af, t + 2);
        }
    }

    // ---- mask + exp + rowsum + pack to A-fragments ----
    const int rowl0 = wm * 16 + (lane >> 2);
    const int colb = wn * 48 + (lane & 3) * 2;
    float rs0 = 0.0f, rs1 = 0.0f;
    #pragma unroll
    for (int nf = 0; nf < 6; nf++) {
        #pragma unroll
        for (int reg = 0; reg < 4; reg++) {
            const int col = colb + nf * 8 + (reg & 1);
            const int row = rowl0 + (reg >> 1) * 8;
            const int j = kstart + col;
            const int d = col - row - Wc;     // = j - q
            const bool valid = (j >= 0) && (j < Sc) && (d >= -Wc) && (d <= Wc);
            const float w = valid ? __expf(sacc[nf][reg]) : 0.0f;
            sacc[nf][reg] = w;
            if (reg >> 1) rs1 += w; else rs0 += w;
        }
    }
    rs0 += __shfl_xor_sync(0xffffffffu, rs0, 1);
    rs0 += __shfl_xor_sync(0xffffffffu, rs0, 2);
    rs1 += __shfl_xor_sync(0xffffffffu, rs1, 1);
    rs1 += __shfl_xor_sync(0xffffffffu, rs1, 2);
    float* sL = (float*)(dynsm + A_SL);
    if ((lane & 3) == 0) {
        sL[wn * 64 + rowl0] = rs0;
        sL[wn * 64 + rowl0 + 8] = rs1;
    }

    uint32_t pA[3][4];
    #pragma unroll
    for (int kc = 0; kc < 3; kc++) {
        pA[kc][0] = pack_h2(sacc[2 * kc][0],     sacc[2 * kc][1]);
        pA[kc][1] = pack_h2(sacc[2 * kc][2],     sacc[2 * kc][3]);
        pA[kc][2] = pack_h2(sacc[2 * kc + 1][0], sacc[2 * kc + 1][1]);
        pA[kc][3] = pack_h2(sacc[2 * kc + 1][2], sacc[2 * kc + 1][3]);
    }

    // ---- phase 2: ctx_partial = P(16x48) @ V[wn*48..][64] ----
    float cacc[8][4];
    #pragma unroll
    for (int i = 0; i < 8; i++)
        #pragma unroll
        for (int j = 0; j < 4; j++) cacc[i][j] = 0.0f;

    int rVOff[4];
    #pragma unroll
    for (int pi = 0; pi < 4; pi++)
        rVOff[pi] = ((2 * pi + (lane >> 4)) * 8 + (lane & 7)) * 208;
    const int gV = (lane >> 3) & 1;

    #pragma unroll
    for (int kc = 0; kc < 3; kc++) {
        const int kg = wn * 6 + kc * 2 + gV;   // key 16B-granule along V^T row
        #pragma unroll
        for (int pi = 0; pi < 4; pi++) {
            uint32_t t[4];
            ldsm_x4(t, sb + A_SV + rVOff[pi] + kg * 16);
            mma16816(cacc[2 * pi], pA[kc], t);
            mma16816(cacc[2 * pi + 1], pA[kc], t + 2);
        }
    }

    // ---- combine wn halves in smem ----
    float* sC = (float*)(dynsm + A_SC);
    const int r0 = wm * 16 + (lane >> 2);
    const int cc0 = (lane & 3) * 2;
    if (wn == 0) {
        #pragma unroll
        for (int nf = 0; nf < 8; nf++) {
            const int c = nf * 8 + cc0;
            *(float2*)&sC[r0 * 64 + c] = make_float2(cacc[nf][0], cacc[nf][1]);
            *(float2*)&sC[(r0 + 8) * 64 + c] = make_float2(cacc[nf][2], cacc[nf][3]);
        }
    }
    __syncthreads();
    if (wn == 1) {
        #pragma unroll
        for (int nf = 0; nf < 8; nf++) {
            const int c = nf * 8 + cc0;
            float2 p0 = *(float2*)&sC[r0 * 64 + c];
            float2 p1 = *(float2*)&sC[(r0 + 8) * 64 + c];
            p0.x += cacc[nf][0]; p0.y += cacc[nf][1];
            p1.x += cacc[nf][2]; p1.y += cacc[nf][3];
            *(float2*)&sC[r0 * 64 + c] = p0;
            *(float2*)&sC[(r0 + 8) * 64 + c] = p1;
        }
    }
    __syncthreads();

    // ---- final: scale by 1/l, split hi/lo fp16, store ----
    const int row = tid >> 2;
    const int c0 = (tid & 3) * 16;
    const float inv = 1.0f / (sL[row] + sL[64 + row]);
    const int b = bh >> 3;
    const int h = bh & 7;
    const size_t obase = ((size_t)(b * Sc + q0 + row)) * Dc + h * 64 + c0;
    #pragma unroll
    for (int i = 0; i < 4; i++) {
        float4 v = *(float4*)&sC[row * 64 + c0 + i * 4];
        v.x *= inv; v.y *= inv; v.z *= inv; v.w *= inv;
        __align__(8) __half hi[4], lo[4];
        float a[4] = {v.x, v.y, v.z, v.w};
        #pragma unroll
        for (int d = 0; d < 4; d++) {
            hi[d] = __float2half_rn(a[d]);
            lo[d] = __float2half_rn(a[d] - __half2float(hi[d]));
        }
        *(uint2*)(g_ch + obase + i * 4) = *(uint2*)hi;
        *(uint2*)(g_cl + obase + i * 4) = *(uint2*)lo;
    }
}

// ---------------------------------------------------------------------------
// Launch
// ---------------------------------------------------------------------------
extern "C" void kernel_launch(void* const* d_in, const int* in_sizes, int n_in,
                              void* d_out, int out_size)
{
    const float* query = (const float*)d_in[0];
    const float* key   = (const float*)d_in[1];
    const float* value = (const float*)d_in[2];
    const float* Wq    = (const float*)d_in[3];
    const float* bq    = (const float*)d_in[4];
    const float* Wk    = (const float*)d_in[5];
    const float* bk    = (const float*)d_in[6];
    const float* Wv    = (const float*)d_in[7];
    const float* bv    = (const float*)d_in[8];
    const float* Wo    = (const float*)d_in[9];
    const float* bo    = (const float*)d_in[10];
    float* out = (float*)d_out;

    static bool attr_done = false;
    if (!attr_done) {
        cudaFuncSetAttribute(qkv_gemm_tc,
            cudaFuncAttributeMaxDynamicSharedMemorySize, GEMM_SMEM);
        cudaFuncSetAttribute(out_gemm_tc,
            cudaFuncAttributeMaxDynamicSharedMemorySize, GEMM_SMEM);
        cudaFuncSetAttribute(attn_kernel,
            cudaFuncAttributeMaxDynamicSharedMemorySize, ATTN_SMEM);
        attr_done = true;
    }

    // 1. fp32 -> fp16 hi/lo splits (weights: hi only, transposed)
    split_inputs_kernel<<<dim3(NELEM / 4 / 256, 3), 256>>>(query, key, value);
    split_weights_kernel<<<dim3(16, 16, 4), 1024>>>(Wq, Wk, Wv, Wo);

    // 2. QKV projections -> fp16 [bh][s][dk] (Q prescaled by 0.125)
    qkv_gemm_tc<<<dim3(4, 64, 3), 256, GEMM_SMEM>>>(bq, bk, bv);

    // 3. banded attention (HMMA)
    attn_kernel<<<dim3(Sc / TQ, Bc * Hc), 256, ATTN_SMEM>>>();

    // 4. output projection
    out_gemm_tc<<<dim3(4, 64), 256, GEMM_SMEM>>>(bo, out);
}

// round 9
// speedup vs baseline: 2.4889x; 1.1216x over previous
#include <cuda_runtime.h>
#include <cuda_bf16.h>
#include <cuda_fp16.h>
#include <cstdint>
#include <math.h>

// ---------------------------------------------------------------------------
// Problem constants
// ---------------------------------------------------------------------------
#define Bc  4
#define Sc  2048
#define Dc  512
#define Hc  8
#define Wc  16
#define DKc 64
#define Mtot (Bc * Sc)          // 8192
#define NELEM (Mtot * Dc)       // 4194304

// ---------------------------------------------------------------------------
// Device scratch
// ---------------------------------------------------------------------------
__device__ __half g_ah[3][NELEM];      // fp16 hi split of query/key/value
__device__ __half g_al[3][NELEM];      // fp16 lo split
__device__ __half g_wth[4][Dc * Dc];   // W^T hi (fp16): [n][k]
__device__ __half g_qs[NELEM];         // projected Q fp16, [bh][s][64], prescaled 0.125
__device__ __half g_ks[NELEM];         // projected K fp16, [bh][s][64]
__device__ __half g_vs[NELEM];         // projected V fp16, [bh][s][64]
__device__ __half g_ch[NELEM];         // ctx fp16 [m, 512]

__device__ __forceinline__ uint32_t smem_to_u32(const void* p) {
    uint32_t a;
    asm("{ .reg .u64 t; cvta.to.shared.u64 t, %1; cvt.u32.u64 %0, t; }"
        : "=r"(a) : "l"(p));
    return a;
}

__device__ __forceinline__ void cp_async16(uint32_t sp, const void* gp) {
    asm volatile("cp.async.cg.shared.global [%0], [%1], 16;" :: "r"(sp), "l"(gp));
}
__device__ __forceinline__ void cp_commit() {
    asm volatile("cp.async.commit_group;");
}
__device__ __forceinline__ void ldsm_x4(uint32_t* r, uint32_t addr) {
    asm volatile("ldmatrix.sync.aligned.m8n8.x4.shared.b16 {%0,%1,%2,%3}, [%4];"
                 : "=r"(r[0]), "=r"(r[1]), "=r"(r[2]), "=r"(r[3]) : "r"(addr));
}
__device__ __forceinline__ void ldsm_x4_trans(uint32_t* r, uint32_t addr) {
    asm volatile("ldmatrix.sync.aligned.m8n8.x4.trans.shared.b16 {%0,%1,%2,%3}, [%4];"
                 : "=r"(r[0]), "=r"(r[1]), "=r"(r[2]), "=r"(r[3]) : "r"(addr));
}
__device__ __forceinline__ void mma16816(
    float* d, const uint32_t* a, const uint32_t* b)
{
    asm volatile(
        "mma.sync.aligned.m16n8k16.row.col.f32.f16.f16.f32 "
        "{%0,%1,%2,%3}, {%4,%5,%6,%7}, {%8,%9}, {%0,%1,%2,%3};"
        : "+f"(d[0]), "+f"(d[1]), "+f"(d[2]), "+f"(d[3])
        : "r"(a[0]), "r"(a[1]), "r"(a[2]), "r"(a[3]), "r"(b[0]), "r"(b[1]));
}
__device__ __forceinline__ uint32_t pack_h2(float a, float b) {
    __half2 h = __floats2half2_rn(a, b);
    return *(uint32_t*)&h;
}

// ---------------------------------------------------------------------------
// fp16 GEMM via mma.sync: C = (Ah [+ Al]) @ Wh^T + bias.
// CTA tile 128x128, 256 thr (8 warps 2x4), warp tile 64x32, K-chunk 32,
// 3-stage cp.async pipeline. TWOA: 1 = two A passes vs one shared Wh tile.
// MODE 0: f32 output (+bias, scale). MODE 1: fp16 scatter to [bh][s][64].
// ---------------------------------------------------------------------------
#define KCHUNK 32
#define NCHUNK 16                     // 512 / 32
#define TILE_B (128 * KCHUNK * 2)     // 8192 bytes per tile
#define QKV_SMEM  (3 * 3 * TILE_B)    // 73728 (Ah, Al, Wh per stage)
#define OUT_SMEM  (3 * 2 * TILE_B)    // 49152 (A, Wh per stage)

__device__ __forceinline__ void load_tile(
    uint32_t sbase, const __half* __restrict__ src, int rowBase, int kk)
{
    #pragma unroll
    for (int i = 0; i < 2; i++) {
        const int g = threadIdx.x + i * 256;   // 0..511
        const int row = g >> 2;
        const int cg = g & 3;
        const int cgs = cg ^ (row & 3);
        cp_async16(sbase + row * 64 + cgs * 16,
                   src + (size_t)(rowBase + row) * Dc + kk + cg * 8);
    }
}

template <int MODE, int TWOA>
__device__ void gemm_core(
    const __half* __restrict__ Ah, const __half* __restrict__ Al,
    const __half* __restrict__ Wh, const float* __restrict__ bias,
    float* __restrict__ dstF, __half* __restrict__ dstH,
    int rowBase, int colBase, float oscale)
{
    extern __shared__ char dynsm[];
    const int STAGE = (2 + TWOA) * TILE_B;
    const int WOFF = (1 + TWOA) * TILE_B;

    const int tid = threadIdx.x;
    const int wid = tid >> 5;
    const int lane = tid & 31;
    const int wm = wid >> 2;       // 0..1
    const int wn = wid & 3;        // 0..3

    const uint32_t sb = smem_to_u32(dynsm);
    uint32_t stg[3];
    #pragma unroll
    for (int s = 0; s < 3; s++) stg[s] = sb + s * STAGE;

    float acc[4][4][4];
    #pragma unroll
    for (int i = 0; i < 4; i++)
        #pragma unroll
        for (int j = 0; j < 4; j++)
            #pragma unroll
            for (int k = 0; k < 4; k++)
                acc[i][j][k] = 0.0f;

    int aRow[4], aR3[4];
    #pragma unroll
    for (int mi = 0; mi < 4; mi++) {
        const int r = wm * 64 + mi * 16 + (lane & 7) + (((lane >> 3) & 1) << 3);
        aRow[mi] = r * 64;
        aR3[mi] = r & 3;
    }
    const int aHi = lane >> 4;
    int bRowP[2], bR3P[2];
    #pragma unroll
    for (int pi = 0; pi < 2; pi++) {
        const int r = wn * 32 + (2 * pi + (lane >> 4)) * 8 + (lane & 7);
        bRowP[pi] = r * 64;
        bR3P[pi] = r & 3;
    }
    const int bG = (lane >> 3) & 1;

    #pragma unroll
    for (int c = 0; c < 2; c++) {
        load_tile(stg[c], Ah, rowBase, c * KCHUNK);
        if (TWOA) load_tile(stg[c] + TILE_B, Al, rowBase, c * KCHUNK);
        load_tile(stg[c] + WOFF, Wh, colBase, c * KCHUNK);
        cp_commit();
    }

    for (int c = 0; c < NCHUNK; c++) {
        if (c < NCHUNK - 2) asm volatile("cp.async.wait_group 1;");
        else                asm volatile("cp.async.wait_group 0;");
        __syncthreads();

        if (c + 2 < NCHUNK) {
            const int cc = c + 2;
            const int kk = cc * KCHUNK;
            const int st = cc - (cc / 3) * 3;
            load_tile(stg[st], Ah, rowBase, kk);
            if (TWOA) load_tile(stg[st] + TILE_B, Al, rowBase, kk);
            load_tile(stg[st] + WOFF, Wh, colBase, kk);
            cp_commit();
        }

        const int cs = c - (c / 3) * 3;
        const uint32_t cBase = stg[cs];
        const uint32_t cB = cBase + WOFF;

        uint32_t bf[2][4][2];
        #pragma unroll
        for (int ks = 0; ks < 2; ks++) {
            #pragma unroll
            for (int pi = 0; pi < 2; pi++) {
                const int cg = (ks * 2 + bG) ^ bR3P[pi];
                uint32_t t[4];
                ldsm_x4(t, cB + bRowP[pi] + cg * 16);
                bf[ks][2 * pi][0] = t[0]; bf[ks][2 * pi][1] = t[1];
                bf[ks][2 * pi + 1][0] = t[2]; bf[ks][2 * pi + 1][1] = t[3];
            }
        }

        #pragma unroll
        for (int seg = 0; seg < 1 + TWOA; seg++) {
            const uint32_t cA = cBase + seg * TILE_B;
            #pragma unroll
            for (int ks = 0; ks < 2; ks++) {
                uint32_t af[4][4];
                #pragma unroll
                for (int mi = 0; mi < 4; mi++) {
                    const int cg = (ks * 2 + aHi) ^ aR3[mi];
                    ldsm_x4(af[mi], cA + aRow[mi] + cg * 16);
                }
                #pragma unroll
                for (int mi = 0; mi < 4; mi++)
                    #pragma unroll
                    for (int ni = 0; ni < 4; ni++)
                        mma16816(acc[mi][ni], af[mi], bf[ks][ni]);
            }
        }
    }

    // epilogue
    const int lr = lane >> 2;
    const int lc = (lane & 3) * 2;
    #pragma unroll
    for (int ni = 0; ni < 4; ni++) {
        const int col = colBase + wn * 32 + ni * 8 + lc;
        const float2 bb = *(const float2*)&bias[col];
        #pragma unroll
        for (int mi = 0; mi < 4; mi++) {
            const int row = rowBase + wm * 64 + mi * 16 + lr;
            float2 v0 = { (acc[mi][ni][0] + bb.x) * oscale,
                          (acc[mi][ni][1] + bb.y) * oscale };
            float2 v1 = { (acc[mi][ni][2] + bb.x) * oscale,
                          (acc[mi][ni][3] + bb.y) * oscale };
            if (MODE == 0) {
                *(float2*)&dstF[(size_t)row * Dc + col] = v0;
                *(float2*)&dstF[(size_t)(row + 8) * Dc + col] = v1;
            } else {
                const int h = col >> 6;
                const int dk = col & 63;
                const int b = row >> 11;
                const int s = row & (Sc - 1);
                const size_t a0 = (((size_t)(b * Hc + h) * Sc + s)) * 64 + dk;
                const size_t a1 = a0 + 8 * 64;
                *(uint32_t*)&dstH[a0] = pack_h2(v0.x, v0.y);
                *(uint32_t*)&dstH[a1] = pack_h2(v1.x, v1.y);
            }
        }
    }
}

__global__ __launch_bounds__(256, 2) void qkv_gemm_tc(
    const float* __restrict__ bq, const float* __restrict__ bk,
    const float* __restrict__ bv)
{
    const int z = blockIdx.z;
    const float* bias = (z == 0) ? bq : (z == 1) ? bk : bv;
    __half* dst = (z == 0) ? g_qs : (z == 1) ? g_ks : g_vs;
    const float sc = (z == 0) ? 0.125f : 1.0f;   // fold 1/sqrt(DK) into Q
    gemm_core<1, 1>(g_ah[z], g_al[z], g_wth[z], bias, nullptr, dst,
                    blockIdx.y * 128, blockIdx.x * 128, sc);
}

__global__ __launch_bounds__(256, 2) void out_gemm_tc(
    const float* __restrict__ bo, float* __restrict__ out)
{
    gemm_core<0, 0>(g_ch, nullptr, g_wth[3], bo, out, nullptr,
                    blockIdx.y * 128, blockIdx.x * 128, 1.0f);
}

// ---------------------------------------------------------------------------
// fp32 -> fp16 hi/lo splits
// ---------------------------------------------------------------------------
__global__ __launch_bounds__(256) void split_inputs_kernel(
    const float* __restrict__ q, const float* __restrict__ k,
    const float* __restrict__ v)
{
    const int z = blockIdx.y;
    const float* src = (z == 0) ? q : (z == 1) ? k : v;
    const size_t i4 = (size_t)blockIdx.x * 256 + threadIdx.x;
    float4 f = ((const float4*)src)[i4];
    float a[4] = {f.x, f.y, f.z, f.w};
    __align__(8) __half h[4], lo[4];
    #pragma unroll
    for (int i = 0; i < 4; i++) {
        h[i] = __float2half_rn(a[i]);
        lo[i] = __float2half_rn(a[i] - __half2float(h[i]));
    }
    *(uint2*)&g_ah[z][i4 * 4] = *(uint2*)h;
    *(uint2*)&g_al[z][i4 * 4] = *(uint2*)lo;
}

__global__ __launch_bounds__(1024) void split_weights_kernel(
    const float* __restrict__ Wq, const float* __restrict__ Wk,
    const float* __restrict__ Wv, const float* __restrict__ Wo)
{
    const int z = blockIdx.z;
    const float* w = (z == 0) ? Wq : (z == 1) ? Wk : (z == 2) ? Wv : Wo;
    __shared__ float s[32][33];
    const int tx = threadIdx.x & 31;
    const int ty = threadIdx.x >> 5;
    const int rb = blockIdx.y * 32;   // k block
    const int cb = blockIdx.x * 32;   // n block
    s[ty][tx] = w[(size_t)(rb + ty) * Dc + cb + tx];
    __syncthreads();
    const float a = s[tx][ty];        // = w[rb+tx][cb+ty]
    g_wth[z][(size_t)(cb + ty) * Dc + rb + tx] = __float2half_rn(a);
}

// ---------------------------------------------------------------------------
// Banded local attention via HMMA.
// S = Q(64x64) @ K^T(96x64); band mask + exp; ctx = P(64x96) @ V(96x64).
// 8 warps as 4(m) x 2(n). V loaded like K (swizzled [key][dk]); P@V B-operand
// fragments come from ldmatrix.x4.trans. ctx written as single fp16.
// ---------------------------------------------------------------------------
#define TQ 64
#define HALO 96
// dynamic smem layout (bytes):
#define A_SQ 0                       // Q: 64 rows x 128B, swizzle ^(r&7)
#define A_SK 8192                    // K: 96 rows x 128B, swizzle ^(r&7)
#define A_SV 20480                   // V: 96 rows x 128B, swizzle ^(r&7)
#define A_SC 32768                   // combine: 64x64 f32
#define A_SL 49152                   // rowsums: float[2][64]
#define ATTN_SMEM 49664

__global__ __launch_bounds__(256) void attn_kernel()
{
    extern __shared__ char dynsm[];
    const uint32_t sb = smem_to_u32(dynsm);
    const int tid = threadIdx.x;
    const int bh = blockIdx.y;
    const int q0 = blockIdx.x * TQ;
    const int kstart = q0 - Wc;
    const size_t base = (size_t)bh * Sc * 64;

    // 1) zero K + V regions (covers out-of-range halo rows)
    for (int i = tid; i < 1536; i += 256)
        *(uint4*)(dynsm + A_SK + i * 16) = make_uint4(0, 0, 0, 0);
    __syncthreads();

    // 2) async-load Q, K, V tiles
    for (int i = tid; i < 512; i += 256) {
        const int row = i >> 3, cg = i & 7;
        cp_async16(sb + A_SQ + row * 128 + ((cg ^ (row & 7)) * 16),
                   g_qs + base + (size_t)(q0 + row) * 64 + cg * 8);
    }
    for (int i = tid; i < 768; i += 256) {
        const int row = i >> 3, cg = i & 7;
        const int j = kstart + row;
        if (j >= 0 && j < Sc)
            cp_async16(sb + A_SK + row * 128 + ((cg ^ (row & 7)) * 16),
                       g_ks + base + (size_t)j * 64 + cg * 8);
    }
    for (int i = tid; i < 768; i += 256) {
        const int row = i >> 3, cg = i & 7;
        const int j = kstart + row;
        if (j >= 0 && j < Sc)
            cp_async16(sb + A_SV + row * 128 + ((cg ^ (row & 7)) * 16),
                       g_vs + base + (size_t)j * 64 + cg * 8);
    }
    cp_commit();
    asm volatile("cp.async.wait_group 0;");
    __syncthreads();

    const int wid = tid >> 5;
    const int lane = tid & 31;
    const int wm = wid >> 1;      // 0..3 (query rows wm*16..)
    const int wn = wid & 1;       // 0..1 (key cols wn*48..)

    // ---- phase 1: S = Q @ K^T ----
    const int rA = wm * 16 + (lane & 7) + (((lane >> 3) & 1) << 3);
    const int aOff = rA * 128, aXor = rA & 7, aG = lane >> 4;
    int rBOff[3], bXor[3];
    #pragma unroll
    for (int pi = 0; pi < 3; pi++) {
        const int r = wn * 48 + (2 * pi + (lane >> 4)) * 8 + (lane & 7);
        rBOff[pi] = r * 128;
        bXor[pi] = r & 7;
    }
    const int bG = (lane >> 3) & 1;

    float sacc[6][4];
    #pragma unroll
    for (int i = 0; i < 6; i++)
        #pragma unroll
        for (int j = 0; j < 4; j++) sacc[i][j] = 0.0f;

    #pragma unroll
    for (int ks = 0; ks < 4; ks++) {
        uint32_t af[4];
        ldsm_x4(af, sb + A_SQ + aOff + (((ks * 2 + aG) ^ aXor) << 4));
        #pragma unroll
        for (int pi = 0; pi < 3; pi++) {
            uint32_t t[4];
            ldsm_x4(t, sb + A_SK + rBOff[pi] + (((ks * 2 + bG) ^ bXor[pi]) << 4));
            mma16816(sacc[2 * pi], af, t);
            mma16816(sacc[2 * pi + 1], af, t + 2);
        }
    }

    // ---- mask + exp + rowsum + pack to A-fragments ----
    const int rowl0 = wm * 16 + (lane >> 2);
    const int colb = wn * 48 + (lane & 3) * 2;
    float rs0 = 0.0f, rs1 = 0.0f;
    #pragma unroll
    for (int nf = 0; nf < 6; nf++) {
        #pragma unroll
        for (int reg = 0; reg < 4; reg++) {
            const int col = colb + nf * 8 + (reg & 1);
            const int row = rowl0 + (reg >> 1) * 8;
            const int j = kstart + col;
            const int d = col - row - Wc;     // = j - q
            const bool valid = (j >= 0) && (j < Sc) && (d >= -Wc) && (d <= Wc);
            const float w = valid ? __expf(sacc[nf][reg]) : 0.0f;
            sacc[nf][reg] = w;
            if (reg >> 1) rs1 += w; else rs0 += w;
        }
    }
    rs0 += __shfl_xor_sync(0xffffffffu, rs0, 1);
    rs0 += __shfl_xor_sync(0xffffffffu, rs0, 2);
    rs1 += __shfl_xor_sync(0xffffffffu, rs1, 1);
    rs1 += __shfl_xor_sync(0xffffffffu, rs1, 2);
    float* sL = (float*)(dynsm + A_SL);
    if ((lane & 3) == 0) {
        sL[wn * 64 + rowl0] = rs0;
        sL[wn * 64 + rowl0 + 8] = rs1;
    }

    uint32_t pA[3][4];
    #pragma unroll
    for (int kc = 0; kc < 3; kc++) {
        pA[kc][0] = pack_h2(sacc[2 * kc][0],     sacc[2 * kc][1]);
        pA[kc][1] = pack_h2(sacc[2 * kc][2],     sacc[2 * kc][3]);
        pA[kc][2] = pack_h2(sacc[2 * kc + 1][0], sacc[2 * kc + 1][1]);
        pA[kc][3] = pack_h2(sacc[2 * kc + 1][2], sacc[2 * kc + 1][3]);
    }

    // ---- phase 2: ctx_partial = P(16x48) @ V[wn*48..][64] via ldsm.trans ----
    float cacc[8][4];
    #pragma unroll
    for (int i = 0; i < 8; i++)
        #pragma unroll
        for (int j = 0; j < 4; j++) cacc[i][j] = 0.0f;

    // lane address components for trans B-fragments:
    // key = kbase + ((lane>>3)&1)*8 + (lane&7); granule = 2*pi + (lane>>4)
    const int vKeyLocal = (((lane >> 3) & 1) << 3) + (lane & 7);
    const int vGHalf = lane >> 4;

    #pragma unroll
    for (int kc = 0; kc < 3; kc++) {
        const int key = wn * 48 + kc * 16 + vKeyLocal;
        const uint32_t rowAddr = sb + A_SV + key * 128;
        const int kx = key & 7;
        #pragma unroll
        for (int pi = 0; pi < 4; pi++) {
            const int gi = 2 * pi + vGHalf;
            uint32_t t[4];
            ldsm_x4_trans(t, rowAddr + ((gi ^ kx) << 4));
            mma16816(cacc[2 * pi], pA[kc], t);
            mma16816(cacc[2 * pi + 1], pA[kc], t + 2);
        }
    }

    // ---- combine wn halves in smem ----
    float* sC = (float*)(dynsm + A_SC);
    const int r0 = wm * 16 + (lane >> 2);
    const int cc0 = (lane & 3) * 2;
    if (wn == 0) {
        #pragma unroll
        for (int nf = 0; nf < 8; nf++) {
            const int c = nf * 8 + cc0;
            *(float2*)&sC[r0 * 64 + c] = make_float2(cacc[nf][0], cacc[nf][1]);
            *(float2*)&sC[(r0 + 8) * 64 + c] = make_float2(cacc[nf][2], cacc[nf][3]);
        }
    }
    __syncthreads();
    if (wn == 1) {
        #pragma unroll
        for (int nf = 0; nf < 8; nf++) {
            const int c = nf * 8 + cc0;
            float2 p0 = *(float2*)&sC[r0 * 64 + c];
            float2 p1 = *(float2*)&sC[(r0 + 8) * 64 + c];
            p0.x += cacc[nf][0]; p0.y += cacc[nf][1];
            p1.x += cacc[nf][2]; p1.y += cacc[nf][3];
            *(float2*)&sC[r0 * 64 + c] = p0;
            *(float2*)&sC[(r0 + 8) * 64 + c] = p1;
        }
    }
    __syncthreads();

    // ---- final: scale by 1/l, fp16, store ----
    const int row = tid >> 2;
    const int c0 = (tid & 3) * 16;
    const float inv = 1.0f / (sL[row] + sL[64 + row]);
    const int b = bh >> 3;
    const int h = bh & 7;
    const size_t obase = ((size_t)(b * Sc + q0 + row)) * Dc + h * 64 + c0;
    #pragma unroll
    for (int i = 0; i < 4; i++) {
        float4 v = *(float4*)&sC[row * 64 + c0 + i * 4];
        __align__(8) __half hi[4];
        hi[0] = __float2half_rn(v.x * inv);
        hi[1] = __float2half_rn(v.y * inv);
        hi[2] = __float2half_rn(v.z * inv);
        hi[3] = __float2half_rn(v.w * inv);
        *(uint2*)(g_ch + obase + i * 4) = *(uint2*)hi;
    }
}

// ---------------------------------------------------------------------------
// Launch
// ---------------------------------------------------------------------------
extern "C" void kernel_launch(void* const* d_in, const int* in_sizes, int n_in,
                              void* d_out, int out_size)
{
    const float* query = (const float*)d_in[0];
    const float* key   = (const float*)d_in[1];
    const float* value = (const float*)d_in[2];
    const float* Wq    = (const float*)d_in[3];
    const float* bq    = (const float*)d_in[4];
    const float* Wk    = (const float*)d_in[5];
    const float* bk    = (const float*)d_in[6];
    const float* Wv    = (const float*)d_in[7];
    const float* bv    = (const float*)d_in[8];
    const float* Wo    = (const float*)d_in[9];
    const float* bo    = (const float*)d_in[10];
    float* out = (float*)d_out;

    static bool attr_done = false;
    if (!attr_done) {
        cudaFuncSetAttribute(qkv_gemm_tc,
            cudaFuncAttributeMaxDynamicSharedMemorySize, QKV_SMEM);
        cudaFuncSetAttribute(out_gemm_tc,
            cudaFuncAttributeMaxDynamicSharedMemorySize, OUT_SMEM);
        cudaFuncSetAttribute(attn_kernel,
            cudaFuncAttributeMaxDynamicSharedMemorySize, ATTN_SMEM);
        attr_done = true;
    }

    // 1. fp32 -> fp16 hi/lo splits (weights: hi only, transposed)
    split_inputs_kernel<<<dim3(NELEM / 4 / 256, 3), 256>>>(query, key, value);
    split_weights_kernel<<<dim3(16, 16, 4), 1024>>>(Wq, Wk, Wv, Wo);

    // 2. QKV projections -> fp16 [bh][s][dk] (Q prescaled by 0.125)
    qkv_gemm_tc<<<dim3(4, 64, 3), 256, QKV_SMEM>>>(bq, bk, bv);

    // 3. banded attention (HMMA, ldsm.trans V)
    attn_kernel<<<dim3(Sc / TQ, Bc * Hc), 256, ATTN_SMEM>>>();

    // 4. output projection (single-term fp16 A)
    out_gemm_tc<<<dim3(4, 64), 256, OUT_SMEM>>>(bo, out);
}

// round 10
// speedup vs baseline: 2.6512x; 1.0652x over previous
#include <cuda_runtime.h>
#include <cuda_bf16.h>
#include <cuda_fp16.h>
#include <cstdint>
#include <math.h>

// ---------------------------------------------------------------------------
// Problem constants
// ---------------------------------------------------------------------------
#define Bc  4
#define Sc  2048
#define Dc  512
#define Hc  8
#define Wc  16
#define DKc 64
#define Mtot (Bc * Sc)          // 8192
#define NELEM (Mtot * Dc)       // 4194304

// ---------------------------------------------------------------------------
// Device scratch
// ---------------------------------------------------------------------------
__device__ __half g_ah[3][NELEM];      // fp16 hi split of query/key/value
__device__ __half g_al[3][NELEM];      // fp16 lo split
__device__ __half g_wth[4][Dc * Dc];   // W^T hi (fp16): [n][k]
__device__ __half g_qs[NELEM];         // projected Q fp16, [bh][s][64], prescaled 0.125
__device__ __half g_ks[NELEM];         // projected K fp16, [bh][s][64]
__device__ __half g_vs[NELEM];         // projected V fp16, [bh][s][64]
__device__ __half g_ch[NELEM];         // ctx fp16 [m, 512]

__device__ __forceinline__ uint32_t smem_to_u32(const void* p) {
    uint32_t a;
    asm("{ .reg .u64 t; cvta.to.shared.u64 t, %1; cvt.u32.u64 %0, t; }"
        : "=r"(a) : "l"(p));
    return a;
}

__device__ __forceinline__ void cp_async16(uint32_t sp, const void* gp) {
    asm volatile("cp.async.cg.shared.global [%0], [%1], 16;" :: "r"(sp), "l"(gp));
}
__device__ __forceinline__ void cp_commit() {
    asm volatile("cp.async.commit_group;");
}
__device__ __forceinline__ void ldsm_x4(uint32_t* r, uint32_t addr) {
    asm volatile("ldmatrix.sync.aligned.m8n8.x4.shared.b16 {%0,%1,%2,%3}, [%4];"
                 : "=r"(r[0]), "=r"(r[1]), "=r"(r[2]), "=r"(r[3]) : "r"(addr));
}
__device__ __forceinline__ void ldsm_x4_trans(uint32_t* r, uint32_t addr) {
    asm volatile("ldmatrix.sync.aligned.m8n8.x4.trans.shared.b16 {%0,%1,%2,%3}, [%4];"
                 : "=r"(r[0]), "=r"(r[1]), "=r"(r[2]), "=r"(r[3]) : "r"(addr));
}
__device__ __forceinline__ void mma16816(
    float* d, const uint32_t* a, const uint32_t* b)
{
    asm volatile(
        "mma.sync.aligned.m16n8k16.row.col.f32.f16.f16.f32 "
        "{%0,%1,%2,%3}, {%4,%5,%6,%7}, {%8,%9}, {%0,%1,%2,%3};"
        : "+f"(d[0]), "+f"(d[1]), "+f"(d[2]), "+f"(d[3])
        : "r"(a[0]), "r"(a[1]), "r"(a[2]), "r"(a[3]), "r"(b[0]), "r"(b[1]));
}
__device__ __forceinline__ uint32_t pack_h2(float a, float b) {
    __half2 h = __floats2half2_rn(a, b);
    return *(uint32_t*)&h;
}

// ---------------------------------------------------------------------------
// fp16 GEMM via mma.sync: C = (Ah [+ Al]) @ Wh^T + bias.
// CTA tile 128x128, 256 thr (8 warps 2x4), warp tile 64x32, K-chunk 32,
// 3-stage cp.async pipeline. TWOA: 1 = two A passes vs one shared Wh tile.
// MODE 0: f32 output (+bias, scale). MODE 1: fp16 scatter to [bh][s][64].
// ---------------------------------------------------------------------------
#define KCHUNK 32
#define NCHUNK 16                     // 512 / 32
#define TILE_B (128 * KCHUNK * 2)     // 8192 bytes per tile
#define QKV_SMEM  (3 * 3 * TILE_B)    // 73728 (Ah, Al, Wh per stage)
#define OUT_SMEM  (3 * 2 * TILE_B)    // 49152 (A, Wh per stage)

__device__ __forceinline__ void load_tile(
    uint32_t sbase, const __half* __restrict__ src, int rowBase, int kk)
{
    #pragma unroll
    for (int i = 0; i < 2; i++) {
        const int g = threadIdx.x + i * 256;   // 0..511
        const int row = g >> 2;
        const int cg = g & 3;
        const int cgs = cg ^ (row & 3);
        cp_async16(sbase + row * 64 + cgs * 16,
                   src + (size_t)(rowBase + row) * Dc + kk + cg * 8);
    }
}

template <int MODE, int TWOA>
__device__ void gemm_core(
    const __half* __restrict__ Ah, const __half* __restrict__ Al,
    const __half* __restrict__ Wh, const float* __restrict__ bias,
    float* __restrict__ dstF, __half* __restrict__ dstH,
    int rowBase, int colBase, float oscale)
{
    extern __shared__ char dynsm[];
    const int STAGE = (2 + TWOA) * TILE_B;
    const int WOFF = (1 + TWOA) * TILE_B;

    const int tid = threadIdx.x;
    const int wid = tid >> 5;
    const int lane = tid & 31;
    const int wm = wid >> 2;       // 0..1
    const int wn = wid & 3;        // 0..3

    const uint32_t sb = smem_to_u32(dynsm);
    uint32_t stg[3];
    #pragma unroll
    for (int s = 0; s < 3; s++) stg[s] = sb + s * STAGE;

    float acc[4][4][4];
    #pragma unroll
    for (int i = 0; i < 4; i++)
        #pragma unroll
        for (int j = 0; j < 4; j++)
            #pragma unroll
            for (int k = 0; k < 4; k++)
                acc[i][j][k] = 0.0f;

    int aRow[4], aR3[4];
    #pragma unroll
    for (int mi = 0; mi < 4; mi++) {
        const int r = wm * 64 + mi * 16 + (lane & 7) + (((lane >> 3) & 1) << 3);
        aRow[mi] = r * 64;
        aR3[mi] = r & 3;
    }
    const int aHi = lane >> 4;
    int bRowP[2], bR3P[2];
    #pragma unroll
    for (int pi = 0; pi < 2; pi++) {
        const int r = wn * 32 + (2 * pi + (lane >> 4)) * 8 + (lane & 7);
        bRowP[pi] = r * 64;
        bR3P[pi] = r & 3;
    }
    const int bG = (lane >> 3) & 1;

    #pragma unroll
    for (int c = 0; c < 2; c++) {
        load_tile(stg[c], Ah, rowBase, c * KCHUNK);
        if (TWOA) load_tile(stg[c] + TILE_B, Al, rowBase, c * KCHUNK);
        load_tile(stg[c] + WOFF, Wh, colBase, c * KCHUNK);
        cp_commit();
    }

    for (int c = 0; c < NCHUNK; c++) {
        if (c < NCHUNK - 2) asm volatile("cp.async.wait_group 1;");
        else                asm volatile("cp.async.wait_group 0;");
        __syncthreads();

        if (c + 2 < NCHUNK) {
            const int cc = c + 2;
            const int kk = cc * KCHUNK;
            const int st = cc - (cc / 3) * 3;
            load_tile(stg[st], Ah, rowBase, kk);
            if (TWOA) load_tile(stg[st] + TILE_B, Al, rowBase, kk);
            load_tile(stg[st] + WOFF, Wh, colBase, kk);
            cp_commit();
        }

        const int cs = c - (c / 3) * 3;
        const uint32_t cBase = stg[cs];
        const uint32_t cB = cBase + WOFF;

        uint32_t bf[2][4][2];
        #pragma unroll
        for (int ks = 0; ks < 2; ks++) {
            #pragma unroll
            for (int pi = 0; pi < 2; pi++) {
                const int cg = (ks * 2 + bG) ^ bR3P[pi];
                uint32_t t[4];
                ldsm_x4(t, cB + bRowP[pi] + cg * 16);
                bf[ks][2 * pi][0] = t[0]; bf[ks][2 * pi][1] = t[1];
                bf[ks][2 * pi + 1][0] = t[2]; bf[ks][2 * pi + 1][1] = t[3];
            }
        }

        #pragma unroll
        for (int seg = 0; seg < 1 + TWOA; seg++) {
            const uint32_t cA = cBase + seg * TILE_B;
            #pragma unroll
            for (int ks = 0; ks < 2; ks++) {
                uint32_t af[4][4];
                #pragma unroll
                for (int mi = 0; mi < 4; mi++) {
                    const int cg = (ks * 2 + aHi) ^ aR3[mi];
                    ldsm_x4(af[mi], cA + aRow[mi] + cg * 16);
                }
                #pragma unroll
                for (int mi = 0; mi < 4; mi++)
                    #pragma unroll
                    for (int ni = 0; ni < 4; ni++)
                        mma16816(acc[mi][ni], af[mi], bf[ks][ni]);
            }
        }
    }

    // epilogue
    const int lr = lane >> 2;
    const int lc = (lane & 3) * 2;
    #pragma unroll
    for (int ni = 0; ni < 4; ni++) {
        const int col = colBase + wn * 32 + ni * 8 + lc;
        const float2 bb = *(const float2*)&bias[col];
        #pragma unroll
        for (int mi = 0; mi < 4; mi++) {
            const int row = rowBase + wm * 64 + mi * 16 + lr;
            float2 v0 = { (acc[mi][ni][0] + bb.x) * oscale,
                          (acc[mi][ni][1] + bb.y) * oscale };
            float2 v1 = { (acc[mi][ni][2] + bb.x) * oscale,
                          (acc[mi][ni][3] + bb.y) * oscale };
            if (MODE == 0) {
                *(float2*)&dstF[(size_t)row * Dc + col] = v0;
                *(float2*)&dstF[(size_t)(row + 8) * Dc + col] = v1;
            } else {
                const int h = col >> 6;
                const int dk = col & 63;
                const int b = row >> 11;
                const int s = row & (Sc - 1);
                const size_t a0 = (((size_t)(b * Hc + h) * Sc + s)) * 64 + dk;
                const size_t a1 = a0 + 8 * 64;
                *(uint32_t*)&dstH[a0] = pack_h2(v0.x, v0.y);
                *(uint32_t*)&dstH[a1] = pack_h2(v1.x, v1.y);
            }
        }
    }
}

__global__ __launch_bounds__(256, 2) void qkv_gemm_tc(
    const float* __restrict__ bq, const float* __restrict__ bk,
    const float* __restrict__ bv)
{
    const int z = blockIdx.z;
    const float* bias = (z == 0) ? bq : (z == 1) ? bk : bv;
    __half* dst = (z == 0) ? g_qs : (z == 1) ? g_ks : g_vs;
    const float sc = (z == 0) ? 0.125f : 1.0f;   // fold 1/sqrt(DK) into Q
    gemm_core<1, 1>(g_ah[z], g_al[z], g_wth[z], bias, nullptr, dst,
                    blockIdx.y * 128, blockIdx.x * 128, sc);
}

__global__ __launch_bounds__(256, 2) void out_gemm_tc(
    const float* __restrict__ bo, float* __restrict__ out)
{
    gemm_core<0, 0>(g_ch, nullptr, g_wth[3], bo, out, nullptr,
                    blockIdx.y * 128, blockIdx.x * 128, 1.0f);
}

// ---------------------------------------------------------------------------
// fp32 -> fp16 hi/lo splits
// ---------------------------------------------------------------------------
__global__ __launch_bounds__(256) void split_inputs_kernel(
    const float* __restrict__ q, const float* __restrict__ k,
    const float* __restrict__ v)
{
    const int z = blockIdx.y;
    const float* src = (z == 0) ? q : (z == 1) ? k : v;
    const size_t i4 = (size_t)blockIdx.x * 256 + threadIdx.x;
    float4 f = ((const float4*)src)[i4];
    float a[4] = {f.x, f.y, f.z, f.w};
    __align__(8) __half h[4], lo[4];
    #pragma unroll
    for (int i = 0; i < 4; i++) {
        h[i] = __float2half_rn(a[i]);
        lo[i] = __float2half_rn(a[i] - __half2float(h[i]));
    }
    *(uint2*)&g_ah[z][i4 * 4] = *(uint2*)h;
    *(uint2*)&g_al[z][i4 * 4] = *(uint2*)lo;
}

__global__ __launch_bounds__(1024) void split_weights_kernel(
    const float* __restrict__ Wq, const float* __restrict__ Wk,
    const float* __restrict__ Wv, const float* __restrict__ Wo)
{
    const int z = blockIdx.z;
    const float* w = (z == 0) ? Wq : (z == 1) ? Wk : (z == 2) ? Wv : Wo;
    __shared__ float s[32][33];
    const int tx = threadIdx.x & 31;
    const int ty = threadIdx.x >> 5;
    const int rb = blockIdx.y * 32;   // k block
    const int cb = blockIdx.x * 32;   // n block
    s[ty][tx] = w[(size_t)(rb + ty) * Dc + cb + tx];
    __syncthreads();
    const float a = s[tx][ty];        // = w[rb+tx][cb+ty]
    g_wth[z][(size_t)(cb + ty) * Dc + rb + tx] = __float2half_rn(a);
}

// ---------------------------------------------------------------------------
// Banded local attention via HMMA, per-warp banded key windows.
// CTA = (bh, 128-query tile), 8 warps each owning 16 query rows.
// Warp wm computes S(16x48) over halo keys [wm*16, wm*16+48) — exactly the
// +-16 band for its rows — then ctx(16x64) = P(16x48) @ V(48x64) via
// ldsm.trans. No cross-warp combine; rowsums stay in registers.
// ---------------------------------------------------------------------------
#define TQ 128
#define HALO 160
// dynamic smem layout (bytes):
#define A_SQ 0                       // Q: 128 rows x 128B, swizzle ^(r&7)
#define A_SK 16384                   // K: 160 rows x 128B, swizzle ^(r&7)
#define A_SV 36864                   // V: 160 rows x 128B, swizzle ^(r&7)
#define ATTN_SMEM 57344

__global__ __launch_bounds__(256) void attn_kernel()
{
    extern __shared__ char dynsm[];
    const uint32_t sb = smem_to_u32(dynsm);
    const int tid = threadIdx.x;
    const int bh = blockIdx.y;
    const int q0 = blockIdx.x * TQ;
    const int kstart = q0 - Wc;
    const size_t base = (size_t)bh * Sc * 64;

    // zero the 16 out-of-range halo rows at sequence edges (V zeros are
    // required: P entries are 0 there but 0 * NaN-garbage would poison ctx)
    if (blockIdx.x == 0 && tid < 128) {
        const int row = tid >> 3, cg = tid & 7;
        *(uint4*)(dynsm + A_SK + row * 128 + cg * 16) = make_uint4(0, 0, 0, 0);
        *(uint4*)(dynsm + A_SV + row * 128 + cg * 16) = make_uint4(0, 0, 0, 0);
    }
    if (blockIdx.x == gridDim.x - 1 && tid < 128) {
        const int row = 144 + (tid >> 3), cg = tid & 7;
        *(uint4*)(dynsm + A_SK + row * 128 + cg * 16) = make_uint4(0, 0, 0, 0);
        *(uint4*)(dynsm + A_SV + row * 128 + cg * 16) = make_uint4(0, 0, 0, 0);
    }

    // async-load Q (128 rows), K and V (160-row halo, valid rows only)
    for (int i = tid; i < 1024; i += 256) {
        const int row = i >> 3, cg = i & 7;
        cp_async16(sb + A_SQ + row * 128 + ((cg ^ (row & 7)) * 16),
                   g_qs + base + (size_t)(q0 + row) * 64 + cg * 8);
    }
    for (int i = tid; i < 1280; i += 256) {
        const int row = i >> 3, cg = i & 7;
        const int j = kstart + row;
        if (j >= 0 && j < Sc)
            cp_async16(sb + A_SK + row * 128 + ((cg ^ (row & 7)) * 16),
                       g_ks + base + (size_t)j * 64 + cg * 8);
    }
    for (int i = tid; i < 1280; i += 256) {
        const int row = i >> 3, cg = i & 7;
        const int j = kstart + row;
        if (j >= 0 && j < Sc)
            cp_async16(sb + A_SV + row * 128 + ((cg ^ (row & 7)) * 16),
                       g_vs + base + (size_t)j * 64 + cg * 8);
    }
    cp_commit();
    asm volatile("cp.async.wait_group 0;");
    __syncthreads();

    const int wid = tid >> 5;     // wm: 0..7, owns query rows wm*16..+15
    const int lane = tid & 31;
    const int kb = wid * 16;      // halo-row base of this warp's 48-key window

    // ---- phase 1: S(16x48) = Q_w @ K_w^T ----
    const int rA = wid * 16 + (lane & 7) + (((lane >> 3) & 1) << 3);
    const int aOff = rA * 128, aXor = rA & 7, aG = lane >> 4;
    int rBOff[3], bXor[3];
    #pragma unroll
    for (int pi = 0; pi < 3; pi++) {
        const int r = kb + (2 * pi + (lane >> 4)) * 8 + (lane & 7);
        rBOff[pi] = r * 128;
        bXor[pi] = r & 7;
    }
    const int bG = (lane >> 3) & 1;

    float sacc[6][4];
    #pragma unroll
    for (int i = 0; i < 6; i++)
        #pragma unroll
        for (int j = 0; j < 4; j++) sacc[i][j] = 0.0f;

    #pragma unroll
    for (int ks = 0; ks < 4; ks++) {
        uint32_t af[4];
        ldsm_x4(af, sb + A_SQ + aOff + (((ks * 2 + aG) ^ aXor) << 4));
        #pragma unroll
        for (int pi = 0; pi < 3; pi++) {
            uint32_t t[4];
            ldsm_x4(t, sb + A_SK + rBOff[pi] + (((ks * 2 + bG) ^ bXor[pi]) << 4));
            mma16816(sacc[2 * pi], af, t);
            mma16816(sacc[2 * pi + 1], af, t + 2);
        }
    }

    // ---- mask + exp + register rowsums ----
    const int rowl = lane >> 2;          // in-warp row (reg>>1 adds 8)
    const int cbl = (lane & 3) * 2;      // in-window col base
    float rs0 = 0.0f, rs1 = 0.0f;
    #pragma unroll
    for (int nf = 0; nf < 6; nf++) {
        #pragma unroll
        for (int reg = 0; reg < 4; reg++) {
            const int c = nf * 8 + cbl + (reg & 1);            // 0..47
            const int r = rowl + ((reg >> 1) << 3);            // 0..15
            const int d = c - 16 - r;                          // j - q
            const int j = q0 + kb + c - 16;                    // global key
            const bool valid = (d >= -Wc) && (d <= Wc) && (j >= 0) && (j < Sc);
            const float w = valid ? __expf(sacc[nf][reg]) : 0.0f;
            sacc[nf][reg] = w;
            if (reg >> 1) rs1 += w; else rs0 += w;
        }
    }
    rs0 += __shfl_xor_sync(0xffffffffu, rs0, 1);
    rs0 += __shfl_xor_sync(0xffffffffu, rs0, 2);
    rs1 += __shfl_xor_sync(0xffffffffu, rs1, 1);
    rs1 += __shfl_xor_sync(0xffffffffu, rs1, 2);
    const float inv0 = 1.0f / rs0;
    const float inv1 = 1.0f / rs1;

    uint32_t pA[3][4];
    #pragma unroll
    for (int kc = 0; kc < 3; kc++) {
        pA[kc][0] = pack_h2(sacc[2 * kc][0],     sacc[2 * kc][1]);
        pA[kc][1] = pack_h2(sacc[2 * kc][2],     sacc[2 * kc][3]);
        pA[kc][2] = pack_h2(sacc[2 * kc + 1][0], sacc[2 * kc + 1][1]);
        pA[kc][3] = pack_h2(sacc[2 * kc + 1][2], sacc[2 * kc + 1][3]);
    }

    // ---- phase 2: ctx(16x64) = P @ V_w via ldsm.trans ----
    float cacc[8][4];
    #pragma unroll
    for (int i = 0; i < 8; i++)
        #pragma unroll
        for (int j = 0; j < 4; j++) cacc[i][j] = 0.0f;

    const int vKeyLocal = (((lane >> 3) & 1) << 3) + (lane & 7);
    const int vGHalf = lane >> 4;

    #pragma unroll
    for (int kc = 0; kc < 3; kc++) {
        const int key = kb + kc * 16 + vKeyLocal;
        const uint32_t rowAddr = sb + A_SV + key * 128;
        const int kx = key & 7;
        #pragma unroll
        for (int pi = 0; pi < 4; pi++) {
            const int gi = 2 * pi + vGHalf;
            uint32_t t[4];
            ldsm_x4_trans(t, rowAddr + ((gi ^ kx) << 4));
            mma16816(cacc[2 * pi], pA[kc], t);
            mma16816(cacc[2 * pi + 1], pA[kc], t + 2);
        }
    }

    // ---- epilogue: scale by 1/l, fp16, direct store ----
    const int b = bh >> 3;
    const int h = bh & 7;
    const int row0 = q0 + kb + rowl;
    const size_t o0 = ((size_t)(b * Sc + row0)) * Dc + h * 64 + cbl;
    const size_t o1 = o0 + 8 * Dc;
    #pragma unroll
    for (int nf = 0; nf < 8; nf++) {
        *(uint32_t*)(g_ch + o0 + nf * 8) =
            pack_h2(cacc[nf][0] * inv0, cacc[nf][1] * inv0);
        *(uint32_t*)(g_ch + o1 + nf * 8) =
            pack_h2(cacc[nf][2] * inv1, cacc[nf][3] * inv1);
    }
}

// ---------------------------------------------------------------------------
// Launch
// ---------------------------------------------------------------------------
extern "C" void kernel_launch(void* const* d_in, const int* in_sizes, int n_in,
                              void* d_out, int out_size)
{
    const float* query = (const float*)d_in[0];
    const float* key   = (const float*)d_in[1];
    const float* value = (const float*)d_in[2];
    const float* Wq    = (const float*)d_in[3];
    const float* bq    = (const float*)d_in[4];
    const float* Wk    = (const float*)d_in[5];
    const float* bk    = (const float*)d_in[6];
    const float* Wv    = (const float*)d_in[7];
    const float* bv    = (const float*)d_in[8];
    const float* Wo    = (const float*)d_in[9];
    const float* bo    = (const float*)d_in[10];
    float* out = (float*)d_out;

    static bool attr_done = false;
    if (!attr_done) {
        cudaFuncSetAttribute(qkv_gemm_tc,
            cudaFuncAttributeMaxDynamicSharedMemorySize, QKV_SMEM);
        cudaFuncSetAttribute(out_gemm_tc,
            cudaFuncAttributeMaxDynamicSharedMemorySize, OUT_SMEM);
        cudaFuncSetAttribute(attn_kernel,
            cudaFuncAttributeMaxDynamicSharedMemorySize, ATTN_SMEM);
        attr_done = true;
    }

    // 1. fp32 -> fp16 hi/lo splits (weights: hi only, transposed)
    split_inputs_kernel<<<dim3(NELEM / 4 / 256, 3), 256>>>(query, key, value);
    split_weights_kernel<<<dim3(16, 16, 4), 1024>>>(Wq, Wk, Wv, Wo);

    // 2. QKV projections -> fp16 [bh][s][dk] (Q prescaled by 0.125)
    qkv_gemm_tc<<<dim3(4, 64, 3), 256, QKV_SMEM>>>(bq, bk, bv);

    // 3. banded attention (HMMA, per-warp banded windows, TQ=128)
    attn_kernel<<<dim3(Sc / TQ, Bc * Hc), 256, ATTN_SMEM>>>();

    // 4. output projection (single-term fp16 A)
    out_gemm_tc<<<dim3(4, 64), 256, OUT_SMEM>>>(bo, out);
}

// round 12
// speedup vs baseline: 2.7892x; 1.0520x over previous
#include <cuda_runtime.h>
#include <cuda_bf16.h>
#include <cuda_fp16.h>
#include <cstdint>
#include <math.h>

// ---------------------------------------------------------------------------
// Problem constants
// ---------------------------------------------------------------------------
#define Bc  4
#define Sc  2048
#define Dc  512
#define Hc  8
#define Wc  16
#define DKc 64
#define Mtot (Bc * Sc)          // 8192
#define NELEM (Mtot * Dc)       // 4194304

// ---------------------------------------------------------------------------
// Device scratch
// ---------------------------------------------------------------------------
__device__ __half g_ah[3][NELEM];      // fp16 hi split of query/key/value
__device__ __half g_al[3][NELEM];      // fp16 lo split
__device__ __half g_wth[4][Dc * Dc];   // W^T hi (fp16): [n][k]
__device__ __half g_qs[NELEM];         // projected Q fp16, [bh][s][64], prescaled
__device__ __half g_ks[NELEM];         // projected K fp16, [bh][s][64]
__device__ __half g_vs[NELEM];         // projected V fp16, [bh][s][64]
__device__ __half g_ch[NELEM];         // ctx fp16 [m, 512]

__device__ __forceinline__ uint32_t smem_to_u32(const void* p) {
    uint32_t a;
    asm("{ .reg .u64 t; cvta.to.shared.u64 t, %1; cvt.u32.u64 %0, t; }"
        : "=r"(a) : "l"(p));
    return a;
}
__device__ __forceinline__ void cp_async16(uint32_t sp, const void* gp) {
    asm volatile("cp.async.cg.shared.global [%0], [%1], 16;" :: "r"(sp), "l"(gp));
}
__device__ __forceinline__ void cp_commit() {
    asm volatile("cp.async.commit_group;");
}
__device__ __forceinline__ void ldsm_x4(uint32_t* r, uint32_t addr) {
    asm volatile("ldmatrix.sync.aligned.m8n8.x4.shared.b16 {%0,%1,%2,%3}, [%4];"
                 : "=r"(r[0]), "=r"(r[1]), "=r"(r[2]), "=r"(r[3]) : "r"(addr));
}
__device__ __forceinline__ void ldsm_x4_trans(uint32_t* r, uint32_t addr) {
    asm volatile("ldmatrix.sync.aligned.m8n8.x4.trans.shared.b16 {%0,%1,%2,%3}, [%4];"
                 : "=r"(r[0]), "=r"(r[1]), "=r"(r[2]), "=r"(r[3]) : "r"(addr));
}
__device__ __forceinline__ void mma16816(
    float* d, const uint32_t* a, const uint32_t* b)
{
    asm volatile(
        "mma.sync.aligned.m16n8k16.row.col.f32.f16.f16.f32 "
        "{%0,%1,%2,%3}, {%4,%5,%6,%7}, {%8,%9}, {%0,%1,%2,%3};"
        : "+f"(d[0]), "+f"(d[1]), "+f"(d[2]), "+f"(d[3])
        : "r"(a[0]), "r"(a[1]), "r"(a[2]), "r"(a[3]), "r"(b[0]), "r"(b[1]));
}
__device__ __forceinline__ uint32_t pack_h2(float a, float b) {
    __half2 h = __floats2half2_rn(a, b);
    return *(uint32_t*)&h;
}

// ---------------------------------------------------------------------------
// QKV GEMM: C = (Ah + Al) @ Wh^T + bias -> fp16 scatter to [bh][s][64].
// CTA tile 128x128, 8 warps 2x4, warp 64x32, KCHUNK 32 (64B rows, ^(r&3)),
// FOUR-stage cp.async ring (96KB), one sync per chunk, shared-W two A passes.
// ---------------------------------------------------------------------------
#define KC32 32
#define NCH32 16
#define T32_B (128 * KC32 * 2)       // 8192
#define ST32_B (3 * T32_B)           // 24576: Ah, Al, Wh
#define QKV_SMEM (4 * ST32_B)        // 98304

__device__ __forceinline__ void load_tile32(
    uint32_t sbase, const __half* __restrict__ src, int rowBase, int kk)
{
    #pragma unroll
    for (int i = 0; i < 2; i++) {
        const int g = threadIdx.x + i * 256;   // 0..511
        const int row = g >> 2;
        const int cg = g & 3;
        cp_async16(sbase + row * 64 + ((cg ^ (row & 3)) * 16),
                   src + (size_t)(rowBase + row) * Dc + kk + cg * 8);
    }
}

__global__ __launch_bounds__(256, 2) void qkv_gemm_tc(
    const float* __restrict__ bq, const float* __restrict__ bk,
    const float* __restrict__ bv)
{
    extern __shared__ char dynsm[];
    const int z = blockIdx.z;
    const float* bias = (z == 0) ? bq : (z == 1) ? bk : bv;
    __half* dstH = (z == 0) ? g_qs : (z == 1) ? g_ks : g_vs;
    const float oscale = (z == 0) ? 0.125f : 1.0f;
    const __half* Ah = g_ah[z];
    const __half* Al = g_al[z];
    const __half* Wh = g_wth[z];
    const int rowBase = blockIdx.y * 128;
    const int colBase = blockIdx.x * 128;

    const int tid = threadIdx.x;
    const int wid = tid >> 5;
    const int lane = tid & 31;
    const int wm = wid >> 2;
    const int wn = wid & 3;

    const uint32_t sb = smem_to_u32(dynsm);
    uint32_t stg[4];
    #pragma unroll
    for (int s = 0; s < 4; s++) stg[s] = sb + s * ST32_B;

    float acc[4][4][4];
    #pragma unroll
    for (int i = 0; i < 4; i++)
        #pragma unroll
        for (int j = 0; j < 4; j++)
            #pragma unroll
            for (int k = 0; k < 4; k++) acc[i][j][k] = 0.0f;

    int aRow[4], aR3[4];
    #pragma unroll
    for (int mi = 0; mi < 4; mi++) {
        const int r = wm * 64 + mi * 16 + (lane & 7) + (((lane >> 3) & 1) << 3);
        aRow[mi] = r * 64;
        aR3[mi] = r & 3;
    }
    const int aHi = lane >> 4;
    int bRowP[2], bR3P[2];
    #pragma unroll
    for (int pi = 0; pi < 2; pi++) {
        const int r = wn * 32 + (2 * pi + (lane >> 4)) * 8 + (lane & 7);
        bRowP[pi] = r * 64;
        bR3P[pi] = r & 3;
    }
    const int bG = (lane >> 3) & 1;

    // prologue: chunks 0..2 into stages 0..2
    #pragma unroll
    for (int c = 0; c < 3; c++) {
        load_tile32(stg[c], Ah, rowBase, c * KC32);
        load_tile32(stg[c] + T32_B, Al, rowBase, c * KC32);
        load_tile32(stg[c] + 2 * T32_B, Wh, colBase, c * KC32);
        cp_commit();
    }

    for (int c = 0; c < NCH32; c++) {
        if (c < NCH32 - 2)       asm volatile("cp.async.wait_group 2;");
        else if (c == NCH32 - 2) asm volatile("cp.async.wait_group 1;");
        else                     asm volatile("cp.async.wait_group 0;");
        __syncthreads();

        if (c + 3 < NCH32) {
            const int cc = c + 3;
            const int kk = cc * KC32;
            const uint32_t st = stg[cc & 3];
            load_tile32(st, Ah, rowBase, kk);
            load_tile32(st + T32_B, Al, rowBase, kk);
            load_tile32(st + 2 * T32_B, Wh, colBase, kk);
            cp_commit();
        }

        const uint32_t cBase = stg[c & 3];
        const uint32_t cB = cBase + 2 * T32_B;

        uint32_t bf[2][4][2];
        #pragma unroll
        for (int ks = 0; ks < 2; ks++) {
            #pragma unroll
            for (int pi = 0; pi < 2; pi++) {
                const int cg = (ks * 2 + bG) ^ bR3P[pi];
                uint32_t t[4];
                ldsm_x4(t, cB + bRowP[pi] + cg * 16);
                bf[ks][2 * pi][0] = t[0]; bf[ks][2 * pi][1] = t[1];
                bf[ks][2 * pi + 1][0] = t[2]; bf[ks][2 * pi + 1][1] = t[3];
            }
        }
        #pragma unroll
        for (int seg = 0; seg < 2; seg++) {
            const uint32_t cA = cBase + seg * T32_B;
            #pragma unroll
            for (int ks = 0; ks < 2; ks++) {
                uint32_t af[4][4];
                #pragma unroll
                for (int mi = 0; mi < 4; mi++) {
                    const int cg = (ks * 2 + aHi) ^ aR3[mi];
                    ldsm_x4(af[mi], cA + aRow[mi] + cg * 16);
                }
                #pragma unroll
                for (int mi = 0; mi < 4; mi++)
                    #pragma unroll
                    for (int ni = 0; ni < 4; ni++)
                        mma16816(acc[mi][ni], af[mi], bf[ks][ni]);
            }
        }
    }

    // epilogue: fp16 scatter to [bh][s][64]
    const int lr = lane >> 2;
    const int lc = (lane & 3) * 2;
    #pragma unroll
    for (int ni = 0; ni < 4; ni++) {
        const int col = colBase + wn * 32 + ni * 8 + lc;
        const float2 bb = *(const float2*)&bias[col];
        const int h = col >> 6;
        const int dk = col & 63;
        #pragma unroll
        for (int mi = 0; mi < 4; mi++) {
            const int row = rowBase + wm * 64 + mi * 16 + lr;
            const int b = row >> 11;
            const int s = row & (Sc - 1);
            const size_t a0 = (((size_t)(b * Hc + h) * Sc + s)) * 64 + dk;
            *(uint32_t*)&dstH[a0] =
                pack_h2((acc[mi][ni][0] + bb.x) * oscale,
                        (acc[mi][ni][1] + bb.y) * oscale);
            *(uint32_t*)&dstH[a0 + 8 * 64] =
                pack_h2((acc[mi][ni][2] + bb.x) * oscale,
                        (acc[mi][ni][3] + bb.y) * oscale);
        }
    }
}

// ---------------------------------------------------------------------------
// OUT GEMM: out = ctx @ Wo^T + bo (fp32 output). KCHUNK 64 (128B rows,
// ^(r&7) swizzle — round-6 validated core), 3-stage pipeline, single A.
// ---------------------------------------------------------------------------
#define KC64 64
#define NCH64 8
#define T64_B (128 * KC64 * 2)       // 16384
#define ST64_B (2 * T64_B)           // 32768: A, Wh
#define OUT_SMEM (3 * ST64_B)        // 98304

__device__ __forceinline__ void load_tile64(
    uint32_t sbase, const __half* __restrict__ src, int rowBase, int kk)
{
    #pragma unroll
    for (int i = 0; i < 4; i++) {
        const int g = threadIdx.x + i * 256;   // 0..1023
        const int row = g >> 3;
        const int cg = g & 7;
        cp_async16(sbase + row * 128 + ((cg ^ (row & 7)) * 16),
                   src + (size_t)(rowBase + row) * Dc + kk + cg * 8);
    }
}

__global__ __launch_bounds__(256, 2) void out_gemm_tc(
    const float* __restrict__ bo, float* __restrict__ out)
{
    extern __shared__ char dynsm[];
    const __half* Ah = g_ch;
    const __half* Wh = g_wth[3];
    const int rowBase = blockIdx.y * 128;
    const int colBase = blockIdx.x * 128;

    const int tid = threadIdx.x;
    const int wid = tid >> 5;
    const int lane = tid & 31;
    const int wm = wid >> 2;
    const int wn = wid & 3;

    const uint32_t sb = smem_to_u32(dynsm);
    uint32_t stg[3];
    #pragma unroll
    for (int s = 0; s < 3; s++) stg[s] = sb + s * ST64_B;

    float acc[4][4][4];
    #pragma unroll
    for (int i = 0; i < 4; i++)
        #pragma unroll
        for (int j = 0; j < 4; j++)
            #pragma unroll
            for (int k = 0; k < 4; k++) acc[i][j][k] = 0.0f;

    int aRow[4], aR7[4];
    #pragma unroll
    for (int mi = 0; mi < 4; mi++) {
        const int r = wm * 64 + mi * 16 + (lane & 7) + (((lane >> 3) & 1) << 3);
        aRow[mi] = r * 128;
        aR7[mi] = r & 7;
    }
    const int aHi = lane >> 4;
    int bRowP[2], bR7P[2];
    #pragma unroll
    for (int pi = 0; pi < 2; pi++) {
        const int r = wn * 32 + (2 * pi + (lane >> 4)) * 8 + (lane & 7);
        bRowP[pi] = r * 128;
        bR7P[pi] = r & 7;
    }
    const int bG = (lane >> 3) & 1;

    #pragma unroll
    for (int c = 0; c < 2; c++) {
        load_tile64(stg[c], Ah, rowBase, c * KC64);
        load_tile64(stg[c] + T64_B, Wh, colBase, c * KC64);
        cp_commit();
    }

    for (int c = 0; c < NCH64; c++) {
        if (c < NCH64 - 2) asm volatile("cp.async.wait_group 1;");
        else               asm volatile("cp.async.wait_group 0;");
        __syncthreads();

        if (c + 2 < NCH64) {
            const int cc = c + 2;
            const uint32_t st = stg[cc - (cc / 3) * 3];
            load_tile64(st, Ah, rowBase, cc * KC64);
            load_tile64(st + T64_B, Wh, colBase, cc * KC64);
            cp_commit();
        }

        const uint32_t cBase = stg[c - (c / 3) * 3];
        const uint32_t cB = cBase + T64_B;

        #pragma unroll
        for (int ks = 0; ks < 4; ks++) {
            uint32_t af[4][4], bf[4][2];
            #pragma unroll
            for (int mi = 0; mi < 4; mi++) {
                const int cg = (ks * 2 + aHi) ^ aR7[mi];
                ldsm_x4(af[mi], cBase + aRow[mi] + cg * 16);
            }
            #pragma unroll
            for (int pi = 0; pi < 2; pi++) {
                const int cg = (ks * 2 + bG) ^ bR7P[pi];
                uint32_t t[4];
                ldsm_x4(t, cB + bRowP[pi] + cg * 16);
                bf[2 * pi][0] = t[0]; bf[2 * pi][1] = t[1];
                bf[2 * pi + 1][0] = t[2]; bf[2 * pi + 1][1] = t[3];
            }
            #pragma unroll
            for (int mi = 0; mi < 4; mi++)
                #pragma unroll
                for (int ni = 0; ni < 4; ni++)
                    mma16816(acc[mi][ni], af[mi], bf[ni]);
        }
    }

    const int lr = lane >> 2;
    const int lc = (lane & 3) * 2;
    #pragma unroll
    for (int ni = 0; ni < 4; ni++) {
        const int col = colBase + wn * 32 + ni * 8 + lc;
        const float2 bb2 = *(const float2*)&bo[col];
        #pragma unroll
        for (int mi = 0; mi < 4; mi++) {
            const int row = rowBase + wm * 64 + mi * 16 + lr;
            float2 v0 = { acc[mi][ni][0] + bb2.x, acc[mi][ni][1] + bb2.y };
            float2 v1 = { acc[mi][ni][2] + bb2.x, acc[mi][ni][3] + bb2.y };
            *(float2*)&out[(size_t)row * Dc + col] = v0;
            *(float2*)&out[(size_t)(row + 8) * Dc + col] = v1;
        }
    }
}

// ---------------------------------------------------------------------------
// prep: fused input hi/lo split + weight transpose (single launch).
// blocks [0, 12288): input split (z = bx>>12). blocks [12288, 13312):
// 32x32 weight transpose tiles (z = (bx-12288)>>8).
// ---------------------------------------------------------------------------
__global__ __launch_bounds__(256) void prep_kernel(
    const float* __restrict__ q, const float* __restrict__ k,
    const float* __restrict__ v,
    const float* __restrict__ Wq, const float* __restrict__ Wk,
    const float* __restrict__ Wv, const float* __restrict__ Wo)
{
    __shared__ float s[32][33];
    const int bx = blockIdx.x;
    if (bx < 12288) {
        const int z = bx >> 12;
        const float* src = (z == 0) ? q : (z == 1) ? k : v;
        const size_t i4 = (size_t)(bx & 4095) * 256 + threadIdx.x;
        float4 f = ((const float4*)src)[i4];
        float a[4] = {f.x, f.y, f.z, f.w};
        __align__(8) __half h[4], lo[4];
        #pragma unroll
        for (int i = 0; i < 4; i++) {
            h[i] = __float2half_rn(a[i]);
            lo[i] = __float2half_rn(a[i] - __half2float(h[i]));
        }
        *(uint2*)&g_ah[z][i4 * 4] = *(uint2*)h;
        *(uint2*)&g_al[z][i4 * 4] = *(uint2*)lo;
    } else {
        const int w = bx - 12288;        // 0..1023
        const int z = w >> 8;
        const int t = w & 255;
        const int cb = (t & 15) * 32;    // n block
        const int rb = (t >> 4) * 32;    // k block
        const float* wsrc = (z == 0) ? Wq : (z == 1) ? Wk : (z == 2) ? Wv : Wo;
        const int tx = threadIdx.x & 31;
        const int ty = threadIdx.x >> 5; // 0..7
        #pragma unroll
        for (int r = 0; r < 4; r++)
            s[ty + r * 8][tx] = wsrc[(size_t)(rb + ty + r * 8) * Dc + cb + tx];
        __syncthreads();
        #pragma unroll
        for (int r = 0; r < 4; r++) {
            const int row = ty + r * 8;
            g_wth[z][(size_t)(cb + row) * Dc + rb + tx] =
                __float2half_rn(s[tx][row]);
        }
    }
}

// ---------------------------------------------------------------------------
// Banded local attention via HMMA, per-warp banded key windows, TQ=256.
// CTA = (bh, 256-query tile), 512 thr / 16 warps, each owning 16 query rows
// and its exact 48-key band window within the 288-row halo.
// ---------------------------------------------------------------------------
#define TQ 256
#define HALO 288
#define A_SQ 0                        // Q: 256 rows x 128B
#define A_SK 32768                    // K: 288 rows x 128B
#define A_SV 69632                    // V: 288 rows x 128B
#define ATTN_SMEM 106496

__global__ __launch_bounds__(512) void attn_kernel()
{
    extern __shared__ char dynsm[];
    const uint32_t sb = smem_to_u32(dynsm);
    const int tid = threadIdx.x;
    const int bh = blockIdx.y;
    const int q0 = blockIdx.x * TQ;
    const int kstart = q0 - Wc;
    const size_t base = (size_t)bh * Sc * 64;

    // zero out-of-range halo rows at sequence edges (V zeros required)
    if (blockIdx.x == 0 && tid < 128) {
        const int row = tid >> 3, cg = tid & 7;
        *(uint4*)(dynsm + A_SK + row * 128 + cg * 16) = make_uint4(0, 0, 0, 0);
        *(uint4*)(dynsm + A_SV + row * 128 + cg * 16) = make_uint4(0, 0, 0, 0);
    }
    if (blockIdx.x == gridDim.x - 1 && tid < 128) {
        const int row = (HALO - 16) + (tid >> 3), cg = tid & 7;
        *(uint4*)(dynsm + A_SK + row * 128 + cg * 16) = make_uint4(0, 0, 0, 0);
        *(uint4*)(dynsm + A_SV + row * 128 + cg * 16) = make_uint4(0, 0, 0, 0);
    }

    // async-load Q (256 rows), K and V (288-row halo, valid rows only)
    for (int i = tid; i < TQ * 8; i += 512) {
        const int row = i >> 3, cg = i & 7;
        cp_async16(sb + A_SQ + row * 128 + ((cg ^ (row & 7)) * 16),
                   g_qs + base + (size_t)(q0 + row) * 64 + cg * 8);
    }
    for (int i = tid; i < HALO * 8; i += 512) {
        const int row = i >> 3, cg = i & 7;
        const int j = kstart + row;
        if (j >= 0 && j < Sc)
            cp_async16(sb + A_SK + row * 128 + ((cg ^ (row & 7)) * 16),
                       g_ks + base + (size_t)j * 64 + cg * 8);
    }
    for (int i = tid; i < HALO * 8; i += 512) {
        const int row = i >> 3, cg = i & 7;
        const int j = kstart + row;
        if (j >= 0 && j < Sc)
            cp_async16(sb + A_SV + row * 128 + ((cg ^ (row & 7)) * 16),
                       g_vs + base + (size_t)j * 64 + cg * 8);
    }
    cp_commit();
    asm volatile("cp.async.wait_group 0;");
    __syncthreads();

    const int wid = tid >> 5;     // 0..15, owns query rows wid*16..+15
    const int lane = tid & 31;
    const int kb = wid * 16;      // halo-row base of this warp's 48-key window

    // ---- phase 1: S(16x48) = Q_w @ K_w^T ----
    const int rA = wid * 16 + (lane & 7) + (((lane >> 3) & 1) << 3);
    const int aOff = rA * 128, aXor = rA & 7, aG = lane >> 4;
    int rBOff[3], bXor[3];
    #pragma unroll
    for (int pi = 0; pi < 3; pi++) {
        const int r = kb + (2 * pi + (lane >> 4)) * 8 + (lane & 7);
        rBOff[pi] = r * 128;
        bXor[pi] = r & 7;
    }
    const int bG = (lane >> 3) & 1;

    float sacc[6][4];
    #pragma unroll
    for (int i = 0; i < 6; i++)
        #pragma unroll
        for (int j = 0; j < 4; j++) sacc[i][j] = 0.0f;

    #pragma unroll
    for (int ks = 0; ks < 4; ks++) {
        uint32_t af[4];
        ldsm_x4(af, sb + A_SQ + aOff + (((ks * 2 + aG) ^ aXor) << 4));
        #pragma unroll
        for (int pi = 0; pi < 3; pi++) {
            uint32_t t[4];
            ldsm_x4(t, sb + A_SK + rBOff[pi] + (((ks * 2 + bG) ^ bXor[pi]) << 4));
            mma16816(sacc[2 * pi], af, t);
            mma16816(sacc[2 * pi + 1], af, t + 2);
        }
    }

    // ---- mask + exp + register rowsums ----
    const int rowl = lane >> 2;
    const int cbl = (lane & 3) * 2;
    float rs0 = 0.0f, rs1 = 0.0f;
    #pragma unroll
    for (int nf = 0; nf < 6; nf++) {
        #pragma unroll
        for (int reg = 0; reg < 4; reg++) {
            const int c = nf * 8 + cbl + (reg & 1);            // 0..47
            const int r = rowl + ((reg >> 1) << 3);            // 0..15
            const int d = c - 16 - r;                          // j - q
            const int j = q0 + kb + c - 16;                    // global key
            const bool valid = (d >= -Wc) && (d <= Wc) && (j >= 0) && (j < Sc);
            const float w = valid ? __expf(sacc[nf][reg]) : 0.0f;
            sacc[nf][reg] = w;
            if (reg >> 1) rs1 += w; else rs0 += w;
        }
    }
    rs0 += __shfl_xor_sync(0xffffffffu, rs0, 1);
    rs0 += __shfl_xor_sync(0xffffffffu, rs0, 2);
    rs1 += __shfl_xor_sync(0xffffffffu, rs1, 1);
    rs1 += __shfl_xor_sync(0xffffffffu, rs1, 2);
    const float inv0 = 1.0f / rs0;
    const float inv1 = 1.0f / rs1;

    uint32_t pA[3][4];
    #pragma unroll
    for (int kc = 0; kc < 3; kc++) {
        pA[kc][0] = pack_h2(sacc[2 * kc][0],     sacc[2 * kc][1]);
        pA[kc][1] = pack_h2(sacc[2 * kc][2],     sacc[2 * kc][3]);
        pA[kc][2] = pack_h2(sacc[2 * kc + 1][0], sacc[2 * kc + 1][1]);
        pA[kc][3] = pack_h2(sacc[2 * kc + 1][2], sacc[2 * kc + 1][3]);
    }

    // ---- phase 2: ctx(16x64) = P @ V_w via ldsm.trans ----
    float cacc[8][4];
    #pragma unroll
    for (int i = 0; i < 8; i++)
        #pragma unroll
        for (int j = 0; j < 4; j++) cacc[i][j] = 0.0f;

    const int vKeyLocal = (((lane >> 3) & 1) << 3) + (lane & 7);
    const int vGHalf = lane >> 4;

    #pragma unroll
    for (int kc = 0; kc < 3; kc++) {
        const int key = kb + kc * 16 + vKeyLocal;
        const uint32_t rowAddr = sb + A_SV + key * 128;
        const int kx = key & 7;
        #pragma unroll
        for (int pi = 0; pi < 4; pi++) {
            const int gi = 2 * pi + vGHalf;
            uint32_t t[4];
            ldsm_x4_trans(t, rowAddr + ((gi ^ kx) << 4));
            mma16816(cacc[2 * pi], pA[kc], t);
            mma16816(cacc[2 * pi + 1], pA[kc], t + 2);
        }
    }

    // ---- epilogue: scale by 1/l, fp16, direct store ----
    const int b = bh >> 3;
    const int h = bh & 7;
    const int row0 = q0 + kb + rowl;
    const size_t o0 = ((size_t)(b * Sc + row0)) * Dc + h * 64 + cbl;
    const size_t o1 = o0 + 8 * Dc;
    #pragma unroll
    for (int nf = 0; nf < 8; nf++) {
        *(uint32_t*)(g_ch + o0 + nf * 8) =
            pack_h2(cacc[nf][0] * inv0, cacc[nf][1] * inv0);
        *(uint32_t*)(g_ch + o1 + nf * 8) =
            pack_h2(cacc[nf][2] * inv1, cacc[nf][3] * inv1);
    }
}

// ---------------------------------------------------------------------------
// Launch
// ---------------------------------------------------------------------------
extern "C" void kernel_launch(void* const* d_in, const int* in_sizes, int n_in,
                              void* d_out, int out_size)
{
    const float* query = (const float*)d_in[0];
    const float* key   = (const float*)d_in[1];
    const float* value = (const float*)d_in[2];
    const float* Wq    = (const float*)d_in[3];
    const float* bq    = (const float*)d_in[4];
    const float* Wk    = (const float*)d_in[5];
    const float* bk    = (const float*)d_in[6];
    const float* Wv    = (const float*)d_in[7];
    const float* bv    = (const float*)d_in[8];
    const float* Wo    = (const float*)d_in[9];
    const float* bo    = (const float*)d_in[10];
    float* out = (float*)d_out;

    static bool attr_done = false;
    if (!attr_done) {
        cudaFuncSetAttribute(qkv_gemm_tc,
            cudaFuncAttributeMaxDynamicSharedMemorySize, QKV_SMEM);
        cudaFuncSetAttribute(out_gemm_tc,
            cudaFuncAttributeMaxDynamicSharedMemorySize, OUT_SMEM);
        cudaFuncSetAttribute(attn_kernel,
            cudaFuncAttributeMaxDynamicSharedMemorySize, ATTN_SMEM);
        attr_done = true;
    }

    // 1. fused splits (inputs hi/lo + weight transpose) in one launch
    prep_kernel<<<13312, 256>>>(query, key, value, Wq, Wk, Wv, Wo);

    // 2. QKV projections -> fp16 [bh][s][dk] (Q prescaled), 4-stage pipeline
    qkv_gemm_tc<<<dim3(4, 64, 3), 256, QKV_SMEM>>>(bq, bk, bv);

    // 3. banded attention (HMMA, per-warp windows, TQ=256)
    attn_kernel<<<dim3(Sc / TQ, Bc * Hc), 512, ATTN_SMEM>>>();

    // 4. output projection (KCHUNK 64)
    out_gemm_tc<<<dim3(4, 64), 256, OUT_SMEM>>>(bo, out);
}

// round 13
// speedup vs baseline: 2.8105x; 1.0076x over previous
#include <cuda_runtime.h>
#include <cuda_bf16.h>
#include <cuda_fp16.h>
#include <cstdint>
#include <math.h>

// ---------------------------------------------------------------------------
// Problem constants
// ---------------------------------------------------------------------------
#define Bc  4
#define Sc  2048
#define Dc  512
#define Hc  8
#define Wc  16
#define DKc 64
#define Mtot (Bc * Sc)          // 8192
#define NELEM (Mtot * Dc)       // 4194304

// ---------------------------------------------------------------------------
// Device scratch
// ---------------------------------------------------------------------------
__device__ __half g_ah[3][NELEM];      // fp16 hi split of query/key/value
__device__ __half g_al[3][NELEM];      // fp16 lo split
__device__ __half g_wth[4][Dc * Dc];   // W^T hi (fp16): [n][k]
__device__ __half g_qs[NELEM];         // projected Q fp16, [bh][s][64], prescaled
__device__ __half g_ks[NELEM];         // projected K fp16, [bh][s][64]
__device__ __half g_vs[NELEM];         // projected V fp16, [bh][s][64]
__device__ __half g_ch[NELEM];         // ctx fp16 [m, 512]

__device__ __forceinline__ uint32_t smem_to_u32(const void* p) {
    uint32_t a;
    asm("{ .reg .u64 t; cvta.to.shared.u64 t, %1; cvt.u32.u64 %0, t; }"
        : "=r"(a) : "l"(p));
    return a;
}
__device__ __forceinline__ void cp_async16(uint32_t sp, const void* gp) {
    asm volatile("cp.async.cg.shared.global [%0], [%1], 16;" :: "r"(sp), "l"(gp));
}
__device__ __forceinline__ void cp_commit() {
    asm volatile("cp.async.commit_group;");
}
__device__ __forceinline__ void ldsm_x4(uint32_t* r, uint32_t addr) {
    asm volatile("ldmatrix.sync.aligned.m8n8.x4.shared.b16 {%0,%1,%2,%3}, [%4];"
                 : "=r"(r[0]), "=r"(r[1]), "=r"(r[2]), "=r"(r[3]) : "r"(addr));
}
__device__ __forceinline__ void ldsm_x4_trans(uint32_t* r, uint32_t addr) {
    asm volatile("ldmatrix.sync.aligned.m8n8.x4.trans.shared.b16 {%0,%1,%2,%3}, [%4];"
                 : "=r"(r[0]), "=r"(r[1]), "=r"(r[2]), "=r"(r[3]) : "r"(addr));
}
__device__ __forceinline__ void mma16816(
    float* d, const uint32_t* a, const uint32_t* b)
{
    asm volatile(
        "mma.sync.aligned.m16n8k16.row.col.f32.f16.f16.f32 "
        "{%0,%1,%2,%3}, {%4,%5,%6,%7}, {%8,%9}, {%0,%1,%2,%3};"
        : "+f"(d[0]), "+f"(d[1]), "+f"(d[2]), "+f"(d[3])
        : "r"(a[0]), "r"(a[1]), "r"(a[2]), "r"(a[3]), "r"(b[0]), "r"(b[1]));
}
__device__ __forceinline__ uint32_t pack_h2(float a, float b) {
    __half2 h = __floats2half2_rn(a, b);
    return *(uint32_t*)&h;
}

// ---------------------------------------------------------------------------
// QKV GEMM: C = (Ah + Al) @ Wh^T + bias -> fp16 scatter to [bh][s][64].
// CTA tile 128x128, 8 warps 2x4, warp 64x32, KCHUNK 32 (64B rows, ^(r&3)),
// FOUR-stage cp.async ring (96KB), one sync per chunk, shared-W two A passes.
// ---------------------------------------------------------------------------
#define KC32 32
#define NCH32 16
#define T32_B (128 * KC32 * 2)       // 8192
#define ST32_B (3 * T32_B)           // 24576: Ah, Al, Wh
#define QKV_SMEM (4 * ST32_B)        // 98304

__device__ __forceinline__ void load_tile32(
    uint32_t sbase, const __half* __restrict__ src, int rowBase, int kk)
{
    #pragma unroll
    for (int i = 0; i < 2; i++) {
        const int g = threadIdx.x + i * 256;   // 0..511
        const int row = g >> 2;
        const int cg = g & 3;
        cp_async16(sbase + row * 64 + ((cg ^ (row & 3)) * 16),
                   src + (size_t)(rowBase + row) * Dc + kk + cg * 8);
    }
}

__global__ __launch_bounds__(256, 2) void qkv_gemm_tc(
    const float* __restrict__ bq, const float* __restrict__ bk,
    const float* __restrict__ bv)
{
    extern __shared__ char dynsm[];
    const int z = blockIdx.z;
    const float* bias = (z == 0) ? bq : (z == 1) ? bk : bv;
    __half* dstH = (z == 0) ? g_qs : (z == 1) ? g_ks : g_vs;
    const float oscale = (z == 0) ? 0.125f : 1.0f;
    const __half* Ah = g_ah[z];
    const __half* Al = g_al[z];
    const __half* Wh = g_wth[z];
    const int rowBase = blockIdx.y * 128;
    const int colBase = blockIdx.x * 128;

    const int tid = threadIdx.x;
    const int wid = tid >> 5;
    const int lane = tid & 31;
    const int wm = wid >> 2;
    const int wn = wid & 3;

    const uint32_t sb = smem_to_u32(dynsm);
    uint32_t stg[4];
    #pragma unroll
    for (int s = 0; s < 4; s++) stg[s] = sb + s * ST32_B;

    float acc[4][4][4];
    #pragma unroll
    for (int i = 0; i < 4; i++)
        #pragma unroll
        for (int j = 0; j < 4; j++)
            #pragma unroll
            for (int k = 0; k < 4; k++) acc[i][j][k] = 0.0f;

    int aRow[4], aR3[4];
    #pragma unroll
    for (int mi = 0; mi < 4; mi++) {
        const int r = wm * 64 + mi * 16 + (lane & 7) + (((lane >> 3) & 1) << 3);
        aRow[mi] = r * 64;
        aR3[mi] = r & 3;
    }
    const int aHi = lane >> 4;
    int bRowP[2], bR3P[2];
    #pragma unroll
    for (int pi = 0; pi < 2; pi++) {
        const int r = wn * 32 + (2 * pi + (lane >> 4)) * 8 + (lane & 7);
        bRowP[pi] = r * 64;
        bR3P[pi] = r & 3;
    }
    const int bG = (lane >> 3) & 1;

    // prologue: chunks 0..2 into stages 0..2
    #pragma unroll
    for (int c = 0; c < 3; c++) {
        load_tile32(stg[c], Ah, rowBase, c * KC32);
        load_tile32(stg[c] + T32_B, Al, rowBase, c * KC32);
        load_tile32(stg[c] + 2 * T32_B, Wh, colBase, c * KC32);
        cp_commit();
    }

    for (int c = 0; c < NCH32; c++) {
        if (c < NCH32 - 2)       asm volatile("cp.async.wait_group 2;");
        else if (c == NCH32 - 2) asm volatile("cp.async.wait_group 1;");
        else                     asm volatile("cp.async.wait_group 0;");
        __syncthreads();

        if (c + 3 < NCH32) {
            const int cc = c + 3;
            const int kk = cc * KC32;
            const uint32_t st = stg[cc & 3];
            load_tile32(st, Ah, rowBase, kk);
            load_tile32(st + T32_B, Al, rowBase, kk);
            load_tile32(st + 2 * T32_B, Wh, colBase, kk);
            cp_commit();
        }

        const uint32_t cBase = stg[c & 3];
        const uint32_t cB = cBase + 2 * T32_B;

        uint32_t bf[2][4][2];
        #pragma unroll
        for (int ks = 0; ks < 2; ks++) {
            #pragma unroll
            for (int pi = 0; pi < 2; pi++) {
                const int cg = (ks * 2 + bG) ^ bR3P[pi];
                uint32_t t[4];
                ldsm_x4(t, cB + bRowP[pi] + cg * 16);
                bf[ks][2 * pi][0] = t[0]; bf[ks][2 * pi][1] = t[1];
                bf[ks][2 * pi + 1][0] = t[2]; bf[ks][2 * pi + 1][1] = t[3];
            }
        }
        #pragma unroll
        for (int seg = 0; seg < 2; seg++) {
            const uint32_t cA = cBase + seg * T32_B;
            #pragma unroll
            for (int ks = 0; ks < 2; ks++) {
                uint32_t af[4][4];
                #pragma unroll
                for (int mi = 0; mi < 4; mi++) {
                    const int cg = (ks * 2 + aHi) ^ aR3[mi];
                    ldsm_x4(af[mi], cA + aRow[mi] + cg * 16);
                }
                #pragma unroll
                for (int mi = 0; mi < 4; mi++)
                    #pragma unroll
                    for (int ni = 0; ni < 4; ni++)
                        mma16816(acc[mi][ni], af[mi], bf[ks][ni]);
            }
        }
    }

    // epilogue: fp16 scatter to [bh][s][64]
    const int lr = lane >> 2;
    const int lc = (lane & 3) * 2;
    #pragma unroll
    for (int ni = 0; ni < 4; ni++) {
        const int col = colBase + wn * 32 + ni * 8 + lc;
        const float2 bb = *(const float2*)&bias[col];
        const int h = col >> 6;
        const int dk = col & 63;
        #pragma unroll
        for (int mi = 0; mi < 4; mi++) {
            const int row = rowBase + wm * 64 + mi * 16 + lr;
            const int b = row >> 11;
            const int s = row & (Sc - 1);
            const size_t a0 = (((size_t)(b * Hc + h) * Sc + s)) * 64 + dk;
            *(uint32_t*)&dstH[a0] =
                pack_h2((acc[mi][ni][0] + bb.x) * oscale,
                        (acc[mi][ni][1] + bb.y) * oscale);
            *(uint32_t*)&dstH[a0 + 8 * 64] =
                pack_h2((acc[mi][ni][2] + bb.x) * oscale,
                        (acc[mi][ni][3] + bb.y) * oscale);
        }
    }
}

// ---------------------------------------------------------------------------
// OUT GEMM: out = ctx @ Wo^T + bo (fp32). CTA tile 64x128 (grid 4x128),
// warp tile 32x32 (8 warps 2x4), KCHUNK 64 (128B rows, ^(r&7)), 3-stage
// pipeline, 72KB smem, 3 CTAs/SM for latency hiding (was occ 18.7%).
// ---------------------------------------------------------------------------
#define KC64 64
#define NCH64 8
#define OA_B (64 * KC64 * 2)         // 8192  (A: 64 rows)
#define OW_B (128 * KC64 * 2)        // 16384 (W: 128 rows)
#define OST_B (OA_B + OW_B)          // 24576
#define OUT_SMEM (3 * OST_B)         // 73728

__device__ __forceinline__ void load_tileA64(
    uint32_t sbase, const __half* __restrict__ src, int rowBase, int kk)
{
    #pragma unroll
    for (int i = 0; i < 2; i++) {
        const int g = threadIdx.x + i * 256;   // 0..511 (64 rows x 8 granules)
        const int row = g >> 3;
        const int cg = g & 7;
        cp_async16(sbase + row * 128 + ((cg ^ (row & 7)) * 16),
                   src + (size_t)(rowBase + row) * Dc + kk + cg * 8);
    }
}
__device__ __forceinline__ void load_tileW64(
    uint32_t sbase, const __half* __restrict__ src, int rowBase, int kk)
{
    #pragma unroll
    for (int i = 0; i < 4; i++) {
        const int g = threadIdx.x + i * 256;   // 0..1023 (128 rows x 8 granules)
        const int row = g >> 3;
        const int cg = g & 7;
        cp_async16(sbase + row * 128 + ((cg ^ (row & 7)) * 16),
                   src + (size_t)(rowBase + row) * Dc + kk + cg * 8);
    }
}

__global__ __launch_bounds__(256, 3) void out_gemm_tc(
    const float* __restrict__ bo, float* __restrict__ out)
{
    extern __shared__ char dynsm[];
    const __half* Ah = g_ch;
    const __half* Wh = g_wth[3];
    const int rowBase = blockIdx.y * 64;
    const int colBase = blockIdx.x * 128;

    const int tid = threadIdx.x;
    const int wid = tid >> 5;
    const int lane = tid & 31;
    const int wm = wid >> 2;       // 0..1 (rows wm*32..)
    const int wn = wid & 3;        // 0..3 (cols wn*32..)

    const uint32_t sb = smem_to_u32(dynsm);
    uint32_t stg[3];
    #pragma unroll
    for (int s = 0; s < 3; s++) stg[s] = sb + s * OST_B;

    float acc[2][4][4];
    #pragma unroll
    for (int i = 0; i < 2; i++)
        #pragma unroll
        for (int j = 0; j < 4; j++)
            #pragma unroll
            for (int k = 0; k < 4; k++) acc[i][j][k] = 0.0f;

    int aRow[2], aR7[2];
    #pragma unroll
    for (int mi = 0; mi < 2; mi++) {
        const int r = wm * 32 + mi * 16 + (lane & 7) + (((lane >> 3) & 1) << 3);
        aRow[mi] = r * 128;
        aR7[mi] = r & 7;
    }
    const int aHi = lane >> 4;
    int bRowP[2], bR7P[2];
    #pragma unroll
    for (int pi = 0; pi < 2; pi++) {
        const int r = wn * 32 + (2 * pi + (lane >> 4)) * 8 + (lane & 7);
        bRowP[pi] = r * 128;
        bR7P[pi] = r & 7;
    }
    const int bG = (lane >> 3) & 1;

    #pragma unroll
    for (int c = 0; c < 2; c++) {
        load_tileA64(stg[c], Ah, rowBase, c * KC64);
        load_tileW64(stg[c] + OA_B, Wh, colBase, c * KC64);
        cp_commit();
    }

    for (int c = 0; c < NCH64; c++) {
        if (c < NCH64 - 2) asm volatile("cp.async.wait_group 1;");
        else               asm volatile("cp.async.wait_group 0;");
        __syncthreads();

        if (c + 2 < NCH64) {
            const int cc = c + 2;
            const uint32_t st = stg[cc - (cc / 3) * 3];
            load_tileA64(st, Ah, rowBase, cc * KC64);
            load_tileW64(st + OA_B, Wh, colBase, cc * KC64);
            cp_commit();
        }

        const uint32_t cBase = stg[c - (c / 3) * 3];
        const uint32_t cB = cBase + OA_B;

        #pragma unroll
        for (int ks = 0; ks < 4; ks++) {
            uint32_t af[2][4], bf[4][2];
            #pragma unroll
            for (int mi = 0; mi < 2; mi++) {
                const int cg = (ks * 2 + aHi) ^ aR7[mi];
                ldsm_x4(af[mi], cBase + aRow[mi] + cg * 16);
            }
            #pragma unroll
            for (int pi = 0; pi < 2; pi++) {
                const int cg = (ks * 2 + bG) ^ bR7P[pi];
                uint32_t t[4];
                ldsm_x4(t, cB + bRowP[pi] + cg * 16);
                bf[2 * pi][0] = t[0]; bf[2 * pi][1] = t[1];
                bf[2 * pi + 1][0] = t[2]; bf[2 * pi + 1][1] = t[3];
            }
            #pragma unroll
            for (int mi = 0; mi < 2; mi++)
                #pragma unroll
                for (int ni = 0; ni < 4; ni++)
                    mma16816(acc[mi][ni], af[mi], bf[ni]);
        }
    }

    const int lr = lane >> 2;
    const int lc = (lane & 3) * 2;
    #pragma unroll
    for (int ni = 0; ni < 4; ni++) {
        const int col = colBase + wn * 32 + ni * 8 + lc;
        const float2 bb2 = *(const float2*)&bo[col];
        #pragma unroll
        for (int mi = 0; mi < 2; mi++) {
            const int row = rowBase + wm * 32 + mi * 16 + lr;
            float2 v0 = { acc[mi][ni][0] + bb2.x, acc[mi][ni][1] + bb2.y };
            float2 v1 = { acc[mi][ni][2] + bb2.x, acc[mi][ni][3] + bb2.y };
            *(float2*)&out[(size_t)row * Dc + col] = v0;
            *(float2*)&out[(size_t)(row + 8) * Dc + col] = v1;
        }
    }
}

// ---------------------------------------------------------------------------
// prep: fused input hi/lo split + weight transpose (single launch).
// ---------------------------------------------------------------------------
__global__ __launch_bounds__(256) void prep_kernel(
    const float* __restrict__ q, const float* __restrict__ k,
    const float* __restrict__ v,
    const float* __restrict__ Wq, const float* __restrict__ Wk,
    const float* __restrict__ Wv, const float* __restrict__ Wo)
{
    __shared__ float s[32][33];
    const int bx = blockIdx.x;
    if (bx < 12288) {
        const int z = bx >> 12;
        const float* src = (z == 0) ? q : (z == 1) ? k : v;
        const size_t i4 = (size_t)(bx & 4095) * 256 + threadIdx.x;
        float4 f = ((const float4*)src)[i4];
        float a[4] = {f.x, f.y, f.z, f.w};
        __align__(8) __half h[4], lo[4];
        #pragma unroll
        for (int i = 0; i < 4; i++) {
            h[i] = __float2half_rn(a[i]);
            lo[i] = __float2half_rn(a[i] - __half2float(h[i]));
        }
        *(uint2*)&g_ah[z][i4 * 4] = *(uint2*)h;
        *(uint2*)&g_al[z][i4 * 4] = *(uint2*)lo;
    } else {
        const int w = bx - 12288;        // 0..1023
        const int z = w >> 8;
        const int t = w & 255;
        const int cb = (t & 15) * 32;    // n block
        const int rb = (t >> 4) * 32;    // k block
        const float* wsrc = (z == 0) ? Wq : (z == 1) ? Wk : (z == 2) ? Wv : Wo;
        const int tx = threadIdx.x & 31;
        const int ty = threadIdx.x >> 5; // 0..7
        #pragma unroll
        for (int r = 0; r < 4; r++)
            s[ty + r * 8][tx] = wsrc[(size_t)(rb + ty + r * 8) * Dc + cb + tx];
        __syncthreads();
        #pragma unroll
        for (int r = 0; r < 4; r++) {
            const int row = ty + r * 8;
            g_wth[z][(size_t)(cb + row) * Dc + rb + tx] =
                __float2half_rn(s[tx][row]);
        }
    }
}

// ---------------------------------------------------------------------------
// Banded local attention via HMMA, per-warp banded key windows, TQ=256.
// ---------------------------------------------------------------------------
#define TQ 256
#define HALO 288
#define A_SQ 0                        // Q: 256 rows x 128B
#define A_SK 32768                    // K: 288 rows x 128B
#define A_SV 69632                    // V: 288 rows x 128B
#define ATTN_SMEM 106496

__global__ __launch_bounds__(512) void attn_kernel()
{
    extern __shared__ char dynsm[];
    const uint32_t sb = smem_to_u32(dynsm);
    const int tid = threadIdx.x;
    const int bh = blockIdx.y;
    const int q0 = blockIdx.x * TQ;
    const int kstart = q0 - Wc;
    const size_t base = (size_t)bh * Sc * 64;

    if (blockIdx.x == 0 && tid < 128) {
        const int row = tid >> 3, cg = tid & 7;
        *(uint4*)(dynsm + A_SK + row * 128 + cg * 16) = make_uint4(0, 0, 0, 0);
        *(uint4*)(dynsm + A_SV + row * 128 + cg * 16) = make_uint4(0, 0, 0, 0);
    }
    if (blockIdx.x == gridDim.x - 1 && tid < 128) {
        const int row = (HALO - 16) + (tid >> 3), cg = tid & 7;
        *(uint4*)(dynsm + A_SK + row * 128 + cg * 16) = make_uint4(0, 0, 0, 0);
        *(uint4*)(dynsm + A_SV + row * 128 + cg * 16) = make_uint4(0, 0, 0, 0);
    }

    for (int i = tid; i < TQ * 8; i += 512) {
        const int row = i >> 3, cg = i & 7;
        cp_async16(sb + A_SQ + row * 128 + ((cg ^ (row & 7)) * 16),
                   g_qs + base + (size_t)(q0 + row) * 64 + cg * 8);
    }
    for (int i = tid; i < HALO * 8; i += 512) {
        const int row = i >> 3, cg = i & 7;
        const int j = kstart + row;
        if (j >= 0 && j < Sc)
            cp_async16(sb + A_SK + row * 128 + ((cg ^ (row & 7)) * 16),
                       g_ks + base + (size_t)j * 64 + cg * 8);
    }
    for (int i = tid; i < HALO * 8; i += 512) {
        const int row = i >> 3, cg = i & 7;
        const int j = kstart + row;
        if (j >= 0 && j < Sc)
            cp_async16(sb + A_SV + row * 128 + ((cg ^ (row & 7)) * 16),
                       g_vs + base + (size_t)j * 64 + cg * 8);
    }
    cp_commit();
    asm volatile("cp.async.wait_group 0;");
    __syncthreads();

    const int wid = tid >> 5;     // 0..15, owns query rows wid*16..+15
    const int lane = tid & 31;
    const int kb = wid * 16;

    // ---- phase 1: S(16x48) = Q_w @ K_w^T ----
    const int rA = wid * 16 + (lane & 7) + (((lane >> 3) & 1) << 3);
    const int aOff = rA * 128, aXor = rA & 7, aG = lane >> 4;
    int rBOff[3], bXor[3];
    #pragma unroll
    for (int pi = 0; pi < 3; pi++) {
        const int r = kb + (2 * pi + (lane >> 4)) * 8 + (lane & 7);
        rBOff[pi] = r * 128;
        bXor[pi] = r & 7;
    }
    const int bG = (lane >> 3) & 1;

    float sacc[6][4];
    #pragma unroll
    for (int i = 0; i < 6; i++)
        #pragma unroll
        for (int j = 0; j < 4; j++) sacc[i][j] = 0.0f;

    #pragma unroll
    for (int ks = 0; ks < 4; ks++) {
        uint32_t af[4];
        ldsm_x4(af, sb + A_SQ + aOff + (((ks * 2 + aG) ^ aXor) << 4));
        #pragma unroll
        for (int pi = 0; pi < 3; pi++) {
            uint32_t t[4];
            ldsm_x4(t, sb + A_SK + rBOff[pi] + (((ks * 2 + bG) ^ bXor[pi]) << 4));
            mma16816(sacc[2 * pi], af, t);
            mma16816(sacc[2 * pi + 1], af, t + 2);
        }
    }

    // ---- mask + exp + register rowsums ----
    const int rowl = lane >> 2;
    const int cbl = (lane & 3) * 2;
    float rs0 = 0.0f, rs1 = 0.0f;
    #pragma unroll
    for (int nf = 0; nf < 6; nf++) {
        #pragma unroll
        for (int reg = 0; reg < 4; reg++) {
            const int c = nf * 8 + cbl + (reg & 1);            // 0..47
            const int r = rowl + ((reg >> 1) << 3);            // 0..15
            const int d = c - 16 - r;                          // j - q
            const int j = q0 + kb + c - 16;                    // global key
            const bool valid = (d >= -Wc) && (d <= Wc) && (j >= 0) && (j < Sc);
            const float w = valid ? __expf(sacc[nf][reg]) : 0.0f;
            sacc[nf][reg] = w;
            if (reg >> 1) rs1 += w; else rs0 += w;
        }
    }
    rs0 += __shfl_xor_sync(0xffffffffu, rs0, 1);
    rs0 += __shfl_xor_sync(0xffffffffu, rs0, 2);
    rs1 += __shfl_xor_sync(0xffffffffu, rs1, 1);
    rs1 += __shfl_xor_sync(0xffffffffu, rs1, 2);
    const float inv0 = 1.0f / rs0;
    const float inv1 = 1.0f / rs1;

    uint32_t pA[3][4];
    #pragma unroll
    for (int kc = 0; kc < 3; kc++) {
        pA[kc][0] = pack_h2(sacc[2 * kc][0],     sacc[2 * kc][1]);
        pA[kc][1] = pack_h2(sacc[2 * kc][2],     sacc[2 * kc][3]);
        pA[kc][2] = pack_h2(sacc[2 * kc + 1][0], sacc[2 * kc + 1][1]);
        pA[kc][3] = pack_h2(sacc[2 * kc + 1][2], sacc[2 * kc + 1][3]);
    }

    // ---- phase 2: ctx(16x64) = P @ V_w via ldsm.trans ----
    float cacc[8][4];
    #pragma unroll
    for (int i = 0; i < 8; i++)
        #pragma unroll
        for (int j = 0; j < 4; j++) cacc[i][j] = 0.0f;

    const int vKeyLocal = (((lane >> 3) & 1) << 3) + (lane & 7);
    const int vGHalf = lane >> 4;

    #pragma unroll
    for (int kc = 0; kc < 3; kc++) {
        const int key = kb + kc * 16 + vKeyLocal;
        const uint32_t rowAddr = sb + A_SV + key * 128;
        const int kx = key & 7;
        #pragma unroll
        for (int pi = 0; pi < 4; pi++) {
            const int gi = 2 * pi + vGHalf;
            uint32_t t[4];
            ldsm_x4_trans(t, rowAddr + ((gi ^ kx) << 4));
            mma16816(cacc[2 * pi], pA[kc], t);
            mma16816(cacc[2 * pi + 1], pA[kc], t + 2);
        }
    }

    // ---- epilogue: scale by 1/l, fp16, direct store ----
    const int b = bh >> 3;
    const int h = bh & 7;
    const int row0 = q0 + kb + rowl;
    const size_t o0 = ((size_t)(b * Sc + row0)) * Dc + h * 64 + cbl;
    const size_t o1 = o0 + 8 * Dc;
    #pragma unroll
    for (int nf = 0; nf < 8; nf++) {
        *(uint32_t*)(g_ch + o0 + nf * 8) =
            pack_h2(cacc[nf][0] * inv0, cacc[nf][1] * inv0);
        *(uint32_t*)(g_ch + o1 + nf * 8) =
            pack_h2(cacc[nf][2] * inv1, cacc[nf][3] * inv1);
    }
}

// ---------------------------------------------------------------------------
// Launch
// ---------------------------------------------------------------------------
extern "C" void kernel_launch(void* const* d_in, const int* in_sizes, int n_in,
                              void* d_out, int out_size)
{
    const float* query = (const float*)d_in[0];
    const float* key   = (const float*)d_in[1];
    const float* value = (const float*)d_in[2];
    const float* Wq    = (const float*)d_in[3];
    const float* bq    = (const float*)d_in[4];
    const float* Wk    = (const float*)d_in[5];
    const float* bk    = (const float*)d_in[6];
    const float* Wv    = (const float*)d_in[7];
    const float* bv    = (const float*)d_in[8];
    const float* Wo    = (const float*)d_in[9];
    const float* bo    = (const float*)d_in[10];
    float* out = (float*)d_out;

    static bool attr_done = false;
    if (!attr_done) {
        cudaFuncSetAttribute(qkv_gemm_tc,
            cudaFuncAttributeMaxDynamicSharedMemorySize, QKV_SMEM);
        cudaFuncSetAttribute(out_gemm_tc,
            cudaFuncAttributeMaxDynamicSharedMemorySize, OUT_SMEM);
        cudaFuncSetAttribute(attn_kernel,
            cudaFuncAttributeMaxDynamicSharedMemorySize, ATTN_SMEM);
        attr_done = true;
    }

    // 1. fused splits (inputs hi/lo + weight transpose) in one launch
    prep_kernel<<<13312, 256>>>(query, key, value, Wq, Wk, Wv, Wo);

    // 2. QKV projections -> fp16 [bh][s][dk] (Q prescaled), 4-stage pipeline
    qkv_gemm_tc<<<dim3(4, 64, 3), 256, QKV_SMEM>>>(bq, bk, bv);

    // 3. banded attention (HMMA, per-warp windows, TQ=256)
    attn_kernel<<<dim3(Sc / TQ, Bc * Hc), 512, ATTN_SMEM>>>();

    // 4. output projection (CTA 64x128, warp 32x32, 3 CTA/SM)
    out_gemm_tc<<<dim3(4, 128), 256, OUT_SMEM>>>(bo, out);
}